// round 1
// baseline (speedup 1.0000x reference)
#include <cuda_runtime.h>
#include <math.h>

#define D_MODEL 1024
#define D3      3072
#define HFF     2730
#define BATCH   4
#define SEQ     4096
#define MTOT    (BATCH*SEQ)          // 16384

#define LN_EPS_F   1e-5f
#define ATTN_EPS_F 1e-6f

// ---------------- scratch (static __device__ globals; no allocation) --------
__device__ float g_qkv[(size_t)MTOT * D3];                 // qp|kp|v fused, elu+1 applied to q,k
__device__ float g_kv[(size_t)BATCH * D_MODEL * D_MODEL];  // per-batch context
__device__ float g_kspart[8 * BATCH * D_MODEL];
__device__ float g_ksum[BATCH * D_MODEL];
__device__ float g_den[MTOT];
__device__ float g_y [(size_t)MTOT * D_MODEL];             // x + attn
__device__ float g_x1[(size_t)MTOT * D_MODEL];             // LN1 out
__device__ float g_h [(size_t)MTOT * HFF];                 // silu(gate)*up
__device__ float g_ffn[(size_t)MTOT * D_MODEL];

// ---------------- generic tiled fp32 GEMM with fused epilogues --------------
// C[m,n] = sum_k A[m,k]*B[k,n]  (transA: A stored [K,M], read A[k*lda+m])
// epi: 0 = C = t(+bias)
//      1 = qkv: cols < 2048 get elu(t)+1
//      2 = attn: C = e2[idx] + t/(e1[m]+eps)   (num -> residual-pre-LN)
//      3 = C = silu(t)
//      4 = C = C * t  (gate*up fuse)
#define BM 128
#define BN 128
#define BKk 8
#define TM 8
#define TN 8

__global__ void __launch_bounds__(256) sgemm_kernel(
    const float* __restrict__ A, const float* __restrict__ B,
    const float* __restrict__ bias, float* __restrict__ C,
    int M, int N, int K, int lda, int ldb, int ldc,
    long long sA, long long sB, long long sC,
    int transA, int epi,
    const float* __restrict__ e1, const float* __restrict__ e2,
    long long sE1)
{
    __shared__ __align__(16) float As[BKk][BM];
    __shared__ __align__(16) float Bs[BKk][BN];

    const int bz = blockIdx.z;
    A += sA * bz;  B += sB * bz;  C += sC * bz;
    if (e1) e1 += sE1 * bz;
    if (e2) e2 += sC  * bz;   // e2 shares C's layout (x residual)

    const int tid = threadIdx.x;
    const int bm = blockIdx.y * BM;
    const int bn = blockIdx.x * BN;
    const int tm = (tid / 16) * TM;
    const int tn = (tid % 16) * TN;

    float acc[TM][TN];
#pragma unroll
    for (int i = 0; i < TM; i++)
#pragma unroll
        for (int j = 0; j < TN; j++) acc[i][j] = 0.f;

    for (int k0 = 0; k0 < K; k0 += BKk) {
        // load A tile
        if (!transA) {
#pragma unroll
            for (int it = 0; it < (BM*BKk)/256; it++) {
                int i = tid + it * 256;
                int m = i / BKk, k = i % BKk;
                int gm = bm + m, gk = k0 + k;
                As[k][m] = (gm < M && gk < K) ? A[(long long)gm * lda + gk] : 0.f;
            }
        } else {
#pragma unroll
            for (int it = 0; it < (BM*BKk)/256; it++) {
                int i = tid + it * 256;
                int k = i / BM, m = i % BM;
                int gm = bm + m, gk = k0 + k;
                As[k][m] = (gm < M && gk < K) ? A[(long long)gk * lda + gm] : 0.f;
            }
        }
        // load B tile
#pragma unroll
        for (int it = 0; it < (BKk*BN)/256; it++) {
            int i = tid + it * 256;
            int k = i / BN, n = i % BN;
            int gn = bn + n, gk = k0 + k;
            Bs[k][n] = (gn < N && gk < K) ? B[(long long)gk * ldb + gn] : 0.f;
        }
        __syncthreads();

#pragma unroll
        for (int k = 0; k < BKk; k++) {
            float4 a0 = *(const float4*)&As[k][tm];
            float4 a1 = *(const float4*)&As[k][tm + 4];
            float4 b0 = *(const float4*)&Bs[k][tn];
            float4 b1 = *(const float4*)&Bs[k][tn + 4];
            float ar[TM] = {a0.x,a0.y,a0.z,a0.w,a1.x,a1.y,a1.z,a1.w};
            float br[TN] = {b0.x,b0.y,b0.z,b0.w,b1.x,b1.y,b1.z,b1.w};
#pragma unroll
            for (int i = 0; i < TM; i++)
#pragma unroll
                for (int j = 0; j < TN; j++)
                    acc[i][j] += ar[i] * br[j];
        }
        __syncthreads();
    }

    // epilogue
#pragma unroll
    for (int i = 0; i < TM; i++) {
        int gm = bm + tm + i;
        if (gm >= M) continue;
#pragma unroll
        for (int j = 0; j < TN; j++) {
            int gn = bn + tn + j;
            if (gn >= N) continue;
            float t = acc[i][j] + (bias ? bias[gn] : 0.f);
            long long cidx = (long long)gm * ldc + gn;
            if (epi == 0) {
                C[cidx] = t;
            } else if (epi == 1) {
                if (gn < 2 * D_MODEL) t = (t > 0.f) ? t + 1.f : expf(t);
                C[cidx] = t;
            } else if (epi == 2) {
                float attn = t / (e1[gm] + ATTN_EPS_F);
                C[cidx] = e2[cidx] + attn;
            } else if (epi == 3) {
                C[cidx] = t / (1.f + expf(-t));
            } else { // 4
                C[cidx] = C[cidx] * t;
            }
        }
    }
}

// ---------------- ksum = sum_s kp[b,s,d] (two-stage, deterministic) ---------
__global__ void ksum_part_kernel() {
    int d  = blockIdx.x * 256 + threadIdx.x;   // grid.x = 4
    int b  = blockIdx.y;                       // grid.y = BATCH
    int sc = blockIdx.z;                       // grid.z = 8
    const float* kp = g_qkv + (size_t)b * SEQ * D3 + D_MODEL;
    int s0 = sc * (SEQ / 8);
    float s = 0.f;
    for (int i = 0; i < SEQ / 8; i++)
        s += kp[(size_t)(s0 + i) * D3 + d];
    g_kspart[(sc * BATCH + b) * D_MODEL + d] = s;
}
__global__ void ksum_reduce_kernel() {
    int i = blockIdx.x * 256 + threadIdx.x;    // grid 16
    if (i < BATCH * D_MODEL) {
        float s = 0.f;
        for (int c = 0; c < 8; c++) s += g_kspart[c * BATCH * D_MODEL + i];
        g_ksum[i] = s;
    }
}

// ---------------- den[m] = dot(qp[m,:], ksum[b,:]) --------------------------
__global__ void den_kernel() {
    int m = blockIdx.x * 8 + (threadIdx.x >> 5);   // 8 warps/block, grid 2048
    int lane = threadIdx.x & 31;
    const float* q  = g_qkv + (size_t)m * D3;      // qp (elu+1 applied)
    const float* ks = g_ksum + (m / SEQ) * D_MODEL;
    float s = 0.f;
    for (int d = lane; d < D_MODEL; d += 32) s += q[d] * ks[d];
#pragma unroll
    for (int o = 16; o > 0; o >>= 1) s += __shfl_xor_sync(0xffffffffu, s, o);
    if (lane == 0) g_den[m] = s;
}

// ---------------- layernorm over rows of 1024 (optional residual add) -------
__global__ void ln_kernel(const float* __restrict__ in1, const float* __restrict__ in2,
                          const float* __restrict__ gamma, const float* __restrict__ beta,
                          float* __restrict__ out)
{
    int row = blockIdx.x;
    int t = threadIdx.x;                       // 256 threads, 4 vals each
    long long base = (long long)row * D_MODEL;
    float vals[4];
    float s = 0.f;
#pragma unroll
    for (int i = 0; i < 4; i++) {
        int c = t + i * 256;
        float v = in1[base + c];
        if (in2) v += in2[base + c];
        vals[i] = v; s += v;
    }
    __shared__ float red[256];
    red[t] = s; __syncthreads();
    for (int o = 128; o > 0; o >>= 1) { if (t < o) red[t] += red[t + o]; __syncthreads(); }
    float mu = red[0] * (1.f / D_MODEL);
    __syncthreads();
    float vs = 0.f;
#pragma unroll
    for (int i = 0; i < 4; i++) { float d = vals[i] - mu; vs += d * d; }
    red[t] = vs; __syncthreads();
    for (int o = 128; o > 0; o >>= 1) { if (t < o) red[t] += red[t + o]; __syncthreads(); }
    float inv = rsqrtf(red[0] * (1.f / D_MODEL) + LN_EPS_F);
#pragma unroll
    for (int i = 0; i < 4; i++) {
        int c = t + i * 256;
        out[base + c] = (vals[i] - mu) * inv * gamma[c] + beta[c];
    }
}

// ---------------- launch ----------------------------------------------------
extern "C" void kernel_launch(void* const* d_in, const int* in_sizes, int n_in,
                              void* d_out, int out_size)
{
    const float* x    = (const float*)d_in[0];
    const float* Wqkv = (const float*)d_in[1];
    const float* bqkv = (const float*)d_in[2];
    const float* Wg   = (const float*)d_in[3];
    const float* bg   = (const float*)d_in[4];
    const float* Wu   = (const float*)d_in[5];
    const float* bu   = (const float*)d_in[6];
    const float* Wd   = (const float*)d_in[7];
    const float* bd   = (const float*)d_in[8];
    const float* g1   = (const float*)d_in[9];
    const float* b1   = (const float*)d_in[10];
    const float* g2   = (const float*)d_in[11];
    const float* b2   = (const float*)d_in[12];
    float* out = (float*)d_out;

    float *qkv, *kv, *yb, *x1, *h, *ffn, *den;
    cudaGetSymbolAddress((void**)&qkv, g_qkv);
    cudaGetSymbolAddress((void**)&kv,  g_kv);
    cudaGetSymbolAddress((void**)&yb,  g_y);
    cudaGetSymbolAddress((void**)&x1,  g_x1);
    cudaGetSymbolAddress((void**)&h,   g_h);
    cudaGetSymbolAddress((void**)&ffn, g_ffn);
    cudaGetSymbolAddress((void**)&den, g_den);

    dim3 blk(256);
    const long long SD3 = (long long)SEQ * D3;
    const long long SDM = (long long)SEQ * D_MODEL;
    const long long DD  = (long long)D_MODEL * D_MODEL;

    // 1) qkv = x @ Wqkv + bqkv, elu+1 fused on q,k columns
    sgemm_kernel<<<dim3(D3/BN, MTOT/BM, 1), blk>>>(
        x, Wqkv, bqkv, qkv, MTOT, D3, D_MODEL, D_MODEL, D3, D3,
        0, 0, 0, 0, 1, nullptr, nullptr, 0);

    // 2) ksum
    ksum_part_kernel<<<dim3(4, BATCH, 8), blk>>>();
    ksum_reduce_kernel<<<16, blk>>>();

    // 3) kv[b] = kp[b]^T @ v[b]   (D x D, K = SEQ)
    sgemm_kernel<<<dim3(D_MODEL/BN, D_MODEL/BM, BATCH), blk>>>(
        qkv + D_MODEL /*kp*/, qkv + 2*D_MODEL /*v*/, nullptr, kv,
        D_MODEL, D_MODEL, SEQ, D3, D3, D_MODEL,
        SD3, SD3, DD, 1, 0, nullptr, nullptr, 0);

    // 4) den
    den_kernel<<<MTOT/8, blk>>>();

    // 5) y = x + (qp @ kv) / (den + eps)
    sgemm_kernel<<<dim3(D_MODEL/BN, SEQ/BM, BATCH), blk>>>(
        qkv /*qp*/, kv, nullptr, yb,
        SEQ, D_MODEL, D_MODEL, D3, D_MODEL, D_MODEL,
        SD3, DD, SDM, 0, 2, den, x, (long long)SEQ);

    // 6) x1 = LN(y)
    ln_kernel<<<MTOT, blk>>>(yb, nullptr, g1, b1, x1);

    // 7) h = silu(x1 @ Wg + bg)
    sgemm_kernel<<<dim3((HFF+BN-1)/BN, MTOT/BM, 1), blk>>>(
        x1, Wg, bg, h, MTOT, HFF, D_MODEL, D_MODEL, HFF, HFF,
        0, 0, 0, 0, 3, nullptr, nullptr, 0);

    // 8) h *= (x1 @ Wu + bu)
    sgemm_kernel<<<dim3((HFF+BN-1)/BN, MTOT/BM, 1), blk>>>(
        x1, Wu, bu, h, MTOT, HFF, D_MODEL, D_MODEL, HFF, HFF,
        0, 0, 0, 0, 4, nullptr, nullptr, 0);

    // 9) ffn = h @ Wd + bd
    sgemm_kernel<<<dim3(D_MODEL/BN, MTOT/BM, 1), blk>>>(
        h, Wd, bd, ffn, MTOT, D_MODEL, HFF, HFF, D_MODEL, D_MODEL,
        0, 0, 0, 0, 0, nullptr, nullptr, 0);

    // 10) out = LN(x1 + ffn)
    ln_kernel<<<MTOT, blk>>>(x1, ffn, g2, b2, out);
}

// round 4
// speedup vs baseline: 1.9774x; 1.9774x over previous
#include <cuda_runtime.h>
#include <cuda_bf16.h>
#include <mma.h>
#include <cstdint>
#include <math.h>

using namespace nvcuda;

#define D_MODEL 1024
#define D3      3072
#define HFF     2730
#define HFFP    2736                 // HFF padded to 8-element (16B) multiple
#define BATCH   4
#define SEQ     4096
#define MTOT    (BATCH*SEQ)          // 16384

#define LN_EPS_F   1e-5f
#define ATTN_EPS_F 1e-6f

// ===================== scratch ==============================================
typedef __nv_bfloat16 bf16;

__device__ float g_qkv[(size_t)MTOT * D3];          // fp32 qkv (elu+1 on q,k)
__device__ bf16  g_xhi[(size_t)MTOT * D_MODEL];
__device__ bf16  g_xlo[(size_t)MTOT * D_MODEL];
__device__ bf16  g_qphi[(size_t)MTOT * D_MODEL];
__device__ bf16  g_qplo[(size_t)MTOT * D_MODEL];
__device__ bf16  g_WqkvThi[(size_t)D3 * D_MODEL];
__device__ bf16  g_WqkvTlo[(size_t)D3 * D_MODEL];
__device__ bf16  g_WgThi[(size_t)HFF * D_MODEL];
__device__ bf16  g_WgTlo[(size_t)HFF * D_MODEL];
__device__ bf16  g_WuThi[(size_t)HFF * D_MODEL];
__device__ bf16  g_WuTlo[(size_t)HFF * D_MODEL];
__device__ bf16  g_WdThi[(size_t)D_MODEL * HFFP];   // padded ld
__device__ bf16  g_WdTlo[(size_t)D_MODEL * HFFP];
__device__ bf16  g_kpThi[(size_t)BATCH * D_MODEL * SEQ];
__device__ bf16  g_kpTlo[(size_t)BATCH * D_MODEL * SEQ];
__device__ bf16  g_vThi [(size_t)BATCH * D_MODEL * SEQ];
__device__ bf16  g_vTlo [(size_t)BATCH * D_MODEL * SEQ];
__device__ float g_kv   [(size_t)BATCH * D_MODEL * D_MODEL];
__device__ bf16  g_kvhi [(size_t)BATCH * D_MODEL * D_MODEL];
__device__ bf16  g_kvlo [(size_t)BATCH * D_MODEL * D_MODEL];
__device__ float g_kspart[8 * BATCH * D_MODEL];
__device__ float g_ksum[BATCH * D_MODEL];
__device__ float g_den[MTOT];
__device__ float g_y [(size_t)MTOT * D_MODEL];
__device__ float g_x1[(size_t)MTOT * D_MODEL];
__device__ bf16  g_x1hi[(size_t)MTOT * D_MODEL];
__device__ bf16  g_x1lo[(size_t)MTOT * D_MODEL];
__device__ float g_h [(size_t)MTOT * HFF];
__device__ bf16  g_hhi[(size_t)MTOT * HFFP];        // padded ld
__device__ bf16  g_hlo[(size_t)MTOT * HFFP];
__device__ float g_ffn[(size_t)MTOT * D_MODEL];

// ===================== helpers ==============================================
__device__ __forceinline__ uint32_t smem_u32(const void* p) {
    uint32_t a;
    asm("{ .reg .u64 t; cvta.to.shared.u64 t, %1; cvt.u32.u64 %0, t; }" : "=r"(a) : "l"(p));
    return a;
}
__device__ __forceinline__ void cp16(uint32_t dst, const void* src, int bytes) {
    asm volatile("cp.async.cg.shared.global [%0], [%1], 16, %2;\n"
        :: "r"(dst), "l"(src), "r"(bytes));
}
#define CP_COMMIT() asm volatile("cp.async.commit_group;\n" ::: "memory")
#define CP_WAIT(n)  asm volatile("cp.async.wait_group %0;\n" :: "n"(n) : "memory")

__device__ __forceinline__ void split2(float v, bf16& h, bf16& l) {
    h = __float2bfloat16(v);
    l = __float2bfloat16(v - __bfloat162float(h));
}

// ===================== WMMA bf16 split-3 GEMM ===============================
// C[m,n] = sum_k A[m,k] * Bt[n,k]   (operands pre-split hi/lo bf16)
// BM=128, BN=128, BK=32, 256 threads (8 warps of 32x64 warp-tiles),
// cp.async double-buffered. Fused epilogues; optional bf16 hi/lo C outputs.
// NOTE: lda/ldb MUST be multiples of 8 elements (16B cp.async alignment).
#define BM 128
#define BN 128
#define BK 32
#define SROW 40                       // halves per smem row (32 + 8 pad)
#define STAGE_B (4 * 128 * SROW * 2)  // Ahi Alo Bhi Blo = 40960 B
#define SMEM_SZ (2 * STAGE_B)         // 81920 (epilogue staging 67584 fits)

typedef wmma::fragment<wmma::matrix_a, 16, 16, 16, bf16, wmma::row_major> FragA;
typedef wmma::fragment<wmma::matrix_b, 16, 16, 16, bf16, wmma::col_major> FragB;
typedef wmma::fragment<wmma::accumulator, 16, 16, 16, float> FragC;

__global__ void __launch_bounds__(256, 1) mma_gemm_kernel(
    const bf16* __restrict__ Ahi, const bf16* __restrict__ Alo,
    const bf16* __restrict__ Bhi, const bf16* __restrict__ Blo,
    const float* __restrict__ bias, float* __restrict__ C,
    bf16* __restrict__ Chi, bf16* __restrict__ Clo,
    int M, int N, int K, int lda, int ldb, int ldc, int ldchi,
    long long sA, long long sB, long long sC, long long sChi,
    int epi, int colLim,
    const float* __restrict__ e1, const float* __restrict__ e2, long long sE1)
{
    extern __shared__ __align__(16) char smem[];
    const uint32_t sbase = smem_u32(smem);
    const int tid = threadIdx.x;
    const int wid = tid >> 5;
    const int warp_m = wid & 3;        // 4 m-warps of 32 rows
    const int warp_n = wid >> 2;       // 2 n-warps of 64 cols
    const int bz = blockIdx.z;
    Ahi += sA * bz;  Alo += sA * bz;
    Bhi += sB * bz;  Blo += sB * bz;
    C   += sC * bz;
    if (Chi) { Chi += sChi * bz; Clo += sChi * bz; }
    if (e1) e1 += sE1 * bz;
    if (e2) e2 += sC * bz;
    const int bm = blockIdx.y * BM;
    const int bn = blockIdx.x * BN;

    FragC acc[2][4];
#pragma unroll
    for (int i = 0; i < 2; i++)
#pragma unroll
        for (int j = 0; j < 4; j++) wmma::fill_fragment(acc[i][j], 0.f);

    const int ntiles = (K + BK - 1) / BK;

    auto load_stage = [&](int s, int t) {
        uint32_t sb = sbase + s * STAGE_B;
        int k0 = t * BK;
#pragma unroll
        for (int j = 0; j < 2; j++) {
            int idx = tid + j * 256;
            int r = idx >> 2, ch = idx & 3;
            int kc = k0 + ch * 8;
            int ab = 2 * (K - kc); ab = ab < 0 ? 0 : (ab > 16 ? 16 : ab);
            long long aoff = (long long)(bm + r) * lda + kc;
            uint32_t d = sb + (r * SROW + ch * 8) * 2;
            cp16(d,                Ahi + aoff, ab);
            cp16(d + 128*SROW*2,   Alo + aoff, ab);
            int gn = bn + r;
            int bb = (gn < N) ? ab : 0;
            long long boff = (long long)(gn < N ? gn : 0) * ldb + kc;
            cp16(d + 2*128*SROW*2, Bhi + boff, bb);
            cp16(d + 3*128*SROW*2, Blo + boff, bb);
        }
    };

    load_stage(0, 0); CP_COMMIT();
    if (ntiles > 1) load_stage(1, 1);
    CP_COMMIT();

    for (int t = 0; t < ntiles; t++) {
        CP_WAIT(1);
        __syncthreads();
        const bf16* base = (const bf16*)(smem + (t & 1) * STAGE_B);
        const bf16* sAhi = base;
        const bf16* sAlo = base + 128 * SROW;
        const bf16* sBhi = base + 2 * 128 * SROW;
        const bf16* sBlo = base + 3 * 128 * SROW;
#pragma unroll
        for (int kk = 0; kk < 2; kk++) {
            FragA ah[2], al[2];
            FragB bh[4], bl[4];
#pragma unroll
            for (int i = 0; i < 2; i++) {
                int m0 = warp_m * 32 + i * 16;
                wmma::load_matrix_sync(ah[i], sAhi + m0 * SROW + kk * 16, SROW);
                wmma::load_matrix_sync(al[i], sAlo + m0 * SROW + kk * 16, SROW);
            }
#pragma unroll
            for (int j = 0; j < 4; j++) {
                int n0 = warp_n * 64 + j * 16;
                wmma::load_matrix_sync(bh[j], sBhi + n0 * SROW + kk * 16, SROW);
                wmma::load_matrix_sync(bl[j], sBlo + n0 * SROW + kk * 16, SROW);
            }
#pragma unroll
            for (int i = 0; i < 2; i++)
#pragma unroll
                for (int j = 0; j < 4; j++) {
                    wmma::mma_sync(acc[i][j], ah[i], bh[j], acc[i][j]);
                    wmma::mma_sync(acc[i][j], ah[i], bl[j], acc[i][j]);
                    wmma::mma_sync(acc[i][j], al[i], bh[j], acc[i][j]);
                }
        }
        __syncthreads();
        if (t + 2 < ntiles) load_stage(t & 1, t + 2);
        CP_COMMIT();
    }
    CP_WAIT(0);
    __syncthreads();

    // ---- epilogue via SMEM staging (128 x 132 floats) ----
    float* stg = (float*)smem;
#pragma unroll
    for (int i = 0; i < 2; i++)
#pragma unroll
        for (int j = 0; j < 4; j++) {
            int r0 = warp_m * 32 + i * 16;
            int c0 = warp_n * 64 + j * 16;
            wmma::store_matrix_sync(stg + r0 * 132 + c0, acc[i][j], 132, wmma::mem_row_major);
        }
    __syncthreads();

#pragma unroll 4
    for (int it = 0; it < 64; it++) {
        int idx = tid + it * 256;
        int r = idx >> 7, c = idx & 127;
        int gm = bm + r, gn = bn + c;
        if (gn >= N) continue;
        float tv = stg[r * 132 + c] + (bias ? bias[gn] : 0.f);
        long long ci = (long long)gm * ldc + gn;
        float outv;
        if (epi == 0) {
            outv = tv;
        } else if (epi == 1) {                 // qkv: elu+1 on q,k cols
            if (gn < 2 * D_MODEL) tv = (tv > 0.f) ? tv + 1.f : expf(tv);
            outv = tv;
        } else if (epi == 2) {                 // attn: residual + normalize
            outv = e2[ci] + tv / (e1[gm] + ATTN_EPS_F);
        } else if (epi == 3) {                 // silu
            outv = tv / (1.f + expf(-tv));
        } else {                               // 4: C *= tv (gate*up)
            outv = C[ci] * tv;
        }
        C[ci] = outv;
        if (Chi && gn < colLim) {
            bf16 h, l; split2(outv, h, l);
            long long chix = (long long)gm * ldchi + gn;
            Chi[chix] = h;  Clo[chix] = l;
        }
    }
}

// ===================== transpose + split ====================================
__global__ void __launch_bounds__(256) transpose_split_kernel(
    const float* __restrict__ in, bf16* __restrict__ ohi, bf16* __restrict__ olo,
    int R, int Ccols, int ldi, int ldo, long long sIn, long long sOut)
{
    __shared__ float tile[32][33];
    int bz = blockIdx.z;
    in  += sIn  * bz;
    ohi += sOut * bz;  olo += sOut * bz;
    int r0 = blockIdx.y * 32, c0 = blockIdx.x * 32;
    int tx = threadIdx.x & 31, ty = threadIdx.x >> 5;
#pragma unroll
    for (int i = 0; i < 32; i += 8) {
        int r = r0 + ty + i, c = c0 + tx;
        tile[ty + i][tx] = (r < R && c < Ccols) ? in[(long long)r * ldi + c] : 0.f;
    }
    __syncthreads();
#pragma unroll
    for (int i = 0; i < 32; i += 8) {
        int r = c0 + ty + i, c = r0 + tx;
        if (r < Ccols && c < R) {
            bf16 h, l; split2(tile[tx][ty + i], h, l);
            long long o = (long long)r * ldo + c;
            ohi[o] = h; olo[o] = l;
        }
    }
}

// ===================== convert + split (x) ==================================
__global__ void split_kernel(const float* __restrict__ in,
                             bf16* __restrict__ ohi, bf16* __restrict__ olo, int n)
{
    int i = blockIdx.x * 256 + threadIdx.x;
    if (i < n) {
        bf16 h, l; split2(in[i], h, l);
        ohi[i] = h; olo[i] = l;
    }
}

// ===================== ksum / den / layernorm ===============================
__global__ void ksum_part_kernel() {
    int d  = blockIdx.x * 256 + threadIdx.x;
    int b  = blockIdx.y;
    int sc = blockIdx.z;
    const float* kp = g_qkv + (size_t)b * SEQ * D3 + D_MODEL;
    int s0 = sc * (SEQ / 8);
    float s = 0.f;
    for (int i = 0; i < SEQ / 8; i++)
        s += kp[(size_t)(s0 + i) * D3 + d];
    g_kspart[(sc * BATCH + b) * D_MODEL + d] = s;
}
__global__ void ksum_reduce_kernel() {
    int i = blockIdx.x * 256 + threadIdx.x;
    if (i < BATCH * D_MODEL) {
        float s = 0.f;
        for (int c = 0; c < 8; c++) s += g_kspart[c * BATCH * D_MODEL + i];
        g_ksum[i] = s;
    }
}
__global__ void den_kernel() {
    int m = blockIdx.x * 8 + (threadIdx.x >> 5);
    int lane = threadIdx.x & 31;
    const float* q  = g_qkv + (size_t)m * D3;
    const float* ks = g_ksum + (m / SEQ) * D_MODEL;
    float s = 0.f;
    for (int d = lane; d < D_MODEL; d += 32) s += q[d] * ks[d];
#pragma unroll
    for (int o = 16; o > 0; o >>= 1) s += __shfl_xor_sync(0xffffffffu, s, o);
    if (lane == 0) g_den[m] = s;
}
__global__ void ln_kernel(const float* __restrict__ in1, const float* __restrict__ in2,
                          const float* __restrict__ gamma, const float* __restrict__ beta,
                          float* __restrict__ out,
                          bf16* __restrict__ ohi, bf16* __restrict__ olo)
{
    int row = blockIdx.x;
    int t = threadIdx.x;
    long long base = (long long)row * D_MODEL;
    float vals[4];
    float s = 0.f;
#pragma unroll
    for (int i = 0; i < 4; i++) {
        int c = t + i * 256;
        float v = in1[base + c];
        if (in2) v += in2[base + c];
        vals[i] = v; s += v;
    }
    __shared__ float red[256];
    red[t] = s; __syncthreads();
    for (int o = 128; o > 0; o >>= 1) { if (t < o) red[t] += red[t + o]; __syncthreads(); }
    float mu = red[0] * (1.f / D_MODEL);
    __syncthreads();
    float vs = 0.f;
#pragma unroll
    for (int i = 0; i < 4; i++) { float d = vals[i] - mu; vs += d * d; }
    red[t] = vs; __syncthreads();
    for (int o = 128; o > 0; o >>= 1) { if (t < o) red[t] += red[t + o]; __syncthreads(); }
    float inv = rsqrtf(red[0] * (1.f / D_MODEL) + LN_EPS_F);
#pragma unroll
    for (int i = 0; i < 4; i++) {
        int c = t + i * 256;
        float v = (vals[i] - mu) * inv * gamma[c] + beta[c];
        out[base + c] = v;
        if (ohi) {
            bf16 h, l; split2(v, h, l);
            ohi[base + c] = h; olo[base + c] = l;
        }
    }
}

// ===================== launch ===============================================
extern "C" void kernel_launch(void* const* d_in, const int* in_sizes, int n_in,
                              void* d_out, int out_size)
{
    const float* x    = (const float*)d_in[0];
    const float* Wqkv = (const float*)d_in[1];
    const float* bqkv = (const float*)d_in[2];
    const float* Wg   = (const float*)d_in[3];
    const float* bg   = (const float*)d_in[4];
    const float* Wu   = (const float*)d_in[5];
    const float* bu   = (const float*)d_in[6];
    const float* Wd   = (const float*)d_in[7];
    const float* bd   = (const float*)d_in[8];
    const float* g1   = (const float*)d_in[9];
    const float* b1   = (const float*)d_in[10];
    const float* g2   = (const float*)d_in[11];
    const float* b2   = (const float*)d_in[12];
    float* out = (float*)d_out;

    float *qkv, *kvf, *den, *yb, *x1, *h, *ffn;
    bf16 *xhi,*xlo,*qphi,*qplo,*WqkvThi,*WqkvTlo,*WgThi,*WgTlo,*WuThi,*WuTlo,*WdThi,*WdTlo;
    bf16 *kpThi,*kpTlo,*vThi,*vTlo,*kvhi,*kvlo,*x1hi,*x1lo,*hhi,*hlo;
    cudaGetSymbolAddress((void**)&qkv,  g_qkv);
    cudaGetSymbolAddress((void**)&kvf,  g_kv);
    cudaGetSymbolAddress((void**)&den,  g_den);
    cudaGetSymbolAddress((void**)&yb,   g_y);
    cudaGetSymbolAddress((void**)&x1,   g_x1);
    cudaGetSymbolAddress((void**)&h,    g_h);
    cudaGetSymbolAddress((void**)&ffn,  g_ffn);
    cudaGetSymbolAddress((void**)&xhi,  g_xhi);     cudaGetSymbolAddress((void**)&xlo,  g_xlo);
    cudaGetSymbolAddress((void**)&qphi, g_qphi);    cudaGetSymbolAddress((void**)&qplo, g_qplo);
    cudaGetSymbolAddress((void**)&WqkvThi, g_WqkvThi); cudaGetSymbolAddress((void**)&WqkvTlo, g_WqkvTlo);
    cudaGetSymbolAddress((void**)&WgThi, g_WgThi);  cudaGetSymbolAddress((void**)&WgTlo, g_WgTlo);
    cudaGetSymbolAddress((void**)&WuThi, g_WuThi);  cudaGetSymbolAddress((void**)&WuTlo, g_WuTlo);
    cudaGetSymbolAddress((void**)&WdThi, g_WdThi);  cudaGetSymbolAddress((void**)&WdTlo, g_WdTlo);
    cudaGetSymbolAddress((void**)&kpThi, g_kpThi);  cudaGetSymbolAddress((void**)&kpTlo, g_kpTlo);
    cudaGetSymbolAddress((void**)&vThi,  g_vThi);   cudaGetSymbolAddress((void**)&vTlo,  g_vTlo);
    cudaGetSymbolAddress((void**)&kvhi,  g_kvhi);   cudaGetSymbolAddress((void**)&kvlo,  g_kvlo);
    cudaGetSymbolAddress((void**)&x1hi,  g_x1hi);   cudaGetSymbolAddress((void**)&x1lo,  g_x1lo);
    cudaGetSymbolAddress((void**)&hhi,   g_hhi);    cudaGetSymbolAddress((void**)&hlo,   g_hlo);

    cudaFuncSetAttribute(mma_gemm_kernel,
                         cudaFuncAttributeMaxDynamicSharedMemorySize, SMEM_SZ);

    dim3 blk(256);
    const long long SD3  = (long long)SEQ * D3;
    const long long SDM  = (long long)SEQ * D_MODEL;
    const long long DD   = (long long)D_MODEL * D_MODEL;
    const long long DS   = (long long)D_MODEL * SEQ;

    // ---- splits & transposes ----
    split_kernel<<<(MTOT * D_MODEL) / 256, blk>>>(x, xhi, xlo, MTOT * D_MODEL);
    transpose_split_kernel<<<dim3(D3/32, D_MODEL/32, 1), blk>>>(
        Wqkv, WqkvThi, WqkvTlo, D_MODEL, D3, D3, D_MODEL, 0, 0);
    transpose_split_kernel<<<dim3((HFF+31)/32, D_MODEL/32, 1), blk>>>(
        Wg, WgThi, WgTlo, D_MODEL, HFF, HFF, D_MODEL, 0, 0);
    transpose_split_kernel<<<dim3((HFF+31)/32, D_MODEL/32, 1), blk>>>(
        Wu, WuThi, WuTlo, D_MODEL, HFF, HFF, D_MODEL, 0, 0);
    transpose_split_kernel<<<dim3(D_MODEL/32, (HFF+31)/32, 1), blk>>>(
        Wd, WdThi, WdTlo, HFF, D_MODEL, D_MODEL, HFFP, 0, 0);

    // ---- 1) qkv = x @ Wqkv + bqkv (elu+1 on q,k); qp hi/lo fused out ----
    mma_gemm_kernel<<<dim3(D3/BN, MTOT/BM, 1), blk, SMEM_SZ>>>(
        xhi, xlo, WqkvThi, WqkvTlo, bqkv, qkv, qphi, qplo,
        MTOT, D3, D_MODEL, D_MODEL, D_MODEL, D3, D_MODEL,
        0, 0, 0, 0, 1, D_MODEL, nullptr, nullptr, 0);

    // ---- kp^T, v^T hi/lo (per batch) ----
    transpose_split_kernel<<<dim3(D_MODEL/32, SEQ/32, BATCH), blk>>>(
        qkv + D_MODEL, kpThi, kpTlo, SEQ, D_MODEL, D3, SEQ, SD3, DS);
    transpose_split_kernel<<<dim3(D_MODEL/32, SEQ/32, BATCH), blk>>>(
        qkv + 2*D_MODEL, vThi, vTlo, SEQ, D_MODEL, D3, SEQ, SD3, DS);

    // ---- ksum, den ----
    ksum_part_kernel<<<dim3(4, BATCH, 8), blk>>>();
    ksum_reduce_kernel<<<16, blk>>>();
    den_kernel<<<MTOT/8, blk>>>();

    // ---- 2) kvT[e][d] = sum_s v[s,e] kp[s,d]; hi/lo fused out ----
    mma_gemm_kernel<<<dim3(D_MODEL/BN, D_MODEL/BM, BATCH), blk, SMEM_SZ>>>(
        vThi, vTlo, kpThi, kpTlo, nullptr, kvf, kvhi, kvlo,
        D_MODEL, D_MODEL, SEQ, SEQ, SEQ, D_MODEL, D_MODEL,
        DS, DS, DD, DD, 0, D_MODEL, nullptr, nullptr, 0);

    // ---- 3) y = x + (qp @ kv) / (den + eps) ----
    mma_gemm_kernel<<<dim3(D_MODEL/BN, SEQ/BM, BATCH), blk, SMEM_SZ>>>(
        qphi, qplo, kvhi, kvlo, nullptr, yb, nullptr, nullptr,
        SEQ, D_MODEL, D_MODEL, D_MODEL, D_MODEL, D_MODEL, D_MODEL,
        SDM, DD, SDM, 0, 2, 0, den, x, (long long)SEQ);

    // ---- 4) x1 = LN(y); hi/lo fused ----
    ln_kernel<<<MTOT, blk>>>(yb, nullptr, g1, b1, x1, x1hi, x1lo);

    // ---- 5) h = silu(x1 @ Wg + bg) ----
    mma_gemm_kernel<<<dim3((HFF+BN-1)/BN, MTOT/BM, 1), blk, SMEM_SZ>>>(
        x1hi, x1lo, WgThi, WgTlo, bg, h, nullptr, nullptr,
        MTOT, HFF, D_MODEL, D_MODEL, D_MODEL, HFF, HFF,
        0, 0, 0, 0, 3, 0, nullptr, nullptr, 0);

    // ---- 6) h *= (x1 @ Wu + bu); h hi/lo fused out (padded ld) ----
    mma_gemm_kernel<<<dim3((HFF+BN-1)/BN, MTOT/BM, 1), blk, SMEM_SZ>>>(
        x1hi, x1lo, WuThi, WuTlo, bu, h, hhi, hlo,
        MTOT, HFF, D_MODEL, D_MODEL, D_MODEL, HFF, HFFP,
        0, 0, 0, 0, 4, HFF, nullptr, nullptr, 0);

    // ---- 7) ffn = h @ Wd + bd (padded strides for 16B cp.async alignment) ----
    mma_gemm_kernel<<<dim3(D_MODEL/BN, MTOT/BM, 1), blk, SMEM_SZ>>>(
        hhi, hlo, WdThi, WdTlo, bd, ffn, nullptr, nullptr,
        MTOT, D_MODEL, HFF, HFFP, HFFP, D_MODEL, D_MODEL,
        0, 0, 0, 0, 0, 0, nullptr, nullptr, 0);

    // ---- 8) out = LN(x1 + ffn) ----
    ln_kernel<<<MTOT, blk>>>(x1, ffn, g2, b2, out, nullptr, nullptr);
}

// round 5
// speedup vs baseline: 3.7042x; 1.8733x over previous
#include <cuda_runtime.h>
#include <cuda_fp16.h>
#include <mma.h>
#include <cstdint>
#include <math.h>

using namespace nvcuda;

#define D_MODEL 1024
#define D3      3072
#define HFF     2730
#define HFFP    2736                 // HFF padded to 8-element (16B) multiple
#define BATCH   4
#define SEQ     4096
#define MTOT    (BATCH*SEQ)          // 16384

#define LN_EPS_F   1e-5f
#define ATTN_EPS_F 1e-6f

typedef __half fp16;

// ===================== scratch ==============================================
__device__ float g_qkv[(size_t)MTOT * D3];          // fp32 qkv (elu+1 on q,k)
__device__ fp16  g_xh  [(size_t)MTOT * D_MODEL];
__device__ fp16  g_qph [(size_t)MTOT * D_MODEL];
__device__ fp16  g_WqkvT[(size_t)D3 * D_MODEL];
__device__ fp16  g_WgT [(size_t)HFF * D_MODEL];
__device__ fp16  g_WuT [(size_t)HFF * D_MODEL];
__device__ fp16  g_WdT [(size_t)D_MODEL * HFFP];    // padded ld
__device__ fp16  g_kpT [(size_t)BATCH * D_MODEL * SEQ];
__device__ fp16  g_vT  [(size_t)BATCH * D_MODEL * SEQ];
__device__ float g_kv  [(size_t)BATCH * D_MODEL * D_MODEL];
__device__ fp16  g_kvh [(size_t)BATCH * D_MODEL * D_MODEL];
__device__ float g_kspart[8 * BATCH * D_MODEL];
__device__ float g_ksum[BATCH * D_MODEL];
__device__ float g_den[MTOT];
__device__ float g_y [(size_t)MTOT * D_MODEL];
__device__ float g_x1[(size_t)MTOT * D_MODEL];
__device__ fp16  g_x1h[(size_t)MTOT * D_MODEL];
__device__ float g_h [(size_t)MTOT * HFF];
__device__ fp16  g_hh[(size_t)MTOT * HFFP];         // padded ld
__device__ float g_ffn[(size_t)MTOT * D_MODEL];

// ===================== helpers ==============================================
__device__ __forceinline__ uint32_t smem_u32(const void* p) {
    uint32_t a;
    asm("{ .reg .u64 t; cvta.to.shared.u64 t, %1; cvt.u32.u64 %0, t; }" : "=r"(a) : "l"(p));
    return a;
}
__device__ __forceinline__ void cp16(uint32_t dst, const void* src, int bytes) {
    asm volatile("cp.async.cg.shared.global [%0], [%1], 16, %2;\n"
        :: "r"(dst), "l"(src), "r"(bytes));
}
#define CP_COMMIT() asm volatile("cp.async.commit_group;\n" ::: "memory")
#define CP_WAIT(n)  asm volatile("cp.async.wait_group %0;\n" :: "n"(n) : "memory")

// ===================== WMMA fp16 GEMM (single-MMA, fp32 accum) ==============
// C[m,n] = sum_k A[m,k] * Bt[n,k]  (fp16 operands, Bt = B^T [N][K] row-major)
// BM=128, BN=128, BK=32, 256 threads (8 warps, 32x64 warp tiles),
// 3-stage cp.async pipeline. Fused epilogues; optional fp16 C copy.
// lda/ldb MUST be multiples of 8 elements (16B cp.async alignment).
#define BM 128
#define BN 128
#define BK 32
#define SROW 40                       // halves per smem row (32 + 8 pad)
#define AB_HALVES (128 * SROW)
#define STAGE_B (2 * AB_HALVES * 2)   // A + B tiles = 20480 bytes
#define NSTAGE 3
#define SMEM_SZ 67584                 // epilogue staging 128*132*4 dominates

typedef wmma::fragment<wmma::matrix_a, 16, 16, 16, fp16, wmma::row_major> FragA;
typedef wmma::fragment<wmma::matrix_b, 16, 16, 16, fp16, wmma::col_major> FragB;
typedef wmma::fragment<wmma::accumulator, 16, 16, 16, float> FragC;

__global__ void __launch_bounds__(256, 1) mma_gemm_kernel(
    const fp16* __restrict__ Ah, const fp16* __restrict__ Bh,
    const float* __restrict__ bias, float* __restrict__ C,
    fp16* __restrict__ Ch,
    int M, int N, int K, int lda, int ldb, int ldc, int ldch,
    long long sA, long long sB, long long sC, long long sCh,
    int epi, int colLim,
    const float* __restrict__ e1, const float* __restrict__ e2, long long sE1)
{
    extern __shared__ __align__(16) char smem[];
    const uint32_t sbase = smem_u32(smem);
    const int tid = threadIdx.x;
    const int wid = tid >> 5;
    const int warp_m = wid & 3;        // 4 m-warps of 32 rows
    const int warp_n = wid >> 2;       // 2 n-warps of 64 cols
    const int bz = blockIdx.z;
    Ah += sA * bz;  Bh += sB * bz;  C += sC * bz;
    if (Ch) Ch += sCh * bz;
    if (e1) e1 += sE1 * bz;
    if (e2) e2 += sC * bz;
    const int bm = blockIdx.y * BM;
    const int bn = blockIdx.x * BN;

    FragC acc[2][4];
#pragma unroll
    for (int i = 0; i < 2; i++)
#pragma unroll
        for (int j = 0; j < 4; j++) wmma::fill_fragment(acc[i][j], 0.f);

    const int ntiles = (K + BK - 1) / BK;

    auto load_stage = [&](int s, int t) {
        uint32_t sb = sbase + s * STAGE_B;
        int k0 = t * BK;
#pragma unroll
        for (int j = 0; j < 2; j++) {
            int idx = tid + j * 256;
            int r = idx >> 2, ch = idx & 3;
            int kc = k0 + ch * 8;
            int ab = 2 * (K - kc); ab = ab < 0 ? 0 : (ab > 16 ? 16 : ab);
            long long aoff = (long long)(bm + r) * lda + kc;
            uint32_t d = sb + (r * SROW + ch * 8) * 2;
            cp16(d, Ah + aoff, ab);
            int gn = bn + r;
            int bb = (gn < N) ? ab : 0;
            long long boff = (long long)(gn < N ? gn : 0) * ldb + kc;
            cp16(d + AB_HALVES * 2, Bh + boff, bb);
        }
    };

    load_stage(0, 0); CP_COMMIT();
    if (ntiles > 1) load_stage(1, 1);
    CP_COMMIT();
    if (ntiles > 2) load_stage(2, 2);
    CP_COMMIT();

    int s = 0;
    for (int t = 0; t < ntiles; t++) {
        CP_WAIT(2);
        __syncthreads();
        const fp16* base = (const fp16*)(smem + s * STAGE_B);
        const fp16* sAh = base;
        const fp16* sBh = base + AB_HALVES;
#pragma unroll
        for (int kk = 0; kk < 2; kk++) {
            FragA a[2];
            FragB b[4];
#pragma unroll
            for (int i = 0; i < 2; i++)
                wmma::load_matrix_sync(a[i], sAh + (warp_m * 32 + i * 16) * SROW + kk * 16, SROW);
#pragma unroll
            for (int j = 0; j < 4; j++)
                wmma::load_matrix_sync(b[j], sBh + (warp_n * 64 + j * 16) * SROW + kk * 16, SROW);
#pragma unroll
            for (int i = 0; i < 2; i++)
#pragma unroll
                for (int j = 0; j < 4; j++)
                    wmma::mma_sync(acc[i][j], a[i], b[j], acc[i][j]);
        }
        __syncthreads();
        if (t + NSTAGE < ntiles) load_stage(s, t + NSTAGE);
        CP_COMMIT();
        s = (s == NSTAGE - 1) ? 0 : s + 1;
    }
    CP_WAIT(0);
    __syncthreads();

    // ---- epilogue via SMEM staging (128 x 132 floats) ----
    float* stg = (float*)smem;
#pragma unroll
    for (int i = 0; i < 2; i++)
#pragma unroll
        for (int j = 0; j < 4; j++) {
            int r0 = warp_m * 32 + i * 16;
            int c0 = warp_n * 64 + j * 16;
            wmma::store_matrix_sync(stg + r0 * 132 + c0, acc[i][j], 132, wmma::mem_row_major);
        }
    __syncthreads();

#pragma unroll 4
    for (int it = 0; it < 64; it++) {
        int idx = tid + it * 256;
        int r = idx >> 7, c = idx & 127;
        int gm = bm + r, gn = bn + c;
        if (gn >= N) continue;
        float tv = stg[r * 132 + c] + (bias ? bias[gn] : 0.f);
        long long ci = (long long)gm * ldc + gn;
        float outv;
        if (epi == 0) {
            outv = tv;
        } else if (epi == 1) {                 // qkv: elu+1 on q,k cols
            if (gn < 2 * D_MODEL) tv = (tv > 0.f) ? tv + 1.f : expf(tv);
            outv = tv;
        } else if (epi == 2) {                 // attn: residual + normalize
            outv = e2[ci] + tv / (e1[gm] + ATTN_EPS_F);
        } else if (epi == 3) {                 // silu
            outv = tv / (1.f + expf(-tv));
        } else {                               // 4: C *= tv (gate*up)
            outv = C[ci] * tv;
        }
        C[ci] = outv;
        if (Ch && gn < colLim)
            Ch[(long long)gm * ldch + gn] = __float2half(outv);
    }
}

// ===================== transpose (fp32 -> fp16) =============================
__global__ void __launch_bounds__(256) transpose_h_kernel(
    const float* __restrict__ in, fp16* __restrict__ oh,
    int R, int Ccols, int ldi, int ldo, long long sIn, long long sOut)
{
    __shared__ float tile[32][33];
    int bz = blockIdx.z;
    in += sIn * bz;
    oh += sOut * bz;
    int r0 = blockIdx.y * 32, c0 = blockIdx.x * 32;
    int tx = threadIdx.x & 31, ty = threadIdx.x >> 5;
#pragma unroll
    for (int i = 0; i < 32; i += 8) {
        int r = r0 + ty + i, c = c0 + tx;
        tile[ty + i][tx] = (r < R && c < Ccols) ? in[(long long)r * ldi + c] : 0.f;
    }
    __syncthreads();
#pragma unroll
    for (int i = 0; i < 32; i += 8) {
        int r = c0 + ty + i, c = r0 + tx;
        if (r < Ccols && c < R)
            oh[(long long)r * ldo + c] = __float2half(tile[tx][ty + i]);
    }
}

// ===================== convert (x -> fp16) ==================================
__global__ void conv_kernel(const float* __restrict__ in, fp16* __restrict__ oh, int n)
{
    int i = blockIdx.x * 256 + threadIdx.x;
    if (i < n) oh[i] = __float2half(in[i]);
}

// ===================== ksum / den / layernorm ===============================
__global__ void ksum_part_kernel() {
    int d  = blockIdx.x * 256 + threadIdx.x;
    int b  = blockIdx.y;
    int sc = blockIdx.z;
    const float* kp = g_qkv + (size_t)b * SEQ * D3 + D_MODEL;
    int s0 = sc * (SEQ / 8);
    float s = 0.f;
    for (int i = 0; i < SEQ / 8; i++)
        s += kp[(size_t)(s0 + i) * D3 + d];
    g_kspart[(sc * BATCH + b) * D_MODEL + d] = s;
}
__global__ void ksum_reduce_kernel() {
    int i = blockIdx.x * 256 + threadIdx.x;
    if (i < BATCH * D_MODEL) {
        float s = 0.f;
        for (int c = 0; c < 8; c++) s += g_kspart[c * BATCH * D_MODEL + i];
        g_ksum[i] = s;
    }
}
__global__ void den_kernel() {
    int m = blockIdx.x * 8 + (threadIdx.x >> 5);
    int lane = threadIdx.x & 31;
    const float* q  = g_qkv + (size_t)m * D3;
    const float* ks = g_ksum + (m / SEQ) * D_MODEL;
    float s = 0.f;
    for (int d = lane; d < D_MODEL; d += 32) s += q[d] * ks[d];
#pragma unroll
    for (int o = 16; o > 0; o >>= 1) s += __shfl_xor_sync(0xffffffffu, s, o);
    if (lane == 0) g_den[m] = s;
}
__global__ void ln_kernel(const float* __restrict__ in1, const float* __restrict__ in2,
                          const float* __restrict__ gamma, const float* __restrict__ beta,
                          float* __restrict__ out, fp16* __restrict__ oh)
{
    int row = blockIdx.x;
    int t = threadIdx.x;
    long long base = (long long)row * D_MODEL;
    float vals[4];
    float s = 0.f;
#pragma unroll
    for (int i = 0; i < 4; i++) {
        int c = t + i * 256;
        float v = in1[base + c];
        if (in2) v += in2[base + c];
        vals[i] = v; s += v;
    }
    __shared__ float red[256];
    red[t] = s; __syncthreads();
    for (int o = 128; o > 0; o >>= 1) { if (t < o) red[t] += red[t + o]; __syncthreads(); }
    float mu = red[0] * (1.f / D_MODEL);
    __syncthreads();
    float vs = 0.f;
#pragma unroll
    for (int i = 0; i < 4; i++) { float d = vals[i] - mu; vs += d * d; }
    red[t] = vs; __syncthreads();
    for (int o = 128; o > 0; o >>= 1) { if (t < o) red[t] += red[t + o]; __syncthreads(); }
    float inv = rsqrtf(red[0] * (1.f / D_MODEL) + LN_EPS_F);
#pragma unroll
    for (int i = 0; i < 4; i++) {
        int c = t + i * 256;
        float v = (vals[i] - mu) * inv * gamma[c] + beta[c];
        out[base + c] = v;
        if (oh) oh[base + c] = __float2half(v);
    }
}

// ===================== launch ===============================================
extern "C" void kernel_launch(void* const* d_in, const int* in_sizes, int n_in,
                              void* d_out, int out_size)
{
    const float* x    = (const float*)d_in[0];
    const float* Wqkv = (const float*)d_in[1];
    const float* bqkv = (const float*)d_in[2];
    const float* Wg   = (const float*)d_in[3];
    const float* bg   = (const float*)d_in[4];
    const float* Wu   = (const float*)d_in[5];
    const float* bu   = (const float*)d_in[6];
    const float* Wd   = (const float*)d_in[7];
    const float* bd   = (const float*)d_in[8];
    const float* g1   = (const float*)d_in[9];
    const float* b1   = (const float*)d_in[10];
    const float* g2   = (const float*)d_in[11];
    const float* b2   = (const float*)d_in[12];
    float* out = (float*)d_out;

    float *qkv, *kvf, *den, *yb, *x1, *h, *ffn;
    fp16 *xh,*qph,*WqkvT,*WgT,*WuT,*WdT,*kpT,*vT,*kvh,*x1h,*hh;
    cudaGetSymbolAddress((void**)&qkv,  g_qkv);
    cudaGetSymbolAddress((void**)&kvf,  g_kv);
    cudaGetSymbolAddress((void**)&den,  g_den);
    cudaGetSymbolAddress((void**)&yb,   g_y);
    cudaGetSymbolAddress((void**)&x1,   g_x1);
    cudaGetSymbolAddress((void**)&h,    g_h);
    cudaGetSymbolAddress((void**)&ffn,  g_ffn);
    cudaGetSymbolAddress((void**)&xh,   g_xh);
    cudaGetSymbolAddress((void**)&qph,  g_qph);
    cudaGetSymbolAddress((void**)&WqkvT,g_WqkvT);
    cudaGetSymbolAddress((void**)&WgT,  g_WgT);
    cudaGetSymbolAddress((void**)&WuT,  g_WuT);
    cudaGetSymbolAddress((void**)&WdT,  g_WdT);
    cudaGetSymbolAddress((void**)&kpT,  g_kpT);
    cudaGetSymbolAddress((void**)&vT,   g_vT);
    cudaGetSymbolAddress((void**)&kvh,  g_kvh);
    cudaGetSymbolAddress((void**)&x1h,  g_x1h);
    cudaGetSymbolAddress((void**)&hh,   g_hh);

    cudaFuncSetAttribute(mma_gemm_kernel,
                         cudaFuncAttributeMaxDynamicSharedMemorySize, SMEM_SZ);

    dim3 blk(256);
    const long long SD3  = (long long)SEQ * D3;
    const long long SDM  = (long long)SEQ * D_MODEL;
    const long long DD   = (long long)D_MODEL * D_MODEL;
    const long long DS   = (long long)D_MODEL * SEQ;

    // ---- converts & transposes ----
    conv_kernel<<<(MTOT * D_MODEL) / 256, blk>>>(x, xh, MTOT * D_MODEL);
    transpose_h_kernel<<<dim3(D3/32, D_MODEL/32, 1), blk>>>(
        Wqkv, WqkvT, D_MODEL, D3, D3, D_MODEL, 0, 0);
    transpose_h_kernel<<<dim3((HFF+31)/32, D_MODEL/32, 1), blk>>>(
        Wg, WgT, D_MODEL, HFF, HFF, D_MODEL, 0, 0);
    transpose_h_kernel<<<dim3((HFF+31)/32, D_MODEL/32, 1), blk>>>(
        Wu, WuT, D_MODEL, HFF, HFF, D_MODEL, 0, 0);
    transpose_h_kernel<<<dim3(D_MODEL/32, (HFF+31)/32, 1), blk>>>(
        Wd, WdT, HFF, D_MODEL, D_MODEL, HFFP, 0, 0);

    // ---- 1) qkv = x @ Wqkv + bqkv (elu+1 on q,k); qp fp16 fused out ----
    mma_gemm_kernel<<<dim3(D3/BN, MTOT/BM, 1), blk, SMEM_SZ>>>(
        xh, WqkvT, bqkv, qkv, qph,
        MTOT, D3, D_MODEL, D_MODEL, D_MODEL, D3, D_MODEL,
        0, 0, 0, 0, 1, D_MODEL, nullptr, nullptr, 0);

    // ---- kp^T, v^T fp16 (per batch) ----
    transpose_h_kernel<<<dim3(D_MODEL/32, SEQ/32, BATCH), blk>>>(
        qkv + D_MODEL, kpT, SEQ, D_MODEL, D3, SEQ, SD3, DS);
    transpose_h_kernel<<<dim3(D_MODEL/32, SEQ/32, BATCH), blk>>>(
        qkv + 2*D_MODEL, vT, SEQ, D_MODEL, D3, SEQ, SD3, DS);

    // ---- ksum, den (fp32 side) ----
    ksum_part_kernel<<<dim3(4, BATCH, 8), blk>>>();
    ksum_reduce_kernel<<<16, blk>>>();
    den_kernel<<<MTOT/8, blk>>>();

    // ---- 2) kvT[e][d] = sum_s v[s,e] kp[s,d]; fp16 fused out ----
    mma_gemm_kernel<<<dim3(D_MODEL/BN, D_MODEL/BM, BATCH), blk, SMEM_SZ>>>(
        vT, kpT, nullptr, kvf, kvh,
        D_MODEL, D_MODEL, SEQ, SEQ, SEQ, D_MODEL, D_MODEL,
        DS, DS, DD, DD, 0, D_MODEL, nullptr, nullptr, 0);

    // ---- 3) y = x + (qp @ kv) / (den + eps) ----
    mma_gemm_kernel<<<dim3(D_MODEL/BN, SEQ/BM, BATCH), blk, SMEM_SZ>>>(
        qph, kvh, nullptr, yb, nullptr,
        SEQ, D_MODEL, D_MODEL, D_MODEL, D_MODEL, D_MODEL, D_MODEL,
        SDM, DD, SDM, 0, 2, 0, den, x, (long long)SEQ);

    // ---- 4) x1 = LN(y); fp16 fused ----
    ln_kernel<<<MTOT, blk>>>(yb, nullptr, g1, b1, x1, x1h);

    // ---- 5) h = silu(x1 @ Wg + bg) ----
    mma_gemm_kernel<<<dim3((HFF+BN-1)/BN, MTOT/BM, 1), blk, SMEM_SZ>>>(
        x1h, WgT, bg, h, nullptr,
        MTOT, HFF, D_MODEL, D_MODEL, D_MODEL, HFF, HFF,
        0, 0, 0, 0, 3, 0, nullptr, nullptr, 0);

    // ---- 6) h *= (x1 @ Wu + bu); fp16 fused out (padded ld) ----
    mma_gemm_kernel<<<dim3((HFF+BN-1)/BN, MTOT/BM, 1), blk, SMEM_SZ>>>(
        x1h, WuT, bu, h, hh,
        MTOT, HFF, D_MODEL, D_MODEL, D_MODEL, HFF, HFFP,
        0, 0, 0, 0, 4, HFF, nullptr, nullptr, 0);

    // ---- 7) ffn = h @ Wd + bd (padded strides, 16B cp.async alignment) ----
    mma_gemm_kernel<<<dim3(D_MODEL/BN, MTOT/BM, 1), blk, SMEM_SZ>>>(
        hh, WdT, bd, ffn, nullptr,
        MTOT, D_MODEL, HFF, HFFP, HFFP, D_MODEL, D_MODEL,
        0, 0, 0, 0, 0, 0, nullptr, nullptr, 0);

    // ---- 8) out = LN(x1 + ffn) ----
    ln_kernel<<<MTOT, blk>>>(x1, ffn, g2, b2, out, nullptr);
}

// round 6
// speedup vs baseline: 3.9634x; 1.0700x over previous
#include <cuda_runtime.h>
#include <cuda_fp16.h>
#include <mma.h>
#include <cstdint>
#include <math.h>

using namespace nvcuda;

#define D_MODEL 1024
#define D3      3072
#define HFF     2730
#define HFFP    2736                 // HFF padded to 8-element (16B) multiple
#define BATCH   4
#define SEQ     4096
#define MTOT    (BATCH*SEQ)          // 16384

#define LN_EPS_F   1e-5f
#define ATTN_EPS_F 1e-6f

typedef __half fp16;

// ===================== scratch ==============================================
__device__ fp16  g_qkvh[(size_t)MTOT * D3];         // fp16 qkv (elu+1 on q,k)
__device__ fp16  g_xh  [(size_t)MTOT * D_MODEL];
__device__ fp16  g_WqkvT[(size_t)D3 * D_MODEL];
__device__ fp16  g_WgT [(size_t)HFF * D_MODEL];
__device__ fp16  g_WuT [(size_t)HFF * D_MODEL];
__device__ fp16  g_WdT [(size_t)D_MODEL * HFFP];    // padded ld
__device__ fp16  g_kpT [(size_t)BATCH * D_MODEL * SEQ];
__device__ fp16  g_vT  [(size_t)BATCH * D_MODEL * SEQ];
__device__ fp16  g_kvh [(size_t)BATCH * D_MODEL * D_MODEL];
__device__ float g_kspart[8 * BATCH * D_MODEL];
__device__ float g_ksum[BATCH * D_MODEL];
__device__ float g_den[MTOT];
__device__ float g_y [(size_t)MTOT * D_MODEL];
__device__ float g_x1[(size_t)MTOT * D_MODEL];
__device__ fp16  g_x1h[(size_t)MTOT * D_MODEL];
__device__ float g_h [(size_t)MTOT * HFF];
__device__ fp16  g_hh[(size_t)MTOT * HFFP];         // padded ld
__device__ float g_ffn[(size_t)MTOT * D_MODEL];

// ===================== helpers ==============================================
__device__ __forceinline__ uint32_t smem_u32(const void* p) {
    uint32_t a;
    asm("{ .reg .u64 t; cvta.to.shared.u64 t, %1; cvt.u32.u64 %0, t; }" : "=r"(a) : "l"(p));
    return a;
}
__device__ __forceinline__ void cp16(uint32_t dst, const void* src, int bytes) {
    asm volatile("cp.async.cg.shared.global [%0], [%1], 16, %2;\n"
        :: "r"(dst), "l"(src), "r"(bytes));
}
#define CP_COMMIT() asm volatile("cp.async.commit_group;\n" ::: "memory")
#define CP_WAIT(n)  asm volatile("cp.async.wait_group %0;\n" :: "n"(n) : "memory")

// ===================== WMMA fp16 GEMM (single-MMA, fp32 accum) ==============
// C[m,n] = sum_k A[m,k] * Bt[n,k]  (fp16 operands, Bt = B^T [N][K] row-major)
// BM=128, BN=256, BK=32. 8 warps, each a 64x64 warp tile (2 m-warps x 4 n-warps).
// 3-stage cp.async pipeline. Fused epilogues; optional fp32/fp16 C outputs.
// lda/ldb MUST be multiples of 8 elements (16B cp.async alignment).
#define BM 128
#define BN 256
#define BK 32
#define SROW 40                       // halves per smem row (32 + 8 pad)
#define A_HALVES (128 * SROW)         // 5120
#define B_HALVES (256 * SROW)         // 10240
#define STAGE_B ((A_HALVES + B_HALVES) * 2)   // 30720 bytes
#define NSTAGE 3
#define SMEM_SZ (NSTAGE * STAGE_B)    // 92160 (epilogue staging 67584 fits)

typedef wmma::fragment<wmma::matrix_a, 16, 16, 16, fp16, wmma::row_major> FragA;
typedef wmma::fragment<wmma::matrix_b, 16, 16, 16, fp16, wmma::col_major> FragB;
typedef wmma::fragment<wmma::accumulator, 16, 16, 16, float> FragC;

__global__ void __launch_bounds__(256, 1) mma_gemm_kernel(
    const fp16* __restrict__ Ah, const fp16* __restrict__ Bh,
    const float* __restrict__ bias, float* __restrict__ C,
    fp16* __restrict__ Ch,
    int M, int N, int K, int lda, int ldb, int ldc, int ldch,
    long long sA, long long sB, long long sC, long long sCh,
    int epi, int colLim,
    const float* __restrict__ e1, const float* __restrict__ e2, long long sE1)
{
    extern __shared__ __align__(16) char smem[];
    const uint32_t sbase = smem_u32(smem);
    const int tid = threadIdx.x;
    const int wid = tid >> 5;
    const int warp_m = wid & 1;        // 2 m-warps of 64 rows
    const int warp_n = wid >> 1;       // 4 n-warps of 64 cols
    const int bz = blockIdx.z;
    Ah += sA * bz;  Bh += sB * bz;
    if (C)  C  += sC * bz;
    if (Ch) Ch += sCh * bz;
    if (e1) e1 += sE1 * bz;
    if (e2) e2 += sC * bz;
    const int bm = blockIdx.y * BM;
    const int bn = blockIdx.x * BN;

    FragC acc[4][4];
#pragma unroll
    for (int i = 0; i < 4; i++)
#pragma unroll
        for (int j = 0; j < 4; j++) wmma::fill_fragment(acc[i][j], 0.f);

    const int ntiles = (K + BK - 1) / BK;

    auto load_stage = [&](int s, int t) {
        uint32_t sb = sbase + s * STAGE_B;
        int k0 = t * BK;
        // A tile: 128 rows x 4 16B-chunks = 512 chunks
#pragma unroll
        for (int j = 0; j < 2; j++) {
            int idx = tid + j * 256;
            int r = idx >> 2, ch = idx & 3;
            int kc = k0 + ch * 8;
            int ab = 2 * (K - kc); ab = ab < 0 ? 0 : (ab > 16 ? 16 : ab);
            cp16(sb + (r * SROW + ch * 8) * 2, Ah + (long long)(bm + r) * lda + kc, ab);
        }
        // B tile: 256 rows x 4 chunks = 1024 chunks
#pragma unroll
        for (int j = 0; j < 4; j++) {
            int idx = tid + j * 256;
            int r = idx >> 2, ch = idx & 3;
            int kc = k0 + ch * 8;
            int ab = 2 * (K - kc); ab = ab < 0 ? 0 : (ab > 16 ? 16 : ab);
            int gn = bn + r;
            int bb = (gn < N) ? ab : 0;
            cp16(sb + A_HALVES * 2 + (r * SROW + ch * 8) * 2,
                 Bh + (long long)(gn < N ? gn : 0) * ldb + kc, bb);
        }
    };

    load_stage(0, 0); CP_COMMIT();
    if (ntiles > 1) load_stage(1, 1);
    CP_COMMIT();
    if (ntiles > 2) load_stage(2, 2);
    CP_COMMIT();

    int s = 0;
    for (int t = 0; t < ntiles; t++) {
        CP_WAIT(2);
        __syncthreads();
        const fp16* base = (const fp16*)(smem + s * STAGE_B);
        const fp16* sAh = base;
        const fp16* sBh = base + A_HALVES;
#pragma unroll
        for (int kk = 0; kk < 2; kk++) {
            FragA a[4];
            FragB b[4];
#pragma unroll
            for (int i = 0; i < 4; i++)
                wmma::load_matrix_sync(a[i], sAh + (warp_m * 64 + i * 16) * SROW + kk * 16, SROW);
#pragma unroll
            for (int j = 0; j < 4; j++)
                wmma::load_matrix_sync(b[j], sBh + (warp_n * 64 + j * 16) * SROW + kk * 16, SROW);
#pragma unroll
            for (int i = 0; i < 4; i++)
#pragma unroll
                for (int j = 0; j < 4; j++)
                    wmma::mma_sync(acc[i][j], a[i], b[j], acc[i][j]);
        }
        __syncthreads();
        if (t + NSTAGE < ntiles) load_stage(s, t + NSTAGE);
        CP_COMMIT();
        s = (s == NSTAGE - 1) ? 0 : s + 1;
    }
    CP_WAIT(0);
    __syncthreads();

    // ---- epilogue: two 128-col halves via SMEM staging (128 x 132 floats) ----
    float* stg = (float*)smem;
#pragma unroll
    for (int nh = 0; nh < 2; nh++) {
        if ((warp_n >> 1) == nh) {
#pragma unroll
            for (int i = 0; i < 4; i++)
#pragma unroll
                for (int j = 0; j < 4; j++) {
                    int r0 = warp_m * 64 + i * 16;
                    int c0 = (warp_n & 1) * 64 + j * 16;
                    wmma::store_matrix_sync(stg + r0 * 132 + c0, acc[i][j], 132,
                                            wmma::mem_row_major);
                }
        }
        __syncthreads();
#pragma unroll 4
        for (int it = 0; it < 64; it++) {
            int idx = tid + it * 256;
            int r = idx >> 7, c = idx & 127;
            int gm = bm + r, gn = bn + nh * 128 + c;
            if (gn < N) {
                float tv = stg[r * 132 + c] + (bias ? bias[gn] : 0.f);
                long long ci = (long long)gm * ldc + gn;
                float outv;
                if (epi == 0) {
                    outv = tv;
                } else if (epi == 1) {             // qkv: elu+1 on q,k cols
                    if (gn < 2 * D_MODEL) tv = (tv > 0.f) ? tv + 1.f : expf(tv);
                    outv = tv;
                } else if (epi == 2) {             // attn: residual + normalize
                    outv = e2[ci] + tv / (e1[gm] + ATTN_EPS_F);
                } else if (epi == 3) {             // silu
                    outv = tv / (1.f + expf(-tv));
                } else {                           // 4: C *= tv (gate*up)
                    outv = C[ci] * tv;
                }
                if (C) C[ci] = outv;
                if (Ch && gn < colLim)
                    Ch[(long long)gm * ldch + gn] = __float2half(outv);
            }
        }
        __syncthreads();
    }
}

// ===================== transposes ===========================================
__global__ void __launch_bounds__(256) transpose_f2h_kernel(
    const float* __restrict__ in, fp16* __restrict__ oh,
    int R, int Ccols, int ldi, int ldo, long long sIn, long long sOut)
{
    __shared__ float tile[32][33];
    int bz = blockIdx.z;
    in += sIn * bz;  oh += sOut * bz;
    int r0 = blockIdx.y * 32, c0 = blockIdx.x * 32;
    int tx = threadIdx.x & 31, ty = threadIdx.x >> 5;
#pragma unroll
    for (int i = 0; i < 32; i += 8) {
        int r = r0 + ty + i, c = c0 + tx;
        tile[ty + i][tx] = (r < R && c < Ccols) ? in[(long long)r * ldi + c] : 0.f;
    }
    __syncthreads();
#pragma unroll
    for (int i = 0; i < 32; i += 8) {
        int r = c0 + ty + i, c = r0 + tx;
        if (r < Ccols && c < R)
            oh[(long long)r * ldo + c] = __float2half(tile[tx][ty + i]);
    }
}
__global__ void __launch_bounds__(256) transpose_h2h_kernel(
    const fp16* __restrict__ in, fp16* __restrict__ oh,
    int R, int Ccols, int ldi, int ldo, long long sIn, long long sOut)
{
    __shared__ fp16 tile[32][34];
    int bz = blockIdx.z;
    in += sIn * bz;  oh += sOut * bz;
    int r0 = blockIdx.y * 32, c0 = blockIdx.x * 32;
    int tx = threadIdx.x & 31, ty = threadIdx.x >> 5;
#pragma unroll
    for (int i = 0; i < 32; i += 8) {
        int r = r0 + ty + i, c = c0 + tx;
        tile[ty + i][tx] = (r < R && c < Ccols) ? in[(long long)r * ldi + c] : __float2half(0.f);
    }
    __syncthreads();
#pragma unroll
    for (int i = 0; i < 32; i += 8) {
        int r = c0 + ty + i, c = r0 + tx;
        if (r < Ccols && c < R)
            oh[(long long)r * ldo + c] = tile[tx][ty + i];
    }
}

// ===================== convert (x -> fp16) ==================================
__global__ void conv_kernel(const float* __restrict__ in, fp16* __restrict__ oh, int n)
{
    int i = blockIdx.x * 256 + threadIdx.x;
    if (i < n) oh[i] = __float2half(in[i]);
}

// ===================== ksum / den / layernorm ===============================
__global__ void ksum_part_kernel() {
    int d  = blockIdx.x * 256 + threadIdx.x;
    int b  = blockIdx.y;
    int sc = blockIdx.z;
    const fp16* kp = g_qkvh + (size_t)b * SEQ * D3 + D_MODEL;
    int s0 = sc * (SEQ / 8);
    float s = 0.f;
    for (int i = 0; i < SEQ / 8; i++)
        s += __half2float(kp[(size_t)(s0 + i) * D3 + d]);
    g_kspart[(sc * BATCH + b) * D_MODEL + d] = s;
}
__global__ void ksum_reduce_kernel() {
    int i = blockIdx.x * 256 + threadIdx.x;
    if (i < BATCH * D_MODEL) {
        float s = 0.f;
        for (int c = 0; c < 8; c++) s += g_kspart[c * BATCH * D_MODEL + i];
        g_ksum[i] = s;
    }
}
__global__ void den_kernel() {
    int m = blockIdx.x * 8 + (threadIdx.x >> 5);
    int lane = threadIdx.x & 31;
    const fp16* q  = g_qkvh + (size_t)m * D3;      // qp (elu+1 applied)
    const float* ks = g_ksum + (m / SEQ) * D_MODEL;
    float s = 0.f;
    for (int d = lane; d < D_MODEL; d += 32) s += __half2float(q[d]) * ks[d];
#pragma unroll
    for (int o = 16; o > 0; o >>= 1) s += __shfl_xor_sync(0xffffffffu, s, o);
    if (lane == 0) g_den[m] = s;
}
__global__ void ln_kernel(const float* __restrict__ in1, const float* __restrict__ in2,
                          const float* __restrict__ gamma, const float* __restrict__ beta,
                          float* __restrict__ out, fp16* __restrict__ oh)
{
    int row = blockIdx.x;
    int t = threadIdx.x;
    long long base = (long long)row * D_MODEL;
    float vals[4];
    float s = 0.f;
#pragma unroll
    for (int i = 0; i < 4; i++) {
        int c = t + i * 256;
        float v = in1[base + c];
        if (in2) v += in2[base + c];
        vals[i] = v; s += v;
    }
    __shared__ float red[256];
    red[t] = s; __syncthreads();
    for (int o = 128; o > 0; o >>= 1) { if (t < o) red[t] += red[t + o]; __syncthreads(); }
    float mu = red[0] * (1.f / D_MODEL);
    __syncthreads();
    float vs = 0.f;
#pragma unroll
    for (int i = 0; i < 4; i++) { float d = vals[i] - mu; vs += d * d; }
    red[t] = vs; __syncthreads();
    for (int o = 128; o > 0; o >>= 1) { if (t < o) red[t] += red[t + o]; __syncthreads(); }
    float inv = rsqrtf(red[0] * (1.f / D_MODEL) + LN_EPS_F);
#pragma unroll
    for (int i = 0; i < 4; i++) {
        int c = t + i * 256;
        float v = (vals[i] - mu) * inv * gamma[c] + beta[c];
        out[base + c] = v;
        if (oh) oh[base + c] = __float2half(v);
    }
}

// ===================== launch ===============================================
extern "C" void kernel_launch(void* const* d_in, const int* in_sizes, int n_in,
                              void* d_out, int out_size)
{
    const float* x    = (const float*)d_in[0];
    const float* Wqkv = (const float*)d_in[1];
    const float* bqkv = (const float*)d_in[2];
    const float* Wg   = (const float*)d_in[3];
    const float* bg   = (const float*)d_in[4];
    const float* Wu   = (const float*)d_in[5];
    const float* bu   = (const float*)d_in[6];
    const float* Wd   = (const float*)d_in[7];
    const float* bd   = (const float*)d_in[8];
    const float* g1   = (const float*)d_in[9];
    const float* b1   = (const float*)d_in[10];
    const float* g2   = (const float*)d_in[11];
    const float* b2   = (const float*)d_in[12];
    float* out = (float*)d_out;

    float *den, *yb, *x1, *h, *ffn;
    fp16 *qkvh,*xh,*WqkvT,*WgT,*WuT,*WdT,*kpT,*vT,*kvh,*x1h,*hh;
    cudaGetSymbolAddress((void**)&qkvh, g_qkvh);
    cudaGetSymbolAddress((void**)&den,  g_den);
    cudaGetSymbolAddress((void**)&yb,   g_y);
    cudaGetSymbolAddress((void**)&x1,   g_x1);
    cudaGetSymbolAddress((void**)&h,    g_h);
    cudaGetSymbolAddress((void**)&ffn,  g_ffn);
    cudaGetSymbolAddress((void**)&xh,   g_xh);
    cudaGetSymbolAddress((void**)&WqkvT,g_WqkvT);
    cudaGetSymbolAddress((void**)&WgT,  g_WgT);
    cudaGetSymbolAddress((void**)&WuT,  g_WuT);
    cudaGetSymbolAddress((void**)&WdT,  g_WdT);
    cudaGetSymbolAddress((void**)&kpT,  g_kpT);
    cudaGetSymbolAddress((void**)&vT,   g_vT);
    cudaGetSymbolAddress((void**)&kvh,  g_kvh);
    cudaGetSymbolAddress((void**)&x1h,  g_x1h);
    cudaGetSymbolAddress((void**)&hh,   g_hh);

    cudaFuncSetAttribute(mma_gemm_kernel,
                         cudaFuncAttributeMaxDynamicSharedMemorySize, SMEM_SZ);

    dim3 blk(256);
    const long long SD3  = (long long)SEQ * D3;
    const long long SDM  = (long long)SEQ * D_MODEL;
    const long long DD   = (long long)D_MODEL * D_MODEL;
    const long long DS   = (long long)D_MODEL * SEQ;

    // ---- converts & weight transposes ----
    conv_kernel<<<(MTOT * D_MODEL) / 256, blk>>>(x, xh, MTOT * D_MODEL);
    transpose_f2h_kernel<<<dim3(D3/32, D_MODEL/32, 1), blk>>>(
        Wqkv, WqkvT, D_MODEL, D3, D3, D_MODEL, 0, 0);
    transpose_f2h_kernel<<<dim3((HFF+31)/32, D_MODEL/32, 1), blk>>>(
        Wg, WgT, D_MODEL, HFF, HFF, D_MODEL, 0, 0);
    transpose_f2h_kernel<<<dim3((HFF+31)/32, D_MODEL/32, 1), blk>>>(
        Wu, WuT, D_MODEL, HFF, HFF, D_MODEL, 0, 0);
    transpose_f2h_kernel<<<dim3(D_MODEL/32, (HFF+31)/32, 1), blk>>>(
        Wd, WdT, HFF, D_MODEL, D_MODEL, HFFP, 0, 0);

    // ---- 1) qkvh = fp16(x @ Wqkv + bqkv), elu+1 on q,k cols ----
    mma_gemm_kernel<<<dim3(D3/BN, MTOT/BM, 1), blk, SMEM_SZ>>>(
        xh, WqkvT, bqkv, nullptr, qkvh,
        MTOT, D3, D_MODEL, D_MODEL, D_MODEL, D3, D3,
        0, 0, 0, 0, 1, D3, nullptr, nullptr, 0);

    // ---- kp^T, v^T fp16 (per batch) ----
    transpose_h2h_kernel<<<dim3(D_MODEL/32, SEQ/32, BATCH), blk>>>(
        qkvh + D_MODEL, kpT, SEQ, D_MODEL, D3, SEQ, SD3, DS);
    transpose_h2h_kernel<<<dim3(D_MODEL/32, SEQ/32, BATCH), blk>>>(
        qkvh + 2*D_MODEL, vT, SEQ, D_MODEL, D3, SEQ, SD3, DS);

    // ---- ksum, den ----
    ksum_part_kernel<<<dim3(4, BATCH, 8), blk>>>();
    ksum_reduce_kernel<<<16, blk>>>();
    den_kernel<<<MTOT/8, blk>>>();

    // ---- 2) kvh[e][d] = fp16(sum_s v[s,e] kp[s,d]) ----
    mma_gemm_kernel<<<dim3(D_MODEL/BN, D_MODEL/BM, BATCH), blk, SMEM_SZ>>>(
        vT, kpT, nullptr, nullptr, kvh,
        D_MODEL, D_MODEL, SEQ, SEQ, SEQ, D_MODEL, D_MODEL,
        DS, DS, DD, DD, 0, D_MODEL, nullptr, nullptr, 0);

    // ---- 3) y = x + (qp @ kv) / (den + eps)   (A = qkvh cols 0..1023) ----
    mma_gemm_kernel<<<dim3(D_MODEL/BN, SEQ/BM, BATCH), blk, SMEM_SZ>>>(
        qkvh, kvh, nullptr, yb, nullptr,
        SEQ, D_MODEL, D_MODEL, D3, D_MODEL, D_MODEL, D_MODEL,
        SD3, DD, SDM, 0, 2, 0, den, x, (long long)SEQ);

    // ---- 4) x1 = LN(y); fp16 fused ----
    ln_kernel<<<MTOT, blk>>>(yb, nullptr, g1, b1, x1, x1h);

    // ---- 5) h = silu(x1 @ Wg + bg) ----
    mma_gemm_kernel<<<dim3((HFF+BN-1)/BN, MTOT/BM, 1), blk, SMEM_SZ>>>(
        x1h, WgT, bg, h, nullptr,
        MTOT, HFF, D_MODEL, D_MODEL, D_MODEL, HFF, HFF,
        0, 0, 0, 0, 3, 0, nullptr, nullptr, 0);

    // ---- 6) h *= (x1 @ Wu + bu); fp16 fused out (padded ld) ----
    mma_gemm_kernel<<<dim3((HFF+BN-1)/BN, MTOT/BM, 1), blk, SMEM_SZ>>>(
        x1h, WuT, bu, h, hh,
        MTOT, HFF, D_MODEL, D_MODEL, D_MODEL, HFF, HFFP,
        0, 0, 0, 0, 4, HFF, nullptr, nullptr, 0);

    // ---- 7) ffn = h @ Wd + bd (padded strides, 16B cp.async alignment) ----
    mma_gemm_kernel<<<dim3(D_MODEL/BN, MTOT/BM, 1), blk, SMEM_SZ>>>(
        hh, WdT, bd, ffn, nullptr,
        MTOT, D_MODEL, HFF, HFFP, HFFP, D_MODEL, D_MODEL,
        0, 0, 0, 0, 0, 0, nullptr, nullptr, 0);

    // ---- 8) out = LN(x1 + ffn) ----
    ln_kernel<<<MTOT, blk>>>(x1, ffn, g2, b2, out, nullptr);
}

// round 7
// speedup vs baseline: 4.0665x; 1.0260x over previous
#include <cuda_runtime.h>
#include <cuda_fp16.h>
#include <cstdint>
#include <math.h>

#define D_MODEL 1024
#define D3      3072
#define HFF     2730
#define HFFP    2736                 // HFF padded to 8-element (16B) multiple
#define BATCH   4
#define SEQ     4096
#define MTOT    (BATCH*SEQ)          // 16384

#define LN_EPS_F   1e-5f
#define ATTN_EPS_F 1e-6f

typedef __half fp16;

// ===================== scratch ==============================================
__device__ fp16  g_qkvh[(size_t)MTOT * D3];         // fp16 qkv (elu+1 on q,k)
__device__ fp16  g_xh  [(size_t)MTOT * D_MODEL];
__device__ fp16  g_WqkvT[(size_t)D3 * D_MODEL];
__device__ fp16  g_WgT [(size_t)HFF * D_MODEL];
__device__ fp16  g_WuT [(size_t)HFF * D_MODEL];
__device__ fp16  g_WdT [(size_t)D_MODEL * HFFP];    // padded ld
__device__ fp16  g_kpT [(size_t)BATCH * D_MODEL * SEQ];
__device__ fp16  g_vT  [(size_t)BATCH * D_MODEL * SEQ];
__device__ fp16  g_kvh [(size_t)BATCH * D_MODEL * D_MODEL];
__device__ float g_kspart[8 * BATCH * D_MODEL];
__device__ float g_ksum[BATCH * D_MODEL];
__device__ float g_den[MTOT];
__device__ float g_y [(size_t)MTOT * D_MODEL];
__device__ float g_x1[(size_t)MTOT * D_MODEL];
__device__ fp16  g_x1h[(size_t)MTOT * D_MODEL];
__device__ float g_h [(size_t)MTOT * HFF];
__device__ fp16  g_hh[(size_t)MTOT * HFFP];         // padded ld
__device__ float g_ffn[(size_t)MTOT * D_MODEL];

// ===================== helpers ==============================================
__device__ __forceinline__ uint32_t smem_u32(const void* p) {
    uint32_t a;
    asm("{ .reg .u64 t; cvta.to.shared.u64 t, %1; cvt.u32.u64 %0, t; }" : "=r"(a) : "l"(p));
    return a;
}
__device__ __forceinline__ void cp16(uint32_t dst, const void* src, int bytes) {
    asm volatile("cp.async.cg.shared.global [%0], [%1], 16, %2;\n"
        :: "r"(dst), "l"(src), "r"(bytes));
}
#define CP_COMMIT() asm volatile("cp.async.commit_group;\n" ::: "memory")
#define CP_WAIT(n)  asm volatile("cp.async.wait_group %0;\n" :: "n"(n) : "memory")

__device__ __forceinline__ void ldmx4(uint32_t& r0, uint32_t& r1, uint32_t& r2,
                                      uint32_t& r3, uint32_t addr) {
    asm volatile("ldmatrix.sync.aligned.m8n8.x4.shared.b16 {%0,%1,%2,%3}, [%4];"
        : "=r"(r0), "=r"(r1), "=r"(r2), "=r"(r3) : "r"(addr));
}
__device__ __forceinline__ void mma16816(float* c, const uint32_t* a, uint32_t b0, uint32_t b1) {
    asm volatile(
        "mma.sync.aligned.m16n8k16.row.col.f32.f16.f16.f32 "
        "{%0,%1,%2,%3}, {%4,%5,%6,%7}, {%8,%9}, {%0,%1,%2,%3};"
        : "+f"(c[0]), "+f"(c[1]), "+f"(c[2]), "+f"(c[3])
        : "r"(a[0]), "r"(a[1]), "r"(a[2]), "r"(a[3]), "r"(b0), "r"(b1));
}

// ===================== mma.sync fp16 GEMM (fp32 accum) ======================
// C[m,n] = sum_k A[m,k] * Bt[n,k]  (fp16, Bt = B^T [N][K] row-major)
// BM=128, BN=256, BK=32. 8 warps: 2 m-warps x 4 n-warps, 64x64 warp tile.
// Raw ldmatrix + mma.sync.m16n8k16. 3-stage cp.async, single sync per tile.
// lda/ldb MUST be multiples of 8 elements (16B cp.async alignment).
#define BM 128
#define BN 256
#define BK 32
#define SROW 40                       // halves per smem row (32 + 8 pad)
#define A_HALVES (128 * SROW)         // 5120
#define B_HALVES (256 * SROW)         // 10240
#define STAGE_B ((A_HALVES + B_HALVES) * 2)   // 30720 bytes
#define NSTAGE 3
#define SMEM_SZ (NSTAGE * STAGE_B)    // 92160 (epilogue staging 67584 fits)

__global__ void __launch_bounds__(256, 1) mma_gemm_kernel(
    const fp16* __restrict__ Ah, const fp16* __restrict__ Bh,
    const float* __restrict__ bias, float* __restrict__ C,
    fp16* __restrict__ Ch,
    int M, int N, int K, int lda, int ldb, int ldc, int ldch,
    long long sA, long long sB, long long sC, long long sCh,
    int epi, int colLim,
    const float* __restrict__ e1, const float* __restrict__ e2, long long sE1)
{
    extern __shared__ __align__(16) char smem[];
    const uint32_t sbase = smem_u32(smem);
    const int tid = threadIdx.x;
    const int wid = tid >> 5;
    const int lane = tid & 31;
    const int warp_m = wid & 1;        // 2 m-warps of 64 rows
    const int warp_n = wid >> 1;       // 4 n-warps of 64 cols
    const int bz = blockIdx.z;
    Ah += sA * bz;  Bh += sB * bz;
    if (C)  C  += sC * bz;
    if (Ch) Ch += sCh * bz;
    if (e1) e1 += sE1 * bz;
    if (e2) e2 += sC * bz;
    const int bm = blockIdx.y * BM;
    const int bn = blockIdx.x * BN;

    float acc[4][8][4];
#pragma unroll
    for (int i = 0; i < 4; i++)
#pragma unroll
        for (int j = 0; j < 8; j++)
#pragma unroll
            for (int v = 0; v < 4; v++) acc[i][j][v] = 0.f;

    // per-lane ldmatrix byte offsets within a stage
    // A tile (mi, kk): row = warp_m*64 + mi*16 + (lane&15); col = (lane>>4)*8 + kk*16
    const uint32_t a_base =
        ((uint32_t)(warp_m * 64 + (lane & 15)) * SROW + ((lane >> 4) * 8)) * 2;
    // B pair p (tiles 2p,2p+1): row = warp_n*64 + p*16 + ((lane>>4)&1)*8 + (lane&7)
    //                           col = ((lane>>3)&1)*8 + kk*16
    const uint32_t b_base = (uint32_t)A_HALVES * 2 +
        (((uint32_t)(warp_n * 64 + ((lane >> 4) & 1) * 8 + (lane & 7))) * SROW +
         (((lane >> 3) & 1) * 8)) * 2;

    const int ntiles = (K + BK - 1) / BK;

    auto load_stage = [&](int s, int t) {
        uint32_t sb = sbase + s * STAGE_B;
        int k0 = t * BK;
#pragma unroll
        for (int j = 0; j < 2; j++) {
            int idx = tid + j * 256;
            int r = idx >> 2, ch = idx & 3;
            int kc = k0 + ch * 8;
            int ab = 2 * (K - kc); ab = ab < 0 ? 0 : (ab > 16 ? 16 : ab);
            cp16(sb + (r * SROW + ch * 8) * 2, Ah + (long long)(bm + r) * lda + kc, ab);
        }
#pragma unroll
        for (int j = 0; j < 4; j++) {
            int idx = tid + j * 256;
            int r = idx >> 2, ch = idx & 3;
            int kc = k0 + ch * 8;
            int ab = 2 * (K - kc); ab = ab < 0 ? 0 : (ab > 16 ? 16 : ab);
            int gn = bn + r;
            int bb = (gn < N) ? ab : 0;
            cp16(sb + A_HALVES * 2 + (r * SROW + ch * 8) * 2,
                 Bh + (long long)(gn < N ? gn : 0) * ldb + kc, bb);
        }
    };

    load_stage(0, 0); CP_COMMIT();
    if (ntiles > 1) load_stage(1, 1);
    CP_COMMIT();

    for (int t = 0; t < ntiles; t++) {
        CP_WAIT(1);
        __syncthreads();
        int ls = t + NSTAGE - 1;
        if (ls < ntiles) load_stage(ls % NSTAGE, ls);
        CP_COMMIT();

        uint32_t sb = sbase + (t % NSTAGE) * STAGE_B;
#pragma unroll
        for (int kk = 0; kk < 2; kk++) {
            uint32_t a[4][4], b[4][4];
#pragma unroll
            for (int mi = 0; mi < 4; mi++)
                ldmx4(a[mi][0], a[mi][1], a[mi][2], a[mi][3],
                      sb + a_base + (uint32_t)(mi * 16 * SROW * 2) + kk * 32);
#pragma unroll
            for (int p = 0; p < 4; p++)
                ldmx4(b[p][0], b[p][1], b[p][2], b[p][3],
                      sb + b_base + (uint32_t)(p * 16 * SROW * 2) + kk * 32);
#pragma unroll
            for (int mi = 0; mi < 4; mi++)
#pragma unroll
                for (int nj = 0; nj < 8; nj++)
                    mma16816(acc[mi][nj], a[mi], b[nj >> 1][(nj & 1) * 2],
                             b[nj >> 1][(nj & 1) * 2 + 1]);
        }
    }
    CP_WAIT(0);
    __syncthreads();

    // ---- epilogue: two 128-col halves via SMEM staging (128 x 132 floats) ----
    float* stg = (float*)smem;
    const int gID = lane >> 2, t4 = lane & 3;
#pragma unroll
    for (int nh = 0; nh < 2; nh++) {
        if ((warp_n >> 1) == nh) {
#pragma unroll
            for (int mi = 0; mi < 4; mi++)
#pragma unroll
                for (int nj = 0; nj < 8; nj++) {
                    int r0 = warp_m * 64 + mi * 16 + gID;
                    int c0 = (warp_n & 1) * 64 + nj * 8 + 2 * t4;
                    stg[r0 * 132 + c0]           = acc[mi][nj][0];
                    stg[r0 * 132 + c0 + 1]       = acc[mi][nj][1];
                    stg[(r0 + 8) * 132 + c0]     = acc[mi][nj][2];
                    stg[(r0 + 8) * 132 + c0 + 1] = acc[mi][nj][3];
                }
        }
        __syncthreads();
#pragma unroll 4
        for (int it = 0; it < 64; it++) {
            int idx = tid + it * 256;
            int r = idx >> 7, c = idx & 127;
            int gm = bm + r, gn = bn + nh * 128 + c;
            if (gn < N) {
                float tv = stg[r * 132 + c] + (bias ? bias[gn] : 0.f);
                long long ci = (long long)gm * ldc + gn;
                float outv;
                if (epi == 0) {
                    outv = tv;
                } else if (epi == 1) {             // qkv: elu+1 on q,k cols
                    if (gn < 2 * D_MODEL) tv = (tv > 0.f) ? tv + 1.f : expf(tv);
                    outv = tv;
                } else if (epi == 2) {             // attn: residual + normalize
                    outv = e2[ci] + tv / (e1[gm] + ATTN_EPS_F);
                } else if (epi == 3) {             // silu
                    outv = tv / (1.f + expf(-tv));
                } else {                           // 4: C *= tv (gate*up)
                    outv = C[ci] * tv;
                }
                if (C) C[ci] = outv;
                if (Ch && gn < colLim)
                    Ch[(long long)gm * ldch + gn] = __float2half(outv);
            }
        }
        __syncthreads();
    }
}

// ===================== transposes ===========================================
__global__ void __launch_bounds__(256) transpose_f2h_kernel(
    const float* __restrict__ in, fp16* __restrict__ oh,
    int R, int Ccols, int ldi, int ldo, long long sIn, long long sOut)
{
    __shared__ float tile[32][33];
    int bz = blockIdx.z;
    in += sIn * bz;  oh += sOut * bz;
    int r0 = blockIdx.y * 32, c0 = blockIdx.x * 32;
    int tx = threadIdx.x & 31, ty = threadIdx.x >> 5;
#pragma unroll
    for (int i = 0; i < 32; i += 8) {
        int r = r0 + ty + i, c = c0 + tx;
        tile[ty + i][tx] = (r < R && c < Ccols) ? in[(long long)r * ldi + c] : 0.f;
    }
    __syncthreads();
#pragma unroll
    for (int i = 0; i < 32; i += 8) {
        int r = c0 + ty + i, c = r0 + tx;
        if (r < Ccols && c < R)
            oh[(long long)r * ldo + c] = __float2half(tile[tx][ty + i]);
    }
}
__global__ void __launch_bounds__(256) transpose_h2h_kernel(
    const fp16* __restrict__ in, fp16* __restrict__ oh,
    int R, int Ccols, int ldi, int ldo, long long sIn, long long sOut)
{
    __shared__ fp16 tile[32][34];
    int bz = blockIdx.z;
    in += sIn * bz;  oh += sOut * bz;
    int r0 = blockIdx.y * 32, c0 = blockIdx.x * 32;
    int tx = threadIdx.x & 31, ty = threadIdx.x >> 5;
#pragma unroll
    for (int i = 0; i < 32; i += 8) {
        int r = r0 + ty + i, c = c0 + tx;
        tile[ty + i][tx] = (r < R && c < Ccols) ? in[(long long)r * ldi + c] : __float2half(0.f);
    }
    __syncthreads();
#pragma unroll
    for (int i = 0; i < 32; i += 8) {
        int r = c0 + ty + i, c = r0 + tx;
        if (r < Ccols && c < R)
            oh[(long long)r * ldo + c] = tile[tx][ty + i];
    }
}

// ===================== convert (x -> fp16) ==================================
__global__ void conv_kernel(const float* __restrict__ in, fp16* __restrict__ oh, int n)
{
    int i = blockIdx.x * 256 + threadIdx.x;
    if (i < n) oh[i] = __float2half(in[i]);
}

// ===================== ksum / den / layernorm ===============================
__global__ void ksum_part_kernel() {
    int d  = blockIdx.x * 256 + threadIdx.x;
    int b  = blockIdx.y;
    int sc = blockIdx.z;
    const fp16* kp = g_qkvh + (size_t)b * SEQ * D3 + D_MODEL;
    int s0 = sc * (SEQ / 8);
    float s = 0.f;
    for (int i = 0; i < SEQ / 8; i++)
        s += __half2float(kp[(size_t)(s0 + i) * D3 + d]);
    g_kspart[(sc * BATCH + b) * D_MODEL + d] = s;
}
__global__ void ksum_reduce_kernel() {
    int i = blockIdx.x * 256 + threadIdx.x;
    if (i < BATCH * D_MODEL) {
        float s = 0.f;
        for (int c = 0; c < 8; c++) s += g_kspart[c * BATCH * D_MODEL + i];
        g_ksum[i] = s;
    }
}
__global__ void den_kernel() {
    int m = blockIdx.x * 8 + (threadIdx.x >> 5);
    int lane = threadIdx.x & 31;
    const fp16* q  = g_qkvh + (size_t)m * D3;      // qp (elu+1 applied)
    const float* ks = g_ksum + (m / SEQ) * D_MODEL;
    float s = 0.f;
    for (int d = lane; d < D_MODEL; d += 32) s += __half2float(q[d]) * ks[d];
#pragma unroll
    for (int o = 16; o > 0; o >>= 1) s += __shfl_xor_sync(0xffffffffu, s, o);
    if (lane == 0) g_den[m] = s;
}
__global__ void ln_kernel(const float* __restrict__ in1, const float* __restrict__ in2,
                          const float* __restrict__ gamma, const float* __restrict__ beta,
                          float* __restrict__ out, fp16* __restrict__ oh)
{
    int row = blockIdx.x;
    int t = threadIdx.x;
    long long base = (long long)row * D_MODEL;
    float vals[4];
    float s = 0.f;
#pragma unroll
    for (int i = 0; i < 4; i++) {
        int c = t + i * 256;
        float v = in1[base + c];
        if (in2) v += in2[base + c];
        vals[i] = v; s += v;
    }
    __shared__ float red[256];
    red[t] = s; __syncthreads();
    for (int o = 128; o > 0; o >>= 1) { if (t < o) red[t] += red[t + o]; __syncthreads(); }
    float mu = red[0] * (1.f / D_MODEL);
    __syncthreads();
    float vs = 0.f;
#pragma unroll
    for (int i = 0; i < 4; i++) { float d = vals[i] - mu; vs += d * d; }
    red[t] = vs; __syncthreads();
    for (int o = 128; o > 0; o >>= 1) { if (t < o) red[t] += red[t + o]; __syncthreads(); }
    float inv = rsqrtf(red[0] * (1.f / D_MODEL) + LN_EPS_F);
#pragma unroll
    for (int i = 0; i < 4; i++) {
        int c = t + i * 256;
        float v = (vals[i] - mu) * inv * gamma[c] + beta[c];
        out[base + c] = v;
        if (oh) oh[base + c] = __float2half(v);
    }
}

// ===================== launch ===============================================
extern "C" void kernel_launch(void* const* d_in, const int* in_sizes, int n_in,
                              void* d_out, int out_size)
{
    const float* x    = (const float*)d_in[0];
    const float* Wqkv = (const float*)d_in[1];
    const float* bqkv = (const float*)d_in[2];
    const float* Wg   = (const float*)d_in[3];
    const float* bg   = (const float*)d_in[4];
    const float* Wu   = (const float*)d_in[5];
    const float* bu   = (const float*)d_in[6];
    const float* Wd   = (const float*)d_in[7];
    const float* bd   = (const float*)d_in[8];
    const float* g1   = (const float*)d_in[9];
    const float* b1   = (const float*)d_in[10];
    const float* g2   = (const float*)d_in[11];
    const float* b2   = (const float*)d_in[12];
    float* out = (float*)d_out;

    float *den, *yb, *x1, *h, *ffn;
    fp16 *qkvh,*xh,*WqkvT,*WgT,*WuT,*WdT,*kpT,*vT,*kvh,*x1h,*hh;
    cudaGetSymbolAddress((void**)&qkvh, g_qkvh);
    cudaGetSymbolAddress((void**)&den,  g_den);
    cudaGetSymbolAddress((void**)&yb,   g_y);
    cudaGetSymbolAddress((void**)&x1,   g_x1);
    cudaGetSymbolAddress((void**)&h,    g_h);
    cudaGetSymbolAddress((void**)&ffn,  g_ffn);
    cudaGetSymbolAddress((void**)&xh,   g_xh);
    cudaGetSymbolAddress((void**)&WqkvT,g_WqkvT);
    cudaGetSymbolAddress((void**)&WgT,  g_WgT);
    cudaGetSymbolAddress((void**)&WuT,  g_WuT);
    cudaGetSymbolAddress((void**)&WdT,  g_WdT);
    cudaGetSymbolAddress((void**)&kpT,  g_kpT);
    cudaGetSymbolAddress((void**)&vT,   g_vT);
    cudaGetSymbolAddress((void**)&kvh,  g_kvh);
    cudaGetSymbolAddress((void**)&x1h,  g_x1h);
    cudaGetSymbolAddress((void**)&hh,   g_hh);

    cudaFuncSetAttribute(mma_gemm_kernel,
                         cudaFuncAttributeMaxDynamicSharedMemorySize, SMEM_SZ);

    dim3 blk(256);
    const long long SD3  = (long long)SEQ * D3;
    const long long SDM  = (long long)SEQ * D_MODEL;
    const long long DD   = (long long)D_MODEL * D_MODEL;
    const long long DS   = (long long)D_MODEL * SEQ;

    // ---- converts & weight transposes ----
    conv_kernel<<<(MTOT * D_MODEL) / 256, blk>>>(x, xh, MTOT * D_MODEL);
    transpose_f2h_kernel<<<dim3(D3/32, D_MODEL/32, 1), blk>>>(
        Wqkv, WqkvT, D_MODEL, D3, D3, D_MODEL, 0, 0);
    transpose_f2h_kernel<<<dim3((HFF+31)/32, D_MODEL/32, 1), blk>>>(
        Wg, WgT, D_MODEL, HFF, HFF, D_MODEL, 0, 0);
    transpose_f2h_kernel<<<dim3((HFF+31)/32, D_MODEL/32, 1), blk>>>(
        Wu, WuT, D_MODEL, HFF, HFF, D_MODEL, 0, 0);
    transpose_f2h_kernel<<<dim3(D_MODEL/32, (HFF+31)/32, 1), blk>>>(
        Wd, WdT, HFF, D_MODEL, D_MODEL, HFFP, 0, 0);

    // ---- 1) qkvh = fp16(x @ Wqkv + bqkv), elu+1 on q,k cols ----
    mma_gemm_kernel<<<dim3(D3/BN, MTOT/BM, 1), blk, SMEM_SZ>>>(
        xh, WqkvT, bqkv, nullptr, qkvh,
        MTOT, D3, D_MODEL, D_MODEL, D_MODEL, D3, D3,
        0, 0, 0, 0, 1, D3, nullptr, nullptr, 0);

    // ---- kp^T, v^T fp16 (per batch) ----
    transpose_h2h_kernel<<<dim3(D_MODEL/32, SEQ/32, BATCH), blk>>>(
        qkvh + D_MODEL, kpT, SEQ, D_MODEL, D3, SEQ, SD3, DS);
    transpose_h2h_kernel<<<dim3(D_MODEL/32, SEQ/32, BATCH), blk>>>(
        qkvh + 2*D_MODEL, vT, SEQ, D_MODEL, D3, SEQ, SD3, DS);

    // ---- ksum, den ----
    ksum_part_kernel<<<dim3(4, BATCH, 8), blk>>>();
    ksum_reduce_kernel<<<16, blk>>>();
    den_kernel<<<MTOT/8, blk>>>();

    // ---- 2) kvh[e][d] = fp16(sum_s v[s,e] kp[s,d]) ----
    mma_gemm_kernel<<<dim3(D_MODEL/BN, D_MODEL/BM, BATCH), blk, SMEM_SZ>>>(
        vT, kpT, nullptr, nullptr, kvh,
        D_MODEL, D_MODEL, SEQ, SEQ, SEQ, D_MODEL, D_MODEL,
        DS, DS, DD, DD, 0, D_MODEL, nullptr, nullptr, 0);

    // ---- 3) y = x + (qp @ kv) / (den + eps)   (A = qkvh cols 0..1023) ----
    mma_gemm_kernel<<<dim3(D_MODEL/BN, SEQ/BM, BATCH), blk, SMEM_SZ>>>(
        qkvh, kvh, nullptr, yb, nullptr,
        SEQ, D_MODEL, D_MODEL, D3, D_MODEL, D_MODEL, D_MODEL,
        SD3, DD, SDM, 0, 2, 0, den, x, (long long)SEQ);

    // ---- 4) x1 = LN(y); fp16 fused ----
    ln_kernel<<<MTOT, blk>>>(yb, nullptr, g1, b1, x1, x1h);

    // ---- 5) h = silu(x1 @ Wg + bg) ----
    mma_gemm_kernel<<<dim3((HFF+BN-1)/BN, MTOT/BM, 1), blk, SMEM_SZ>>>(
        x1h, WgT, bg, h, nullptr,
        MTOT, HFF, D_MODEL, D_MODEL, D_MODEL, HFF, HFF,
        0, 0, 0, 0, 3, 0, nullptr, nullptr, 0);

    // ---- 6) h *= (x1 @ Wu + bu); fp16 fused out (padded ld) ----
    mma_gemm_kernel<<<dim3((HFF+BN-1)/BN, MTOT/BM, 1), blk, SMEM_SZ>>>(
        x1h, WuT, bu, h, hh,
        MTOT, HFF, D_MODEL, D_MODEL, D_MODEL, HFF, HFFP,
        0, 0, 0, 0, 4, HFF, nullptr, nullptr, 0);

    // ---- 7) ffn = h @ Wd + bd (padded strides, 16B cp.async alignment) ----
    mma_gemm_kernel<<<dim3(D_MODEL/BN, MTOT/BM, 1), blk, SMEM_SZ>>>(
        hh, WdT, bd, ffn, nullptr,
        MTOT, D_MODEL, HFF, HFFP, HFFP, D_MODEL, D_MODEL,
        0, 0, 0, 0, 0, 0, nullptr, nullptr, 0);

    // ---- 8) out = LN(x1 + ffn) ----
    ln_kernel<<<MTOT, blk>>>(x1, ffn, g2, b2, out, nullptr);
}

// round 8
// speedup vs baseline: 5.7170x; 1.4059x over previous
#include <cuda_runtime.h>
#include <cuda_fp16.h>
#include <cstdint>
#include <math.h>

#define D_MODEL 1024
#define D3      3072
#define HFF     2730
#define HFFP    2736                 // HFF padded to 8-element (16B) multiple
#define NGU     5472                 // interleaved gate/up N (2*2736)
#define BATCH   4
#define SEQ     4096
#define MTOT    (BATCH*SEQ)          // 16384

#define LN_EPS_F   1e-5f
#define ATTN_EPS_F 1e-6f

typedef __half fp16;

// ===================== scratch ==============================================
__device__ fp16  g_qkvh[(size_t)MTOT * D3];         // only q cols [0,1024) used
__device__ fp16  g_xh  [(size_t)MTOT * D_MODEL];
__device__ fp16  g_WqkvT[(size_t)D3 * D_MODEL];
__device__ fp16  g_WguT[(size_t)NGU * D_MODEL];     // interleaved gate/up rows (8-blocks)
__device__ float g_bgu [5632];                      // interleaved biases (zero padded)
__device__ fp16  g_WdT [(size_t)D_MODEL * HFFP];    // padded ld
__device__ fp16  g_kpT [(size_t)BATCH * D_MODEL * SEQ];
__device__ fp16  g_vT  [(size_t)BATCH * D_MODEL * SEQ];
__device__ fp16  g_kvh [(size_t)BATCH * D_MODEL * D_MODEL];
__device__ float g_ksum[BATCH * D_MODEL];
__device__ float g_den[MTOT];
__device__ float g_y [(size_t)MTOT * D_MODEL];
__device__ float g_x1[(size_t)MTOT * D_MODEL];
__device__ fp16  g_x1h[(size_t)MTOT * D_MODEL];
__device__ fp16  g_hh[(size_t)MTOT * HFFP];         // fused silu(gate)*up, padded ld
__device__ float g_ffn[(size_t)MTOT * D_MODEL];

// ===================== helpers ==============================================
__device__ __forceinline__ uint32_t smem_u32(const void* p) {
    uint32_t a;
    asm("{ .reg .u64 t; cvta.to.shared.u64 t, %1; cvt.u32.u64 %0, t; }" : "=r"(a) : "l"(p));
    return a;
}
__device__ __forceinline__ void cp16(uint32_t dst, const void* src, int bytes) {
    asm volatile("cp.async.cg.shared.global [%0], [%1], 16, %2;\n"
        :: "r"(dst), "l"(src), "r"(bytes));
}
#define CP_COMMIT() asm volatile("cp.async.commit_group;\n" ::: "memory")
#define CP_WAIT(n)  asm volatile("cp.async.wait_group %0;\n" :: "n"(n) : "memory")

__device__ __forceinline__ void ldmx4(uint32_t& r0, uint32_t& r1, uint32_t& r2,
                                      uint32_t& r3, uint32_t addr) {
    asm volatile("ldmatrix.sync.aligned.m8n8.x4.shared.b16 {%0,%1,%2,%3}, [%4];"
        : "=r"(r0), "=r"(r1), "=r"(r2), "=r"(r3) : "r"(addr));
}
__device__ __forceinline__ void mma16816(float* c, const uint32_t* a, uint32_t b0, uint32_t b1) {
    asm volatile(
        "mma.sync.aligned.m16n8k16.row.col.f32.f16.f16.f32 "
        "{%0,%1,%2,%3}, {%4,%5,%6,%7}, {%8,%9}, {%0,%1,%2,%3};"
        : "+f"(c[0]), "+f"(c[1]), "+f"(c[2]), "+f"(c[3])
        : "r"(a[0]), "r"(a[1]), "r"(a[2]), "r"(a[3]), "r"(b0), "r"(b1));
}
__device__ __forceinline__ float silu_f(float g) { return g / (1.f + expf(-g)); }

// ===================== mma.sync fp16 GEMM (fp32 accum) ======================
// C[m,n] = sum_k A[m,k] * Bt[n,k]  (fp16, Bt = B^T [N][K] row-major)
// BM=128, BN=256, BK=32. 8 warps: 2 m-warps x 4 n-warps, 64x64 warp tile.
// epi: 0 plain(+bias); 1 qkv (q->qkvh elu+1, k->KT elu+1 transposed, v->VT);
//      2 residual+attn-div; 5 fused silu(gate)*up (interleaved B) -> Ch only.
#define BM 128
#define BN 256
#define BK 32
#define SROW 40                       // halves per smem row (32 + 8 pad)
#define A_HALVES (128 * SROW)         // 5120
#define B_HALVES (256 * SROW)         // 10240
#define STAGE_B ((A_HALVES + B_HALVES) * 2)   // 30720 bytes
#define NSTAGE 3
#define SMEM_SZ (NSTAGE * STAGE_B)    // 92160 (epilogue staging 68096 fits)
#define SSTG 133                      // staging stride (conflict-free transposed reads)

__global__ void __launch_bounds__(256, 1) mma_gemm_kernel(
    const fp16* __restrict__ Ah, const fp16* __restrict__ Bh,
    const float* __restrict__ bias, float* __restrict__ C,
    fp16* __restrict__ Ch, fp16* __restrict__ KT, fp16* __restrict__ VT,
    int M, int N, int K, int lda, int ldb, int ldc, int ldch,
    long long sA, long long sB, long long sC, long long sCh,
    int epi, int colLim,
    const float* __restrict__ e1, const float* __restrict__ e2, long long sE1)
{
    extern __shared__ __align__(16) char smem[];
    const uint32_t sbase = smem_u32(smem);
    const int tid = threadIdx.x;
    const int wid = tid >> 5;
    const int lane = tid & 31;
    const int warp_m = wid & 1;        // 2 m-warps of 64 rows
    const int warp_n = wid >> 1;       // 4 n-warps of 64 cols
    const int bz = blockIdx.z;
    Ah += sA * bz;  Bh += sB * bz;
    if (C)  C  += sC * bz;
    if (Ch) Ch += sCh * bz;
    if (e1) e1 += sE1 * bz;
    if (e2) e2 += sC * bz;
    const int bm = blockIdx.y * BM;
    const int bn = blockIdx.x * BN;

    float acc[4][8][4];
#pragma unroll
    for (int i = 0; i < 4; i++)
#pragma unroll
        for (int j = 0; j < 8; j++)
#pragma unroll
            for (int v = 0; v < 4; v++) acc[i][j][v] = 0.f;

    const uint32_t a_base =
        ((uint32_t)(warp_m * 64 + (lane & 15)) * SROW + ((lane >> 4) * 8)) * 2;
    const uint32_t b_base = (uint32_t)A_HALVES * 2 +
        (((uint32_t)(warp_n * 64 + ((lane >> 4) & 1) * 8 + (lane & 7))) * SROW +
         (((lane >> 3) & 1) * 8)) * 2;

    const int ntiles = (K + BK - 1) / BK;

    auto load_stage = [&](int s, int t) {
        uint32_t sb = sbase + s * STAGE_B;
        int k0 = t * BK;
#pragma unroll
        for (int j = 0; j < 2; j++) {
            int idx = tid + j * 256;
            int r = idx >> 2, ch = idx & 3;
            int kc = k0 + ch * 8;
            int ab = 2 * (K - kc); ab = ab < 0 ? 0 : (ab > 16 ? 16 : ab);
            cp16(sb + (r * SROW + ch * 8) * 2, Ah + (long long)(bm + r) * lda + kc, ab);
        }
#pragma unroll
        for (int j = 0; j < 4; j++) {
            int idx = tid + j * 256;
            int r = idx >> 2, ch = idx & 3;
            int kc = k0 + ch * 8;
            int ab = 2 * (K - kc); ab = ab < 0 ? 0 : (ab > 16 ? 16 : ab);
            int gn = bn + r;
            int bb = (gn < N) ? ab : 0;
            cp16(sb + A_HALVES * 2 + (r * SROW + ch * 8) * 2,
                 Bh + (long long)(gn < N ? gn : 0) * ldb + kc, bb);
        }
    };

    load_stage(0, 0); CP_COMMIT();
    if (ntiles > 1) load_stage(1, 1);
    CP_COMMIT();

    for (int t = 0; t < ntiles; t++) {
        CP_WAIT(1);
        __syncthreads();
        int ls = t + NSTAGE - 1;
        if (ls < ntiles) load_stage(ls % NSTAGE, ls);
        CP_COMMIT();

        uint32_t sb = sbase + (t % NSTAGE) * STAGE_B;
#pragma unroll
        for (int kk = 0; kk < 2; kk++) {
            uint32_t a[4][4], b[4][4];
#pragma unroll
            for (int mi = 0; mi < 4; mi++)
                ldmx4(a[mi][0], a[mi][1], a[mi][2], a[mi][3],
                      sb + a_base + (uint32_t)(mi * 16 * SROW * 2) + kk * 32);
#pragma unroll
            for (int p = 0; p < 4; p++)
                ldmx4(b[p][0], b[p][1], b[p][2], b[p][3],
                      sb + b_base + (uint32_t)(p * 16 * SROW * 2) + kk * 32);
#pragma unroll
            for (int mi = 0; mi < 4; mi++)
#pragma unroll
                for (int nj = 0; nj < 8; nj++)
                    mma16816(acc[mi][nj], a[mi], b[nj >> 1][(nj & 1) * 2],
                             b[nj >> 1][(nj & 1) * 2 + 1]);
        }
    }
    CP_WAIT(0);
    __syncthreads();

    float* stg = (float*)smem;
    const int gID = lane >> 2, t4 = lane & 3;

    if (epi == 5) {
        // ---- fused silu(gate)*up: nj even = gate, nj odd = up, same h cols ----
#pragma unroll
        for (int p = 0; p < 4; p++) {
            int bc = bn + warp_n * 64 + p * 16 + 2 * t4;
            float bg0 = bias[bc],     bg1 = bias[bc + 1];
            float bu0 = bias[bc + 8], bu1 = bias[bc + 9];
            int hc = warp_n * 32 + p * 8 + 2 * t4;
#pragma unroll
            for (int mi = 0; mi < 4; mi++) {
                int r0 = warp_m * 64 + mi * 16 + gID;
                float o0 = silu_f(acc[mi][2*p][0] + bg0) * (acc[mi][2*p+1][0] + bu0);
                float o1 = silu_f(acc[mi][2*p][1] + bg1) * (acc[mi][2*p+1][1] + bu1);
                float o2 = silu_f(acc[mi][2*p][2] + bg0) * (acc[mi][2*p+1][2] + bu0);
                float o3 = silu_f(acc[mi][2*p][3] + bg1) * (acc[mi][2*p+1][3] + bu1);
                stg[r0 * SSTG + hc]           = o0;
                stg[r0 * SSTG + hc + 1]       = o1;
                stg[(r0 + 8) * SSTG + hc]     = o2;
                stg[(r0 + 8) * SSTG + hc + 1] = o3;
            }
        }
        __syncthreads();
        int hbase = bn >> 1;
#pragma unroll 4
        for (int it = 0; it < 64; it++) {
            int idx = tid + it * 256;
            int r = idx >> 7, c = idx & 127;
            int hcol = hbase + c;
            if (hcol < HFF)
                Ch[(long long)(bm + r) * ldch + hcol] = __float2half(stg[r * SSTG + c]);
        }
        return;
    }

    // ---- generic: two 128-col halves via SMEM staging ----
#pragma unroll
    for (int nh = 0; nh < 2; nh++) {
        if ((warp_n >> 1) == nh) {
#pragma unroll
            for (int mi = 0; mi < 4; mi++)
#pragma unroll
                for (int nj = 0; nj < 8; nj++) {
                    int r0 = warp_m * 64 + mi * 16 + gID;
                    int c0 = (warp_n & 1) * 64 + nj * 8 + 2 * t4;
                    stg[r0 * SSTG + c0]           = acc[mi][nj][0];
                    stg[r0 * SSTG + c0 + 1]       = acc[mi][nj][1];
                    stg[(r0 + 8) * SSTG + c0]     = acc[mi][nj][2];
                    stg[(r0 + 8) * SSTG + c0 + 1] = acc[mi][nj][3];
                }
        }
        __syncthreads();

        if (epi == 1 && (bn + nh * 128) >= D_MODEL) {
            // k or v region: transposed coalesced store to KT/VT
            int reg = (bn + nh * 128) >> 10;           // 1=k, 2=v
            fp16* T = (reg == 1) ? KT : VT;
            int dbase = bn + nh * 128 - reg * 1024;
            int b = bm >> 12, s0v = bm & 4095;
            fp16* Tb = T + (size_t)b * D_MODEL * SEQ + s0v;
#pragma unroll 4
            for (int it = 0; it < 64; it++) {
                int idx = tid + it * 256;
                int c = idx >> 7, r = idx & 127;
                int gn = bn + nh * 128 + c;
                float tv = stg[r * SSTG + c] + (bias ? bias[gn] : 0.f);
                if (reg == 1) tv = (tv > 0.f) ? tv + 1.f : expf(tv);
                Tb[(size_t)(dbase + c) * SEQ + r] = __float2half(tv);
            }
        } else {
#pragma unroll 4
            for (int it = 0; it < 64; it++) {
                int idx = tid + it * 256;
                int r = idx >> 7, c = idx & 127;
                int gm = bm + r, gn = bn + nh * 128 + c;
                if (gn < N) {
                    float tv = stg[r * SSTG + c] + (bias ? bias[gn] : 0.f);
                    long long ci = (long long)gm * ldc + gn;
                    float outv;
                    if (epi == 0) {
                        outv = tv;
                    } else if (epi == 1) {         // q cols: elu+1
                        outv = (tv > 0.f) ? tv + 1.f : expf(tv);
                    } else {                       // 2: residual + normalize
                        outv = e2[ci] + tv / (e1[gm] + ATTN_EPS_F);
                    }
                    if (C) C[ci] = outv;
                    if (Ch && gn < colLim)
                        Ch[(long long)gm * ldch + gn] = __float2half(outv);
                }
            }
        }
        __syncthreads();
    }
}

// ===================== weight transpose (fp32 -> fp16, optional row remap) ==
// map: 0 identity; 1 gate-interleave (out row 16*(n/8)+(n%8));
//      2 up-interleave (gate+8)
__global__ void __launch_bounds__(256) transpose_f2h_kernel(
    const float* __restrict__ in, fp16* __restrict__ oh,
    int R, int Ccols, int ldi, int ldo, int map)
{
    __shared__ float tile[32][33];
    int r0 = blockIdx.y * 32, c0 = blockIdx.x * 32;
    int tx = threadIdx.x & 31, ty = threadIdx.x >> 5;
#pragma unroll
    for (int i = 0; i < 32; i += 8) {
        int r = r0 + ty + i, c = c0 + tx;
        tile[ty + i][tx] = (r < R && c < Ccols) ? in[(long long)r * ldi + c] : 0.f;
    }
    __syncthreads();
#pragma unroll
    for (int i = 0; i < 32; i += 8) {
        int r = c0 + ty + i, c = r0 + tx;
        if (r < Ccols && c < R) {
            int rr = r;
            if (map) rr = ((r >> 3) << 4) + (r & 7) + (map == 2 ? 8 : 0);
            oh[(long long)rr * ldo + c] = __float2half(tile[tx][ty + i]);
        }
    }
}

// ===================== small kernels ========================================
__global__ void conv_kernel(const float* __restrict__ in, fp16* __restrict__ oh, int n)
{
    int i = blockIdx.x * 256 + threadIdx.x;
    if (i < n) oh[i] = __float2half(in[i]);
}
__global__ void bias_interleave_kernel(const float* __restrict__ bg,
                                       const float* __restrict__ bu)
{
    int n = blockIdx.x * 256 + threadIdx.x;
    if (n < HFF) {
        int o = ((n >> 3) << 4) + (n & 7);
        g_bgu[o] = bg[n];
        g_bgu[o + 8] = bu[n];
    }
}
// ksum over contiguous kpT rows: one warp per (b,d)
__global__ void ksum_kernel() {
    int row = blockIdx.x * 8 + (threadIdx.x >> 5);    // grid 512, row in [0,4096)
    int lane = threadIdx.x & 31;
    const fp16* p = g_kpT + (size_t)row * SEQ;
    float s = 0.f;
    for (int i = lane; i < SEQ; i += 32) s += __half2float(p[i]);
#pragma unroll
    for (int o = 16; o > 0; o >>= 1) s += __shfl_xor_sync(0xffffffffu, s, o);
    if (lane == 0) g_ksum[row] = s;
}
__global__ void den_kernel() {
    int m = blockIdx.x * 8 + (threadIdx.x >> 5);
    int lane = threadIdx.x & 31;
    const fp16* q  = g_qkvh + (size_t)m * D3;      // qp (elu+1 applied)
    const float* ks = g_ksum + (m / SEQ) * D_MODEL;
    float s = 0.f;
    for (int d = lane; d < D_MODEL; d += 32) s += __half2float(q[d]) * ks[d];
#pragma unroll
    for (int o = 16; o > 0; o >>= 1) s += __shfl_xor_sync(0xffffffffu, s, o);
    if (lane == 0) g_den[m] = s;
}
__global__ void ln_kernel(const float* __restrict__ in1, const float* __restrict__ in2,
                          const float* __restrict__ gamma, const float* __restrict__ beta,
                          float* __restrict__ out, fp16* __restrict__ oh)
{
    int row = blockIdx.x;
    int t = threadIdx.x;
    long long base = (long long)row * D_MODEL;
    float vals[4];
    float s = 0.f;
#pragma unroll
    for (int i = 0; i < 4; i++) {
        int c = t + i * 256;
        float v = in1[base + c];
        if (in2) v += in2[base + c];
        vals[i] = v; s += v;
    }
    __shared__ float red[256];
    red[t] = s; __syncthreads();
    for (int o = 128; o > 0; o >>= 1) { if (t < o) red[t] += red[t + o]; __syncthreads(); }
    float mu = red[0] * (1.f / D_MODEL);
    __syncthreads();
    float vs = 0.f;
#pragma unroll
    for (int i = 0; i < 4; i++) { float d = vals[i] - mu; vs += d * d; }
    red[t] = vs; __syncthreads();
    for (int o = 128; o > 0; o >>= 1) { if (t < o) red[t] += red[t + o]; __syncthreads(); }
    float inv = rsqrtf(red[0] * (1.f / D_MODEL) + LN_EPS_F);
#pragma unroll
    for (int i = 0; i < 4; i++) {
        int c = t + i * 256;
        float v = (vals[i] - mu) * inv * gamma[c] + beta[c];
        out[base + c] = v;
        if (oh) oh[base + c] = __float2half(v);
    }
}

// ===================== launch ===============================================
extern "C" void kernel_launch(void* const* d_in, const int* in_sizes, int n_in,
                              void* d_out, int out_size)
{
    const float* x    = (const float*)d_in[0];
    const float* Wqkv = (const float*)d_in[1];
    const float* bqkv = (const float*)d_in[2];
    const float* Wg   = (const float*)d_in[3];
    const float* bg   = (const float*)d_in[4];
    const float* Wu   = (const float*)d_in[5];
    const float* bu   = (const float*)d_in[6];
    const float* Wd   = (const float*)d_in[7];
    const float* bd   = (const float*)d_in[8];
    const float* g1   = (const float*)d_in[9];
    const float* b1   = (const float*)d_in[10];
    const float* g2   = (const float*)d_in[11];
    const float* b2   = (const float*)d_in[12];
    float* out = (float*)d_out;

    float *den, *yb, *x1, *ffn, *bgu;
    fp16 *qkvh,*xh,*WqkvT,*WguT,*WdT,*kpT,*vT,*kvh,*x1h,*hh;
    cudaGetSymbolAddress((void**)&qkvh, g_qkvh);
    cudaGetSymbolAddress((void**)&den,  g_den);
    cudaGetSymbolAddress((void**)&yb,   g_y);
    cudaGetSymbolAddress((void**)&x1,   g_x1);
    cudaGetSymbolAddress((void**)&ffn,  g_ffn);
    cudaGetSymbolAddress((void**)&bgu,  g_bgu);
    cudaGetSymbolAddress((void**)&xh,   g_xh);
    cudaGetSymbolAddress((void**)&WqkvT,g_WqkvT);
    cudaGetSymbolAddress((void**)&WguT, g_WguT);
    cudaGetSymbolAddress((void**)&WdT,  g_WdT);
    cudaGetSymbolAddress((void**)&kpT,  g_kpT);
    cudaGetSymbolAddress((void**)&vT,   g_vT);
    cudaGetSymbolAddress((void**)&kvh,  g_kvh);
    cudaGetSymbolAddress((void**)&x1h,  g_x1h);
    cudaGetSymbolAddress((void**)&hh,   g_hh);

    cudaFuncSetAttribute(mma_gemm_kernel,
                         cudaFuncAttributeMaxDynamicSharedMemorySize, SMEM_SZ);

    dim3 blk(256);
    const long long SD3  = (long long)SEQ * D3;
    const long long SDM  = (long long)SEQ * D_MODEL;
    const long long DD   = (long long)D_MODEL * D_MODEL;
    const long long DS   = (long long)D_MODEL * SEQ;

    // ---- converts & weight transposes ----
    conv_kernel<<<(MTOT * D_MODEL) / 256, blk>>>(x, xh, MTOT * D_MODEL);
    transpose_f2h_kernel<<<dim3(D3/32, D_MODEL/32), blk>>>(
        Wqkv, WqkvT, D_MODEL, D3, D3, D_MODEL, 0);
    transpose_f2h_kernel<<<dim3((HFF+31)/32, D_MODEL/32), blk>>>(
        Wg, WguT, D_MODEL, HFF, HFF, D_MODEL, 1);
    transpose_f2h_kernel<<<dim3((HFF+31)/32, D_MODEL/32), blk>>>(
        Wu, WguT, D_MODEL, HFF, HFF, D_MODEL, 2);
    transpose_f2h_kernel<<<dim3(D_MODEL/32, (HFF+31)/32), blk>>>(
        Wd, WdT, HFF, D_MODEL, D_MODEL, HFFP, 0);
    bias_interleave_kernel<<<(HFF+255)/256, blk>>>(bg, bu);

    // ---- 1) qkv GEMM: q->qkvh (elu+1), k->kpT (elu+1, transposed), v->vT ----
    mma_gemm_kernel<<<dim3(D3/BN, MTOT/BM, 1), blk, SMEM_SZ>>>(
        xh, WqkvT, bqkv, nullptr, qkvh, kpT, vT,
        MTOT, D3, D_MODEL, D_MODEL, D_MODEL, D3, D3,
        0, 0, 0, 0, 1, D_MODEL, nullptr, nullptr, 0);

    // ---- ksum (rows of kpT), den ----
    ksum_kernel<<<512, blk>>>();
    den_kernel<<<MTOT/8, blk>>>();

    // ---- 2) kvh[e][d] = fp16(sum_s v[s,e] kp[s,d]) ----
    mma_gemm_kernel<<<dim3(D_MODEL/BN, D_MODEL/BM, BATCH), blk, SMEM_SZ>>>(
        vT, kpT, nullptr, nullptr, kvh, nullptr, nullptr,
        D_MODEL, D_MODEL, SEQ, SEQ, SEQ, D_MODEL, D_MODEL,
        DS, DS, DD, DD, 0, D_MODEL, nullptr, nullptr, 0);

    // ---- 3) y = x + (qp @ kv) / (den + eps)   (A = qkvh cols 0..1023) ----
    mma_gemm_kernel<<<dim3(D_MODEL/BN, SEQ/BM, BATCH), blk, SMEM_SZ>>>(
        qkvh, kvh, nullptr, yb, nullptr, nullptr, nullptr,
        SEQ, D_MODEL, D_MODEL, D3, D_MODEL, D_MODEL, D_MODEL,
        SD3, DD, SDM, 0, 2, 0, den, x, (long long)SEQ);

    // ---- 4) x1 = LN(y); fp16 fused ----
    ln_kernel<<<MTOT, blk>>>(yb, nullptr, g1, b1, x1, x1h);

    // ---- 5+6) hh = fp16(silu(x1@Wg+bg) * (x1@Wu+bu))  [one fused GEMM] ----
    mma_gemm_kernel<<<dim3((NGU+BN-1)/BN, MTOT/BM, 1), blk, SMEM_SZ>>>(
        x1h, WguT, bgu, nullptr, hh, nullptr, nullptr,
        MTOT, NGU, D_MODEL, D_MODEL, D_MODEL, NGU, HFFP,
        0, 0, 0, 0, 5, HFF, nullptr, nullptr, 0);

    // ---- 7) ffn = h @ Wd + bd ----
    mma_gemm_kernel<<<dim3(D_MODEL/BN, MTOT/BM, 1), blk, SMEM_SZ>>>(
        hh, WdT, bd, ffn, nullptr, nullptr, nullptr,
        MTOT, D_MODEL, HFF, HFFP, HFFP, D_MODEL, D_MODEL,
        0, 0, 0, 0, 0, 0, nullptr, nullptr, 0);

    // ---- 8) out = LN(x1 + ffn) ----
    ln_kernel<<<MTOT, blk>>>(x1, ffn, g2, b2, out, nullptr);
}

// round 9
// speedup vs baseline: 7.4320x; 1.3000x over previous
#include <cuda_runtime.h>
#include <cuda_fp16.h>
#include <cstdint>
#include <math.h>

#define D_MODEL 1024
#define D3      3072
#define HFF     2730
#define HFFP    2736                 // HFF padded to 8-element (16B) multiple
#define NGU     5472                 // interleaved gate/up N (2*2736)
#define BATCH   4
#define SEQ     4096
#define MTOT    (BATCH*SEQ)          // 16384

#define LN_EPS_F   1e-5f
#define ATTN_EPS_F 1e-6f

typedef __half fp16;

// ===================== scratch ==============================================
__device__ fp16  g_qkvh[(size_t)MTOT * D3];         // only q cols [0,1024) used
__device__ fp16  g_xh  [(size_t)MTOT * D_MODEL];
__device__ fp16  g_WqkvT[(size_t)D3 * D_MODEL];
__device__ fp16  g_WguT[(size_t)NGU * D_MODEL];     // interleaved gate/up rows (8-blocks)
__device__ float g_bgu [5632];                      // interleaved biases (zero padded)
__device__ fp16  g_WdT [(size_t)D_MODEL * HFFP];    // padded ld
__device__ fp16  g_kpT [(size_t)BATCH * D_MODEL * SEQ];
__device__ fp16  g_vT  [(size_t)BATCH * D_MODEL * SEQ];
__device__ fp16  g_kvh [(size_t)BATCH * D_MODEL * D_MODEL];
__device__ float g_ksum[BATCH * D_MODEL];
__device__ float g_den[MTOT];
__device__ float g_y [(size_t)MTOT * D_MODEL];
__device__ float g_x1[(size_t)MTOT * D_MODEL];
__device__ fp16  g_x1h[(size_t)MTOT * D_MODEL];
__device__ fp16  g_hh[(size_t)MTOT * HFFP];         // fused silu(gate)*up, padded ld
__device__ float g_ffn[(size_t)MTOT * D_MODEL];

// ===================== helpers ==============================================
__device__ __forceinline__ uint32_t smem_u32(const void* p) {
    uint32_t a;
    asm("{ .reg .u64 t; cvta.to.shared.u64 t, %1; cvt.u32.u64 %0, t; }" : "=r"(a) : "l"(p));
    return a;
}
__device__ __forceinline__ void cp16(uint32_t dst, const void* src, int bytes) {
    asm volatile("cp.async.cg.shared.global [%0], [%1], 16, %2;\n"
        :: "r"(dst), "l"(src), "r"(bytes));
}
#define CP_COMMIT() asm volatile("cp.async.commit_group;\n" ::: "memory")
#define CP_WAIT(n)  asm volatile("cp.async.wait_group %0;\n" :: "n"(n) : "memory")

__device__ __forceinline__ void ldmx4(uint32_t& r0, uint32_t& r1, uint32_t& r2,
                                      uint32_t& r3, uint32_t addr) {
    asm volatile("ldmatrix.sync.aligned.m8n8.x4.shared.b16 {%0,%1,%2,%3}, [%4];"
        : "=r"(r0), "=r"(r1), "=r"(r2), "=r"(r3) : "r"(addr));
}
__device__ __forceinline__ void mma16816(float* c, const uint32_t* a, uint32_t b0, uint32_t b1) {
    asm volatile(
        "mma.sync.aligned.m16n8k16.row.col.f32.f16.f16.f32 "
        "{%0,%1,%2,%3}, {%4,%5,%6,%7}, {%8,%9}, {%0,%1,%2,%3};"
        : "+f"(c[0]), "+f"(c[1]), "+f"(c[2]), "+f"(c[3])
        : "r"(a[0]), "r"(a[1]), "r"(a[2]), "r"(a[3]), "r"(b0), "r"(b1));
}
__device__ __forceinline__ float silu_f(float g) { return g / (1.f + expf(-g)); }

// ===================== mma.sync fp16 GEMM (fp32 accum) ======================
// C[m,n] = sum_k A[m,k] * Bt[n,k]  (fp16, Bt = B^T [N][K] row-major)
// BM=128, BN=128, BK=32. 8 warps: 2 m-warps x 4 n-warps, 64x32 warp tile.
// 2 CTAs/SM (regs <=128). 4-stage cp.async pipeline.
// epi: 0 plain(+bias); 1 qkv (q->qkvh elu+1, k->KT elu+1 transposed, v->VT);
//      2 residual+attn-div; 5 fused silu(gate)*up (interleaved B) -> Ch only.
#define BM 128
#define BN 128
#define BK 32
#define SROW 40                       // halves per smem row (32 + 8 pad)
#define A_HALVES (128 * SROW)         // 5120
#define B_HALVES (128 * SROW)         // 5120
#define STAGE_B ((A_HALVES + B_HALVES) * 2)   // 20480 bytes
#define NSTAGE 4
#define SMEM_SZ (NSTAGE * STAGE_B)    // 81920; epilogue staging 68096 fits
#define SSTG 133                      // staging stride (conflict-free transposed reads)

__global__ void __launch_bounds__(256, 2) mma_gemm_kernel(
    const fp16* __restrict__ Ah, const fp16* __restrict__ Bh,
    const float* __restrict__ bias, float* __restrict__ C,
    fp16* __restrict__ Ch, fp16* __restrict__ KT, fp16* __restrict__ VT,
    int M, int N, int K, int lda, int ldb, int ldc, int ldch,
    long long sA, long long sB, long long sC, long long sCh,
    int epi, int colLim,
    const float* __restrict__ e1, const float* __restrict__ e2, long long sE1)
{
    extern __shared__ __align__(16) char smem[];
    const uint32_t sbase = smem_u32(smem);
    const int tid = threadIdx.x;
    const int wid = tid >> 5;
    const int lane = tid & 31;
    const int warp_m = wid & 1;        // 2 m-warps of 64 rows
    const int warp_n = wid >> 1;       // 4 n-warps of 32 cols
    const int bz = blockIdx.z;
    Ah += sA * bz;  Bh += sB * bz;
    if (C)  C  += sC * bz;
    if (Ch) Ch += sCh * bz;
    if (e1) e1 += sE1 * bz;
    if (e2) e2 += sC * bz;
    const int bm = blockIdx.y * BM;
    const int bn = blockIdx.x * BN;

    float acc[4][4][4];
#pragma unroll
    for (int i = 0; i < 4; i++)
#pragma unroll
        for (int j = 0; j < 4; j++)
#pragma unroll
            for (int v = 0; v < 4; v++) acc[i][j][v] = 0.f;

    const uint32_t a_base =
        ((uint32_t)(warp_m * 64 + (lane & 15)) * SROW + ((lane >> 4) * 8)) * 2;
    const uint32_t b_base = (uint32_t)A_HALVES * 2 +
        (((uint32_t)(warp_n * 32 + ((lane >> 4) & 1) * 8 + (lane & 7))) * SROW +
         (((lane >> 3) & 1) * 8)) * 2;

    const int ntiles = (K + BK - 1) / BK;

    auto load_stage = [&](int s, int t) {
        uint32_t sb = sbase + s * STAGE_B;
        int k0 = t * BK;
#pragma unroll
        for (int j = 0; j < 2; j++) {
            int idx = tid + j * 256;
            int r = idx >> 2, ch = idx & 3;
            int kc = k0 + ch * 8;
            int ab = 2 * (K - kc); ab = ab < 0 ? 0 : (ab > 16 ? 16 : ab);
            cp16(sb + (r * SROW + ch * 8) * 2, Ah + (long long)(bm + r) * lda + kc, ab);
        }
#pragma unroll
        for (int j = 0; j < 2; j++) {
            int idx = tid + j * 256;
            int r = idx >> 2, ch = idx & 3;
            int kc = k0 + ch * 8;
            int ab = 2 * (K - kc); ab = ab < 0 ? 0 : (ab > 16 ? 16 : ab);
            int gn = bn + r;
            int bb = (gn < N) ? ab : 0;
            cp16(sb + A_HALVES * 2 + (r * SROW + ch * 8) * 2,
                 Bh + (long long)(gn < N ? gn : 0) * ldb + kc, bb);
        }
    };

    load_stage(0, 0); CP_COMMIT();
    if (ntiles > 1) load_stage(1, 1);
    CP_COMMIT();
    if (ntiles > 2) load_stage(2, 2);
    CP_COMMIT();

    for (int t = 0; t < ntiles; t++) {
        CP_WAIT(2);
        __syncthreads();
        int ls = t + NSTAGE - 1;
        if (ls < ntiles) load_stage(ls & (NSTAGE - 1), ls);
        CP_COMMIT();

        uint32_t sb = sbase + (t & (NSTAGE - 1)) * STAGE_B;
#pragma unroll
        for (int kk = 0; kk < 2; kk++) {
            uint32_t a[4][4], b[2][4];
#pragma unroll
            for (int mi = 0; mi < 4; mi++)
                ldmx4(a[mi][0], a[mi][1], a[mi][2], a[mi][3],
                      sb + a_base + (uint32_t)(mi * 16 * SROW * 2) + kk * 32);
#pragma unroll
            for (int p = 0; p < 2; p++)
                ldmx4(b[p][0], b[p][1], b[p][2], b[p][3],
                      sb + b_base + (uint32_t)(p * 16 * SROW * 2) + kk * 32);
#pragma unroll
            for (int mi = 0; mi < 4; mi++)
#pragma unroll
                for (int nj = 0; nj < 4; nj++)
                    mma16816(acc[mi][nj], a[mi], b[nj >> 1][(nj & 1) * 2],
                             b[nj >> 1][(nj & 1) * 2 + 1]);
        }
    }
    CP_WAIT(0);
    __syncthreads();

    float* stg = (float*)smem;
    const int gID = lane >> 2, t4 = lane & 3;

    if (epi == 5) {
        // ---- fused silu(gate)*up: nj even = gate, nj odd = up ----
#pragma unroll
        for (int p = 0; p < 2; p++) {
            int bc = bn + warp_n * 32 + p * 16 + 2 * t4;
            float bg0 = bias[bc],     bg1 = bias[bc + 1];
            float bu0 = bias[bc + 8], bu1 = bias[bc + 9];
            int hc = warp_n * 16 + p * 8 + 2 * t4;
#pragma unroll
            for (int mi = 0; mi < 4; mi++) {
                int r0 = warp_m * 64 + mi * 16 + gID;
                float o0 = silu_f(acc[mi][2*p][0] + bg0) * (acc[mi][2*p+1][0] + bu0);
                float o1 = silu_f(acc[mi][2*p][1] + bg1) * (acc[mi][2*p+1][1] + bu1);
                float o2 = silu_f(acc[mi][2*p][2] + bg0) * (acc[mi][2*p+1][2] + bu0);
                float o3 = silu_f(acc[mi][2*p][3] + bg1) * (acc[mi][2*p+1][3] + bu1);
                stg[r0 * SSTG + hc]           = o0;
                stg[r0 * SSTG + hc + 1]       = o1;
                stg[(r0 + 8) * SSTG + hc]     = o2;
                stg[(r0 + 8) * SSTG + hc + 1] = o3;
            }
        }
        __syncthreads();
        int hbase = bn >> 1;
#pragma unroll 4
        for (int it = 0; it < 32; it++) {
            int idx = tid + it * 256;
            int r = idx >> 6, c = idx & 63;
            int hcol = hbase + c;
            if (hcol < HFF)
                Ch[(long long)(bm + r) * ldch + hcol] = __float2half(stg[r * SSTG + c]);
        }
        return;
    }

    // ---- generic: single 128-col pass via SMEM staging ----
#pragma unroll
    for (int mi = 0; mi < 4; mi++)
#pragma unroll
        for (int nj = 0; nj < 4; nj++) {
            int r0 = warp_m * 64 + mi * 16 + gID;
            int c0 = warp_n * 32 + nj * 8 + 2 * t4;
            stg[r0 * SSTG + c0]           = acc[mi][nj][0];
            stg[r0 * SSTG + c0 + 1]       = acc[mi][nj][1];
            stg[(r0 + 8) * SSTG + c0]     = acc[mi][nj][2];
            stg[(r0 + 8) * SSTG + c0 + 1] = acc[mi][nj][3];
        }
    __syncthreads();

    if (epi == 1 && bn >= D_MODEL) {
        // k or v region: transposed coalesced store to KT/VT
        int reg = bn >> 10;                        // 1=k, 2=v
        fp16* T = (reg == 1) ? KT : VT;
        int dbase = bn - reg * 1024;
        int b = bm >> 12, s0v = bm & 4095;
        fp16* Tb = T + (size_t)b * D_MODEL * SEQ + s0v;
#pragma unroll 4
        for (int it = 0; it < 64; it++) {
            int idx = tid + it * 256;
            int c = idx >> 7, r = idx & 127;
            int gn = bn + c;
            float tv = stg[r * SSTG + c] + (bias ? bias[gn] : 0.f);
            if (reg == 1) tv = (tv > 0.f) ? tv + 1.f : expf(tv);
            Tb[(size_t)(dbase + c) * SEQ + r] = __float2half(tv);
        }
    } else {
#pragma unroll 4
        for (int it = 0; it < 64; it++) {
            int idx = tid + it * 256;
            int r = idx >> 7, c = idx & 127;
            int gm = bm + r, gn = bn + c;
            if (gn < N) {
                float tv = stg[r * SSTG + c] + (bias ? bias[gn] : 0.f);
                long long ci = (long long)gm * ldc + gn;
                float outv;
                if (epi == 0) {
                    outv = tv;
                } else if (epi == 1) {         // q cols: elu+1
                    outv = (tv > 0.f) ? tv + 1.f : expf(tv);
                } else {                       // 2: residual + normalize
                    outv = e2[ci] + tv / (e1[gm] + ATTN_EPS_F);
                }
                if (C) C[ci] = outv;
                if (Ch && gn < colLim)
                    Ch[(long long)gm * ldch + gn] = __float2half(outv);
            }
        }
    }
}

// ===================== weight transpose (fp32 -> fp16, optional row remap) ==
__global__ void __launch_bounds__(256) transpose_f2h_kernel(
    const float* __restrict__ in, fp16* __restrict__ oh,
    int R, int Ccols, int ldi, int ldo, int map)
{
    __shared__ float tile[32][33];
    int r0 = blockIdx.y * 32, c0 = blockIdx.x * 32;
    int tx = threadIdx.x & 31, ty = threadIdx.x >> 5;
#pragma unroll
    for (int i = 0; i < 32; i += 8) {
        int r = r0 + ty + i, c = c0 + tx;
        tile[ty + i][tx] = (r < R && c < Ccols) ? in[(long long)r * ldi + c] : 0.f;
    }
    __syncthreads();
#pragma unroll
    for (int i = 0; i < 32; i += 8) {
        int r = c0 + ty + i, c = r0 + tx;
        if (r < Ccols && c < R) {
            int rr = r;
            if (map) rr = ((r >> 3) << 4) + (r & 7) + (map == 2 ? 8 : 0);
            oh[(long long)rr * ldo + c] = __float2half(tile[tx][ty + i]);
        }
    }
}

// ===================== small kernels ========================================
__global__ void conv_kernel(const float* __restrict__ in, fp16* __restrict__ oh, int n)
{
    int i = blockIdx.x * 256 + threadIdx.x;
    if (i < n) oh[i] = __float2half(in[i]);
}
__global__ void bias_interleave_kernel(const float* __restrict__ bg,
                                       const float* __restrict__ bu)
{
    int n = blockIdx.x * 256 + threadIdx.x;
    if (n < HFF) {
        int o = ((n >> 3) << 4) + (n & 7);
        g_bgu[o] = bg[n];
        g_bgu[o + 8] = bu[n];
    }
}
__global__ void ksum_kernel() {
    int row = blockIdx.x * 8 + (threadIdx.x >> 5);
    int lane = threadIdx.x & 31;
    const __half2* p = (const __half2*)(g_kpT + (size_t)row * SEQ);
    float s = 0.f;
    for (int i = lane; i < SEQ / 2; i += 32) {
        float2 v = __half22float2(p[i]);
        s += v.x + v.y;
    }
#pragma unroll
    for (int o = 16; o > 0; o >>= 1) s += __shfl_xor_sync(0xffffffffu, s, o);
    if (lane == 0) g_ksum[row] = s;
}
__global__ void den_kernel() {
    int m = blockIdx.x * 8 + (threadIdx.x >> 5);
    int lane = threadIdx.x & 31;
    const __half2* q = (const __half2*)(g_qkvh + (size_t)m * D3);
    const float2* ks = (const float2*)(g_ksum + (m / SEQ) * D_MODEL);
    float s = 0.f;
    for (int d = lane; d < D_MODEL / 2; d += 32) {
        float2 qv = __half22float2(q[d]);
        float2 kv = ks[d];
        s += qv.x * kv.x + qv.y * kv.y;
    }
#pragma unroll
    for (int o = 16; o > 0; o >>= 1) s += __shfl_xor_sync(0xffffffffu, s, o);
    if (lane == 0) g_den[m] = s;
}
__global__ void ln_kernel(const float* __restrict__ in1, const float* __restrict__ in2,
                          const float* __restrict__ gamma, const float* __restrict__ beta,
                          float* __restrict__ out, fp16* __restrict__ oh)
{
    int row = blockIdx.x;
    int t = threadIdx.x;
    long long base4 = (long long)row * (D_MODEL / 4);
    float4 v4 = ((const float4*)in1)[base4 + t];
    if (in2) {
        float4 w4 = ((const float4*)in2)[base4 + t];
        v4.x += w4.x; v4.y += w4.y; v4.z += w4.z; v4.w += w4.w;
    }
    float s = v4.x + v4.y + v4.z + v4.w;
    __shared__ float red[256];
    red[t] = s; __syncthreads();
    for (int o = 128; o > 0; o >>= 1) { if (t < o) red[t] += red[t + o]; __syncthreads(); }
    float mu = red[0] * (1.f / D_MODEL);
    __syncthreads();
    float dx = v4.x - mu, dy = v4.y - mu, dz = v4.z - mu, dw = v4.w - mu;
    red[t] = dx * dx + dy * dy + dz * dz + dw * dw;
    __syncthreads();
    for (int o = 128; o > 0; o >>= 1) { if (t < o) red[t] += red[t + o]; __syncthreads(); }
    float inv = rsqrtf(red[0] * (1.f / D_MODEL) + LN_EPS_F);
    float4 g4 = ((const float4*)gamma)[t];
    float4 b4 = ((const float4*)beta)[t];
    float4 o4;
    o4.x = dx * inv * g4.x + b4.x;
    o4.y = dy * inv * g4.y + b4.y;
    o4.z = dz * inv * g4.z + b4.z;
    o4.w = dw * inv * g4.w + b4.w;
    ((float4*)out)[base4 + t] = o4;
    if (oh) {
        __half2 h0 = __floats2half2_rn(o4.x, o4.y);
        __half2 h1 = __floats2half2_rn(o4.z, o4.w);
        ((__half2*)oh)[base4 * 2 + 2 * t]     = h0;
        ((__half2*)oh)[base4 * 2 + 2 * t + 1] = h1;
    }
}

// ===================== launch ===============================================
extern "C" void kernel_launch(void* const* d_in, const int* in_sizes, int n_in,
                              void* d_out, int out_size)
{
    const float* x    = (const float*)d_in[0];
    const float* Wqkv = (const float*)d_in[1];
    const float* bqkv = (const float*)d_in[2];
    const float* Wg   = (const float*)d_in[3];
    const float* bg   = (const float*)d_in[4];
    const float* Wu   = (const float*)d_in[5];
    const float* bu   = (const float*)d_in[6];
    const float* Wd   = (const float*)d_in[7];
    const float* bd   = (const float*)d_in[8];
    const float* g1   = (const float*)d_in[9];
    const float* b1   = (const float*)d_in[10];
    const float* g2   = (const float*)d_in[11];
    const float* b2   = (const float*)d_in[12];
    float* out = (float*)d_out;

    float *den, *yb, *x1, *ffn, *bgu;
    fp16 *qkvh,*xh,*WqkvT,*WguT,*WdT,*kpT,*vT,*kvh,*x1h,*hh;
    cudaGetSymbolAddress((void**)&qkvh, g_qkvh);
    cudaGetSymbolAddress((void**)&den,  g_den);
    cudaGetSymbolAddress((void**)&yb,   g_y);
    cudaGetSymbolAddress((void**)&x1,   g_x1);
    cudaGetSymbolAddress((void**)&ffn,  g_ffn);
    cudaGetSymbolAddress((void**)&bgu,  g_bgu);
    cudaGetSymbolAddress((void**)&xh,   g_xh);
    cudaGetSymbolAddress((void**)&WqkvT,g_WqkvT);
    cudaGetSymbolAddress((void**)&WguT, g_WguT);
    cudaGetSymbolAddress((void**)&WdT,  g_WdT);
    cudaGetSymbolAddress((void**)&kpT,  g_kpT);
    cudaGetSymbolAddress((void**)&vT,   g_vT);
    cudaGetSymbolAddress((void**)&kvh,  g_kvh);
    cudaGetSymbolAddress((void**)&x1h,  g_x1h);
    cudaGetSymbolAddress((void**)&hh,   g_hh);

    cudaFuncSetAttribute(mma_gemm_kernel,
                         cudaFuncAttributeMaxDynamicSharedMemorySize, SMEM_SZ);

    dim3 blk(256);
    const long long SD3  = (long long)SEQ * D3;
    const long long SDM  = (long long)SEQ * D_MODEL;
    const long long DD   = (long long)D_MODEL * D_MODEL;
    const long long DS   = (long long)D_MODEL * SEQ;

    // ---- converts & weight transposes ----
    conv_kernel<<<(MTOT * D_MODEL) / 256, blk>>>(x, xh, MTOT * D_MODEL);
    transpose_f2h_kernel<<<dim3(D3/32, D_MODEL/32), blk>>>(
        Wqkv, WqkvT, D_MODEL, D3, D3, D_MODEL, 0);
    transpose_f2h_kernel<<<dim3((HFF+31)/32, D_MODEL/32), blk>>>(
        Wg, WguT, D_MODEL, HFF, HFF, D_MODEL, 1);
    transpose_f2h_kernel<<<dim3((HFF+31)/32, D_MODEL/32), blk>>>(
        Wu, WguT, D_MODEL, HFF, HFF, D_MODEL, 2);
    transpose_f2h_kernel<<<dim3(D_MODEL/32, (HFF+31)/32), blk>>>(
        Wd, WdT, HFF, D_MODEL, D_MODEL, HFFP, 0);
    bias_interleave_kernel<<<(HFF+255)/256, blk>>>(bg, bu);

    // ---- 1) qkv GEMM: q->qkvh (elu+1), k->kpT (elu+1, transposed), v->vT ----
    mma_gemm_kernel<<<dim3(D3/BN, MTOT/BM, 1), blk, SMEM_SZ>>>(
        xh, WqkvT, bqkv, nullptr, qkvh, kpT, vT,
        MTOT, D3, D_MODEL, D_MODEL, D_MODEL, D3, D3,
        0, 0, 0, 0, 1, D_MODEL, nullptr, nullptr, 0);

    // ---- ksum (rows of kpT), den ----
    ksum_kernel<<<512, blk>>>();
    den_kernel<<<MTOT/8, blk>>>();

    // ---- 2) kvh[e][d] = fp16(sum_s v[s,e] kp[s,d]) ----
    mma_gemm_kernel<<<dim3(D_MODEL/BN, D_MODEL/BM, BATCH), blk, SMEM_SZ>>>(
        vT, kpT, nullptr, nullptr, kvh, nullptr, nullptr,
        D_MODEL, D_MODEL, SEQ, SEQ, SEQ, D_MODEL, D_MODEL,
        DS, DS, DD, DD, 0, D_MODEL, nullptr, nullptr, 0);

    // ---- 3) y = x + (qp @ kv) / (den + eps)   (A = qkvh cols 0..1023) ----
    mma_gemm_kernel<<<dim3(D_MODEL/BN, SEQ/BM, BATCH), blk, SMEM_SZ>>>(
        qkvh, kvh, nullptr, yb, nullptr, nullptr, nullptr,
        SEQ, D_MODEL, D_MODEL, D3, D_MODEL, D_MODEL, D_MODEL,
        SD3, DD, SDM, 0, 2, 0, den, x, (long long)SEQ);

    // ---- 4) x1 = LN(y); fp16 fused ----
    ln_kernel<<<MTOT, blk>>>(yb, nullptr, g1, b1, x1, x1h);

    // ---- 5+6) hh = fp16(silu(x1@Wg+bg) * (x1@Wu+bu))  [one fused GEMM] ----
    mma_gemm_kernel<<<dim3((NGU+BN-1)/BN, MTOT/BM, 1), blk, SMEM_SZ>>>(
        x1h, WguT, bgu, nullptr, hh, nullptr, nullptr,
        MTOT, NGU, D_MODEL, D_MODEL, D_MODEL, NGU, HFFP,
        0, 0, 0, 0, 5, HFF, nullptr, nullptr, 0);

    // ---- 7) ffn = h @ Wd + bd ----
    mma_gemm_kernel<<<dim3(D_MODEL/BN, MTOT/BM, 1), blk, SMEM_SZ>>>(
        hh, WdT, bd, ffn, nullptr, nullptr, nullptr,
        MTOT, D_MODEL, HFF, HFFP, HFFP, D_MODEL, D_MODEL,
        0, 0, 0, 0, 0, 0, nullptr, nullptr, 0);

    // ---- 8) out = LN(x1 + ffn) ----
    ln_kernel<<<MTOT, blk>>>(x1, ffn, g2, b2, out, nullptr);
}

// round 10
// speedup vs baseline: 8.0143x; 1.0783x over previous
#include <cuda_runtime.h>
#include <cuda_fp16.h>
#include <cstdint>
#include <math.h>

#define D_MODEL 1024
#define D3      3072
#define HFF     2730
#define HFFP    2736                 // HFF padded to 8-element (16B) multiple
#define NGU     5472                 // interleaved gate/up N (2*2736)
#define BATCH   4
#define SEQ     4096
#define MTOT    (BATCH*SEQ)          // 16384

#define LN_EPS_F   1e-5f
#define ATTN_EPS_F 1e-6f

typedef __half fp16;

// ===================== scratch ==============================================
__device__ fp16  g_qkvh[(size_t)MTOT * D3];         // only q cols [0,1024) used
__device__ fp16  g_xh  [(size_t)MTOT * D_MODEL];
__device__ fp16  g_WqkvT[(size_t)D3 * D_MODEL];
__device__ fp16  g_WguT[(size_t)NGU * D_MODEL];     // interleaved gate/up rows (8-blocks)
__device__ float g_bgu [5632];                      // interleaved biases (zero padded)
__device__ fp16  g_WdT [(size_t)D_MODEL * HFFP];    // padded ld
__device__ fp16  g_kpT [(size_t)BATCH * D_MODEL * SEQ];
__device__ fp16  g_vT  [(size_t)BATCH * D_MODEL * SEQ];
__device__ fp16  g_kvh [(size_t)BATCH * D_MODEL * D_MODEL];
__device__ float g_ksum[BATCH * D_MODEL];
__device__ float g_den[MTOT];
__device__ float g_y [(size_t)MTOT * D_MODEL];
__device__ float g_x1[(size_t)MTOT * D_MODEL];
__device__ fp16  g_x1h[(size_t)MTOT * D_MODEL];
__device__ fp16  g_hh[(size_t)MTOT * HFFP];         // fused silu(gate)*up, padded ld
__device__ float g_ffn[(size_t)MTOT * D_MODEL];

// ===================== helpers ==============================================
__device__ __forceinline__ uint32_t smem_u32(const void* p) {
    uint32_t a;
    asm("{ .reg .u64 t; cvta.to.shared.u64 t, %1; cvt.u32.u64 %0, t; }" : "=r"(a) : "l"(p));
    return a;
}
__device__ __forceinline__ void cp16(uint32_t dst, const void* src, int bytes) {
    asm volatile("cp.async.cg.shared.global [%0], [%1], 16, %2;\n"
        :: "r"(dst), "l"(src), "r"(bytes));
}
#define CP_COMMIT() asm volatile("cp.async.commit_group;\n" ::: "memory")
#define CP_WAIT(n)  asm volatile("cp.async.wait_group %0;\n" :: "n"(n) : "memory")

__device__ __forceinline__ void ldmx4(uint32_t& r0, uint32_t& r1, uint32_t& r2,
                                      uint32_t& r3, uint32_t addr) {
    asm volatile("ldmatrix.sync.aligned.m8n8.x4.shared.b16 {%0,%1,%2,%3}, [%4];"
        : "=r"(r0), "=r"(r1), "=r"(r2), "=r"(r3) : "r"(addr));
}
__device__ __forceinline__ void mma16816(float* c, const uint32_t* a, uint32_t b0, uint32_t b1) {
    asm volatile(
        "mma.sync.aligned.m16n8k16.row.col.f32.f16.f16.f32 "
        "{%0,%1,%2,%3}, {%4,%5,%6,%7}, {%8,%9}, {%0,%1,%2,%3};"
        : "+f"(c[0]), "+f"(c[1]), "+f"(c[2]), "+f"(c[3])
        : "r"(a[0]), "r"(a[1]), "r"(a[2]), "r"(a[3]), "r"(b0), "r"(b1));
}
__device__ __forceinline__ float silu_f(float g) { return g / (1.f + expf(-g)); }

// ===================== mma.sync fp16 GEMM (fp32 accum) ======================
// C[m,n] = sum_k A[m,k] * Bt[n,k]  (fp16, Bt = B^T [N][K] row-major)
// BM=128, BN=128, BK=64. 8 warps: 2 m-warps x 4 n-warps, 64x32 warp tile.
// 2 CTAs/SM (regs <=128). 3-stage cp.async pipeline.
// epi: 0 plain(+bias); 1 qkv (q->qkvh elu+1, k->KT elu+1 transposed, v->VT);
//      2 residual+attn-div; 5 fused silu(gate)*up (interleaved B) -> Ch only.
#define BM 128
#define BN 128
#define BK 64
#define SROW 72                       // halves per smem row (64 + 8 pad)
#define A_HALVES (128 * SROW)         // 9216
#define B_HALVES (128 * SROW)         // 9216
#define STAGE_B ((A_HALVES + B_HALVES) * 2)   // 36864 bytes
#define NSTAGE 3
#define SMEM_SZ (NSTAGE * STAGE_B)    // 110592; epilogue staging 68096 fits
#define SSTG 133                      // staging stride (conflict-free transposed reads)

__global__ void __launch_bounds__(256, 2) mma_gemm_kernel(
    const fp16* __restrict__ Ah, const fp16* __restrict__ Bh,
    const float* __restrict__ bias, float* __restrict__ C,
    fp16* __restrict__ Ch, fp16* __restrict__ KT, fp16* __restrict__ VT,
    int M, int N, int K, int lda, int ldb, int ldc, int ldch,
    long long sA, long long sB, long long sC, long long sCh,
    int epi, int colLim,
    const float* __restrict__ e1, const float* __restrict__ e2, long long sE1)
{
    extern __shared__ __align__(16) char smem[];
    const uint32_t sbase = smem_u32(smem);
    const int tid = threadIdx.x;
    const int wid = tid >> 5;
    const int lane = tid & 31;
    const int warp_m = wid & 1;        // 2 m-warps of 64 rows
    const int warp_n = wid >> 1;       // 4 n-warps of 32 cols
    const int bz = blockIdx.z;
    Ah += sA * bz;  Bh += sB * bz;
    if (C)  C  += sC * bz;
    if (Ch) Ch += sCh * bz;
    if (e1) e1 += sE1 * bz;
    if (e2) e2 += sC * bz;
    const int bm = blockIdx.y * BM;
    const int bn = blockIdx.x * BN;

    float acc[4][4][4];
#pragma unroll
    for (int i = 0; i < 4; i++)
#pragma unroll
        for (int j = 0; j < 4; j++)
#pragma unroll
            for (int v = 0; v < 4; v++) acc[i][j][v] = 0.f;

    const uint32_t a_base =
        ((uint32_t)(warp_m * 64 + (lane & 15)) * SROW + ((lane >> 4) * 8)) * 2;
    const uint32_t b_base = (uint32_t)A_HALVES * 2 +
        (((uint32_t)(warp_n * 32 + ((lane >> 4) & 1) * 8 + (lane & 7))) * SROW +
         (((lane >> 3) & 1) * 8)) * 2;

    const int ntiles = (K + BK - 1) / BK;

    auto load_stage = [&](int s, int t) {
        uint32_t sb = sbase + s * STAGE_B;
        int k0 = t * BK;
        // A: 128 rows x 8 chunks = 1024 cp16; B same
#pragma unroll
        for (int j = 0; j < 4; j++) {
            int idx = tid + j * 256;
            int r = idx >> 3, ch = idx & 7;
            int kc = k0 + ch * 8;
            int ab = 2 * (K - kc); ab = ab < 0 ? 0 : (ab > 16 ? 16 : ab);
            cp16(sb + (r * SROW + ch * 8) * 2, Ah + (long long)(bm + r) * lda + kc, ab);
        }
#pragma unroll
        for (int j = 0; j < 4; j++) {
            int idx = tid + j * 256;
            int r = idx >> 3, ch = idx & 7;
            int kc = k0 + ch * 8;
            int ab = 2 * (K - kc); ab = ab < 0 ? 0 : (ab > 16 ? 16 : ab);
            int gn = bn + r;
            int bb = (gn < N) ? ab : 0;
            cp16(sb + A_HALVES * 2 + (r * SROW + ch * 8) * 2,
                 Bh + (long long)(gn < N ? gn : 0) * ldb + kc, bb);
        }
    };

    load_stage(0, 0); CP_COMMIT();
    if (ntiles > 1) load_stage(1, 1);
    CP_COMMIT();

    for (int t = 0; t < ntiles; t++) {
        CP_WAIT(1);
        __syncthreads();
        int ls = t + NSTAGE - 1;
        if (ls < ntiles) load_stage(ls % NSTAGE, ls);
        CP_COMMIT();

        uint32_t sb = sbase + (t % NSTAGE) * STAGE_B;
#pragma unroll
        for (int kk = 0; kk < 4; kk++) {
            uint32_t a[4][4], b[2][4];
#pragma unroll
            for (int mi = 0; mi < 4; mi++)
                ldmx4(a[mi][0], a[mi][1], a[mi][2], a[mi][3],
                      sb + a_base + (uint32_t)(mi * 16 * SROW * 2) + kk * 32);
#pragma unroll
            for (int p = 0; p < 2; p++)
                ldmx4(b[p][0], b[p][1], b[p][2], b[p][3],
                      sb + b_base + (uint32_t)(p * 16 * SROW * 2) + kk * 32);
#pragma unroll
            for (int mi = 0; mi < 4; mi++)
#pragma unroll
                for (int nj = 0; nj < 4; nj++)
                    mma16816(acc[mi][nj], a[mi], b[nj >> 1][(nj & 1) * 2],
                             b[nj >> 1][(nj & 1) * 2 + 1]);
        }
    }
    CP_WAIT(0);
    __syncthreads();

    float* stg = (float*)smem;
    const int gID = lane >> 2, t4 = lane & 3;

    if (epi == 5) {
        // ---- fused silu(gate)*up: nj even = gate, nj odd = up ----
#pragma unroll
        for (int p = 0; p < 2; p++) {
            int bc = bn + warp_n * 32 + p * 16 + 2 * t4;
            float bg0 = bias[bc],     bg1 = bias[bc + 1];
            float bu0 = bias[bc + 8], bu1 = bias[bc + 9];
            int hc = warp_n * 16 + p * 8 + 2 * t4;
#pragma unroll
            for (int mi = 0; mi < 4; mi++) {
                int r0 = warp_m * 64 + mi * 16 + gID;
                float o0 = silu_f(acc[mi][2*p][0] + bg0) * (acc[mi][2*p+1][0] + bu0);
                float o1 = silu_f(acc[mi][2*p][1] + bg1) * (acc[mi][2*p+1][1] + bu1);
                float o2 = silu_f(acc[mi][2*p][2] + bg0) * (acc[mi][2*p+1][2] + bu0);
                float o3 = silu_f(acc[mi][2*p][3] + bg1) * (acc[mi][2*p+1][3] + bu1);
                stg[r0 * SSTG + hc]           = o0;
                stg[r0 * SSTG + hc + 1]       = o1;
                stg[(r0 + 8) * SSTG + hc]     = o2;
                stg[(r0 + 8) * SSTG + hc + 1] = o3;
            }
        }
        __syncthreads();
        int hbase = bn >> 1;
#pragma unroll 4
        for (int it = 0; it < 32; it++) {
            int idx = tid + it * 256;
            int r = idx >> 6, c = idx & 63;
            int hcol = hbase + c;
            if (hcol < HFF)
                Ch[(long long)(bm + r) * ldch + hcol] = __float2half(stg[r * SSTG + c]);
        }
        return;
    }

    // ---- generic: single 128-col pass via SMEM staging ----
#pragma unroll
    for (int mi = 0; mi < 4; mi++)
#pragma unroll
        for (int nj = 0; nj < 4; nj++) {
            int r0 = warp_m * 64 + mi * 16 + gID;
            int c0 = warp_n * 32 + nj * 8 + 2 * t4;
            stg[r0 * SSTG + c0]           = acc[mi][nj][0];
            stg[r0 * SSTG + c0 + 1]       = acc[mi][nj][1];
            stg[(r0 + 8) * SSTG + c0]     = acc[mi][nj][2];
            stg[(r0 + 8) * SSTG + c0 + 1] = acc[mi][nj][3];
        }
    __syncthreads();

    if (epi == 1 && bn >= D_MODEL) {
        // k or v region: transposed coalesced store to KT/VT
        int reg = bn >> 10;                        // 1=k, 2=v
        fp16* T = (reg == 1) ? KT : VT;
        int dbase = bn - reg * 1024;
        int b = bm >> 12, s0v = bm & 4095;
        fp16* Tb = T + (size_t)b * D_MODEL * SEQ + s0v;
#pragma unroll 4
        for (int it = 0; it < 64; it++) {
            int idx = tid + it * 256;
            int c = idx >> 7, r = idx & 127;
            int gn = bn + c;
            float tv = stg[r * SSTG + c] + (bias ? bias[gn] : 0.f);
            if (reg == 1) tv = (tv > 0.f) ? tv + 1.f : expf(tv);
            Tb[(size_t)(dbase + c) * SEQ + r] = __float2half(tv);
        }
    } else {
#pragma unroll 4
        for (int it = 0; it < 64; it++) {
            int idx = tid + it * 256;
            int r = idx >> 7, c = idx & 127;
            int gm = bm + r, gn = bn + c;
            if (gn < N) {
                float tv = stg[r * SSTG + c] + (bias ? bias[gn] : 0.f);
                long long ci = (long long)gm * ldc + gn;
                float outv;
                if (epi == 0) {
                    outv = tv;
                } else if (epi == 1) {         // q cols: elu+1
                    outv = (tv > 0.f) ? tv + 1.f : expf(tv);
                } else {                       // 2: residual + normalize
                    outv = e2[ci] + tv / (e1[gm] + ATTN_EPS_F);
                }
                if (C) C[ci] = outv;
                if (Ch && gn < colLim)
                    Ch[(long long)gm * ldch + gn] = __float2half(outv);
            }
        }
    }
}

// ===================== merged prep kernel ===================================
// One launch: x->fp16 convert + 4 weight transposes + bias interleave.
#define NB_CONV (MTOT * D_MODEL / 1024)   // 16384
#define GX_QKV  (D3 / 32)                 // 96
#define NB_QKV  (GX_QKV * (D_MODEL / 32)) // 3072
#define GX_GU   ((HFF + 31) / 32)         // 86
#define NB_GU   (GX_GU * (D_MODEL / 32))  // 2752
#define GX_WD   (D_MODEL / 32)            // 32
#define NB_WD   (GX_WD * ((HFF + 31) / 32)) // 2752
#define NB_BIAS ((HFF + 255) / 256)       // 11
#define NB_PREP (NB_CONV + NB_QKV + 2 * NB_GU + NB_WD + NB_BIAS)

__global__ void __launch_bounds__(256) prep_kernel(
    const float* __restrict__ x, const float* __restrict__ Wqkv,
    const float* __restrict__ Wg, const float* __restrict__ Wu,
    const float* __restrict__ Wd, const float* __restrict__ bg,
    const float* __restrict__ bu)
{
    __shared__ float tile[32][33];
    int b = blockIdx.x;
    int t = threadIdx.x;

    if (b < NB_CONV) {                    // x -> fp16
        int i = b * 1024 + t * 4;
        float4 v = *(const float4*)(x + i);
        *(__half2*)(g_xh + i)     = __floats2half2_rn(v.x, v.y);
        *(__half2*)(g_xh + i + 2) = __floats2half2_rn(v.z, v.w);
        return;
    }
    b -= NB_CONV;

    const float* in; fp16* oh;
    int R, Ccols, ldi, ldo, map, bx, by;
    if (b < NB_QKV) {
        in = Wqkv; oh = g_WqkvT; R = D_MODEL; Ccols = D3; ldi = D3; ldo = D_MODEL;
        map = 0; bx = b % GX_QKV; by = b / GX_QKV;
    } else if ((b -= NB_QKV) < NB_GU) {
        in = Wg; oh = g_WguT; R = D_MODEL; Ccols = HFF; ldi = HFF; ldo = D_MODEL;
        map = 1; bx = b % GX_GU; by = b / GX_GU;
    } else if ((b -= NB_GU) < NB_GU) {
        in = Wu; oh = g_WguT; R = D_MODEL; Ccols = HFF; ldi = HFF; ldo = D_MODEL;
        map = 2; bx = b % GX_GU; by = b / GX_GU;
    } else if ((b -= NB_GU) < NB_WD) {
        in = Wd; oh = g_WdT; R = HFF; Ccols = D_MODEL; ldi = D_MODEL; ldo = HFFP;
        map = 0; bx = b % GX_WD; by = b / GX_WD;
    } else {                              // bias interleave
        b -= NB_WD;
        int n = b * 256 + t;
        if (n < HFF) {
            int o = ((n >> 3) << 4) + (n & 7);
            g_bgu[o] = bg[n];
            g_bgu[o + 8] = bu[n];
        }
        return;
    }

    int r0 = by * 32, c0 = bx * 32;
    int tx = t & 31, ty = t >> 5;
#pragma unroll
    for (int i = 0; i < 32; i += 8) {
        int r = r0 + ty + i, c = c0 + tx;
        tile[ty + i][tx] = (r < R && c < Ccols) ? in[(long long)r * ldi + c] : 0.f;
    }
    __syncthreads();
#pragma unroll
    for (int i = 0; i < 32; i += 8) {
        int r = c0 + ty + i, c = r0 + tx;
        if (r < Ccols && c < R) {
            int rr = r;
            if (map) rr = ((r >> 3) << 4) + (r & 7) + (map == 2 ? 8 : 0);
            oh[(long long)rr * ldo + c] = __float2half(tile[tx][ty + i]);
        }
    }
}

// ===================== small kernels ========================================
__global__ void ksum_kernel() {
    int row = blockIdx.x * 8 + (threadIdx.x >> 5);
    int lane = threadIdx.x & 31;
    const __half2* p = (const __half2*)(g_kpT + (size_t)row * SEQ);
    float s = 0.f;
    for (int i = lane; i < SEQ / 2; i += 32) {
        float2 v = __half22float2(p[i]);
        s += v.x + v.y;
    }
#pragma unroll
    for (int o = 16; o > 0; o >>= 1) s += __shfl_xor_sync(0xffffffffu, s, o);
    if (lane == 0) g_ksum[row] = s;
}
__global__ void den_kernel() {
    int m = blockIdx.x * 8 + (threadIdx.x >> 5);
    int lane = threadIdx.x & 31;
    const __half2* q = (const __half2*)(g_qkvh + (size_t)m * D3);
    const float2* ks = (const float2*)(g_ksum + (m / SEQ) * D_MODEL);
    float s = 0.f;
    for (int d = lane; d < D_MODEL / 2; d += 32) {
        float2 qv = __half22float2(q[d]);
        float2 kv = ks[d];
        s += qv.x * kv.x + qv.y * kv.y;
    }
#pragma unroll
    for (int o = 16; o > 0; o >>= 1) s += __shfl_xor_sync(0xffffffffu, s, o);
    if (lane == 0) g_den[m] = s;
}
__global__ void ln_kernel(const float* __restrict__ in1, const float* __restrict__ in2,
                          const float* __restrict__ gamma, const float* __restrict__ beta,
                          float* __restrict__ out, fp16* __restrict__ oh)
{
    int row = blockIdx.x;
    int t = threadIdx.x;
    long long base4 = (long long)row * (D_MODEL / 4);
    float4 v4 = ((const float4*)in1)[base4 + t];
    if (in2) {
        float4 w4 = ((const float4*)in2)[base4 + t];
        v4.x += w4.x; v4.y += w4.y; v4.z += w4.z; v4.w += w4.w;
    }
    float s = v4.x + v4.y + v4.z + v4.w;
    __shared__ float red[256];
    red[t] = s; __syncthreads();
    for (int o = 128; o > 0; o >>= 1) { if (t < o) red[t] += red[t + o]; __syncthreads(); }
    float mu = red[0] * (1.f / D_MODEL);
    __syncthreads();
    float dx = v4.x - mu, dy = v4.y - mu, dz = v4.z - mu, dw = v4.w - mu;
    red[t] = dx * dx + dy * dy + dz * dz + dw * dw;
    __syncthreads();
    for (int o = 128; o > 0; o >>= 1) { if (t < o) red[t] += red[t + o]; __syncthreads(); }
    float inv = rsqrtf(red[0] * (1.f / D_MODEL) + LN_EPS_F);
    float4 g4 = ((const float4*)gamma)[t];
    float4 b4 = ((const float4*)beta)[t];
    float4 o4;
    o4.x = dx * inv * g4.x + b4.x;
    o4.y = dy * inv * g4.y + b4.y;
    o4.z = dz * inv * g4.z + b4.z;
    o4.w = dw * inv * g4.w + b4.w;
    ((float4*)out)[base4 + t] = o4;
    if (oh) {
        ((__half2*)oh)[base4 * 2 + 2 * t]     = __floats2half2_rn(o4.x, o4.y);
        ((__half2*)oh)[base4 * 2 + 2 * t + 1] = __floats2half2_rn(o4.z, o4.w);
    }
}

// ===================== launch ===============================================
extern "C" void kernel_launch(void* const* d_in, const int* in_sizes, int n_in,
                              void* d_out, int out_size)
{
    const float* x    = (const float*)d_in[0];
    const float* Wqkv = (const float*)d_in[1];
    const float* bqkv = (const float*)d_in[2];
    const float* Wg   = (const float*)d_in[3];
    const float* bg   = (const float*)d_in[4];
    const float* Wu   = (const float*)d_in[5];
    const float* bu   = (const float*)d_in[6];
    const float* Wd   = (const float*)d_in[7];
    const float* bd   = (const float*)d_in[8];
    const float* g1   = (const float*)d_in[9];
    const float* b1   = (const float*)d_in[10];
    const float* g2   = (const float*)d_in[11];
    const float* b2   = (const float*)d_in[12];
    float* out = (float*)d_out;

    float *den, *yb, *x1, *ffn, *bgu;
    fp16 *qkvh,*xh,*WqkvT,*WguT,*WdT,*kpT,*vT,*kvh,*x1h,*hh;
    cudaGetSymbolAddress((void**)&qkvh, g_qkvh);
    cudaGetSymbolAddress((void**)&den,  g_den);
    cudaGetSymbolAddress((void**)&yb,   g_y);
    cudaGetSymbolAddress((void**)&x1,   g_x1);
    cudaGetSymbolAddress((void**)&ffn,  g_ffn);
    cudaGetSymbolAddress((void**)&bgu,  g_bgu);
    cudaGetSymbolAddress((void**)&xh,   g_xh);
    cudaGetSymbolAddress((void**)&WqkvT,g_WqkvT);
    cudaGetSymbolAddress((void**)&WguT, g_WguT);
    cudaGetSymbolAddress((void**)&WdT,  g_WdT);
    cudaGetSymbolAddress((void**)&kpT,  g_kpT);
    cudaGetSymbolAddress((void**)&vT,   g_vT);
    cudaGetSymbolAddress((void**)&kvh,  g_kvh);
    cudaGetSymbolAddress((void**)&x1h,  g_x1h);
    cudaGetSymbolAddress((void**)&hh,   g_hh);

    cudaFuncSetAttribute(mma_gemm_kernel,
                         cudaFuncAttributeMaxDynamicSharedMemorySize, SMEM_SZ);

    dim3 blk(256);
    const long long SD3  = (long long)SEQ * D3;
    const long long SDM  = (long long)SEQ * D_MODEL;
    const long long DD   = (long long)D_MODEL * D_MODEL;
    const long long DS   = (long long)D_MODEL * SEQ;

    // ---- 0) merged prep: convert + transposes + bias interleave ----
    prep_kernel<<<NB_PREP, blk>>>(x, Wqkv, Wg, Wu, Wd, bg, bu);

    // ---- 1) qkv GEMM: q->qkvh (elu+1), k->kpT (elu+1, transposed), v->vT ----
    mma_gemm_kernel<<<dim3(D3/BN, MTOT/BM, 1), blk, SMEM_SZ>>>(
        xh, WqkvT, bqkv, nullptr, qkvh, kpT, vT,
        MTOT, D3, D_MODEL, D_MODEL, D_MODEL, D3, D3,
        0, 0, 0, 0, 1, D_MODEL, nullptr, nullptr, 0);

    // ---- ksum (rows of kpT), den ----
    ksum_kernel<<<512, blk>>>();
    den_kernel<<<MTOT/8, blk>>>();

    // ---- 2) kvh[e][d] = fp16(sum_s v[s,e] kp[s,d]) ----
    mma_gemm_kernel<<<dim3(D_MODEL/BN, D_MODEL/BM, BATCH), blk, SMEM_SZ>>>(
        vT, kpT, nullptr, nullptr, kvh, nullptr, nullptr,
        D_MODEL, D_MODEL, SEQ, SEQ, SEQ, D_MODEL, D_MODEL,
        DS, DS, DD, DD, 0, D_MODEL, nullptr, nullptr, 0);

    // ---- 3) y = x + (qp @ kv) / (den + eps)   (A = qkvh cols 0..1023) ----
    mma_gemm_kernel<<<dim3(D_MODEL/BN, SEQ/BM, BATCH), blk, SMEM_SZ>>>(
        qkvh, kvh, nullptr, yb, nullptr, nullptr, nullptr,
        SEQ, D_MODEL, D_MODEL, D3, D_MODEL, D_MODEL, D_MODEL,
        SD3, DD, SDM, 0, 2, 0, den, x, (long long)SEQ);

    // ---- 4) x1 = LN(y); fp16 fused ----
    ln_kernel<<<MTOT, blk>>>(yb, nullptr, g1, b1, x1, x1h);

    // ---- 5+6) hh = fp16(silu(x1@Wg+bg) * (x1@Wu+bu))  [one fused GEMM] ----
    mma_gemm_kernel<<<dim3((NGU+BN-1)/BN, MTOT/BM, 1), blk, SMEM_SZ>>>(
        x1h, WguT, bgu, nullptr, hh, nullptr, nullptr,
        MTOT, NGU, D_MODEL, D_MODEL, D_MODEL, NGU, HFFP,
        0, 0, 0, 0, 5, HFF, nullptr, nullptr, 0);

    // ---- 7) ffn = h @ Wd + bd ----
    mma_gemm_kernel<<<dim3(D_MODEL/BN, MTOT/BM, 1), blk, SMEM_SZ>>>(
        hh, WdT, bd, ffn, nullptr, nullptr, nullptr,
        MTOT, D_MODEL, HFF, HFFP, HFFP, D_MODEL, D_MODEL,
        0, 0, 0, 0, 0, 0, nullptr, nullptr, 0);

    // ---- 8) out = LN(x1 + ffn) ----
    ln_kernel<<<MTOT, blk>>>(x1, ffn, g2, b2, out, nullptr);
}

// round 11
// speedup vs baseline: 8.0774x; 1.0079x over previous
#include <cuda_runtime.h>
#include <cuda_fp16.h>
#include <cstdint>
#include <math.h>

#define D_MODEL 1024
#define D3      3072
#define HFF     2730
#define HFFP    2736                 // HFF padded to 8-element (16B) multiple
#define NGU     5472                 // interleaved gate/up N (2*2736)
#define BATCH   4
#define SEQ     4096
#define MTOT    (BATCH*SEQ)          // 16384

#define LN_EPS_F   1e-5f
#define ATTN_EPS_F 1e-6f

typedef __half fp16;

// ===================== scratch ==============================================
__device__ fp16  g_qkvh[(size_t)MTOT * D3];         // only q cols [0,1024) used
__device__ fp16  g_xh  [(size_t)MTOT * D_MODEL];
__device__ fp16  g_WqkvT[(size_t)D3 * D_MODEL];
__device__ fp16  g_WguT[(size_t)NGU * D_MODEL];     // interleaved gate/up rows (8-blocks)
__device__ float g_bgu [5632];                      // interleaved biases (zero padded)
__device__ fp16  g_WdT [(size_t)D_MODEL * HFFP];    // padded ld
__device__ fp16  g_kpT [(size_t)BATCH * D_MODEL * SEQ];
__device__ fp16  g_vT  [(size_t)BATCH * D_MODEL * SEQ];
__device__ fp16  g_kvh [(size_t)BATCH * D_MODEL * D_MODEL];
__device__ float g_ksum[BATCH * D_MODEL];
__device__ float g_den[MTOT];
__device__ float g_y [(size_t)MTOT * D_MODEL];      // x + attn (pre-LN1, fp32)
__device__ fp16  g_x1h[(size_t)MTOT * D_MODEL];     // LN1 out (fp16 only)
__device__ fp16  g_hh[(size_t)MTOT * HFFP];         // fused silu(gate)*up, padded ld
__device__ fp16  g_ffnh[(size_t)MTOT * D_MODEL];    // down-proj out (fp16)

// ===================== helpers ==============================================
__device__ __forceinline__ uint32_t smem_u32(const void* p) {
    uint32_t a;
    asm("{ .reg .u64 t; cvta.to.shared.u64 t, %1; cvt.u32.u64 %0, t; }" : "=r"(a) : "l"(p));
    return a;
}
__device__ __forceinline__ void cp16(uint32_t dst, const void* src, int bytes) {
    asm volatile("cp.async.cg.shared.global [%0], [%1], 16, %2;\n"
        :: "r"(dst), "l"(src), "r"(bytes));
}
#define CP_COMMIT() asm volatile("cp.async.commit_group;\n" ::: "memory")
#define CP_WAIT(n)  asm volatile("cp.async.wait_group %0;\n" :: "n"(n) : "memory")

__device__ __forceinline__ void ldmx4(uint32_t& r0, uint32_t& r1, uint32_t& r2,
                                      uint32_t& r3, uint32_t addr) {
    asm volatile("ldmatrix.sync.aligned.m8n8.x4.shared.b16 {%0,%1,%2,%3}, [%4];"
        : "=r"(r0), "=r"(r1), "=r"(r2), "=r"(r3) : "r"(addr));
}
__device__ __forceinline__ void mma16816(float* c, const uint32_t* a, uint32_t b0, uint32_t b1) {
    asm volatile(
        "mma.sync.aligned.m16n8k16.row.col.f32.f16.f16.f32 "
        "{%0,%1,%2,%3}, {%4,%5,%6,%7}, {%8,%9}, {%0,%1,%2,%3};"
        : "+f"(c[0]), "+f"(c[1]), "+f"(c[2]), "+f"(c[3])
        : "r"(a[0]), "r"(a[1]), "r"(a[2]), "r"(a[3]), "r"(b0), "r"(b1));
}
__device__ __forceinline__ float silu_f(float g) { return g / (1.f + expf(-g)); }

// ===================== mma.sync fp16 GEMM (fp32 accum) ======================
// C[m,n] = sum_k A[m,k] * Bt[n,k]  (fp16, Bt = B^T [N][K] row-major)
// BM=128, BN=128, BK=64. 8 warps: 2 m-warps x 4 n-warps, 64x32 warp tile.
// 2 CTAs/SM (regs <=128). 3-stage cp.async pipeline.
// epi: 0 plain(+bias); 1 qkv (q->qkvh elu+1, k->KT elu+1 transposed, v->VT);
//      2 residual+attn-div; 5 fused silu(gate)*up (interleaved B) -> Ch only.
#define BM 128
#define BN 128
#define BK 64
#define SROW 72                       // halves per smem row (64 + 8 pad)
#define A_HALVES (128 * SROW)         // 9216
#define B_HALVES (128 * SROW)         // 9216
#define STAGE_B ((A_HALVES + B_HALVES) * 2)   // 36864 bytes
#define NSTAGE 3
#define SMEM_SZ (NSTAGE * STAGE_B)    // 110592; epilogue staging 68096 fits
#define SSTG 133                      // staging stride (conflict-free transposed reads)

__global__ void __launch_bounds__(256, 2) mma_gemm_kernel(
    const fp16* __restrict__ Ah, const fp16* __restrict__ Bh,
    const float* __restrict__ bias, float* __restrict__ C,
    fp16* __restrict__ Ch, fp16* __restrict__ KT, fp16* __restrict__ VT,
    int M, int N, int K, int lda, int ldb, int ldc, int ldch,
    long long sA, long long sB, long long sC, long long sCh,
    int epi, int colLim,
    const float* __restrict__ e1, const float* __restrict__ e2, long long sE1)
{
    extern __shared__ __align__(16) char smem[];
    const uint32_t sbase = smem_u32(smem);
    const int tid = threadIdx.x;
    const int wid = tid >> 5;
    const int lane = tid & 31;
    const int warp_m = wid & 1;        // 2 m-warps of 64 rows
    const int warp_n = wid >> 1;       // 4 n-warps of 32 cols
    const int bz = blockIdx.z;
    Ah += sA * bz;  Bh += sB * bz;
    if (C)  C  += sC * bz;
    if (Ch) Ch += sCh * bz;
    if (e1) e1 += sE1 * bz;
    if (e2) e2 += sC * bz;
    const int bm = blockIdx.y * BM;
    const int bn = blockIdx.x * BN;

    float acc[4][4][4];
#pragma unroll
    for (int i = 0; i < 4; i++)
#pragma unroll
        for (int j = 0; j < 4; j++)
#pragma unroll
            for (int v = 0; v < 4; v++) acc[i][j][v] = 0.f;

    const uint32_t a_base =
        ((uint32_t)(warp_m * 64 + (lane & 15)) * SROW + ((lane >> 4) * 8)) * 2;
    const uint32_t b_base = (uint32_t)A_HALVES * 2 +
        (((uint32_t)(warp_n * 32 + ((lane >> 4) & 1) * 8 + (lane & 7))) * SROW +
         (((lane >> 3) & 1) * 8)) * 2;

    const int ntiles = (K + BK - 1) / BK;

    auto load_stage = [&](int s, int t) {
        uint32_t sb = sbase + s * STAGE_B;
        int k0 = t * BK;
#pragma unroll
        for (int j = 0; j < 4; j++) {
            int idx = tid + j * 256;
            int r = idx >> 3, ch = idx & 7;
            int kc = k0 + ch * 8;
            int ab = 2 * (K - kc); ab = ab < 0 ? 0 : (ab > 16 ? 16 : ab);
            cp16(sb + (r * SROW + ch * 8) * 2, Ah + (long long)(bm + r) * lda + kc, ab);
        }
#pragma unroll
        for (int j = 0; j < 4; j++) {
            int idx = tid + j * 256;
            int r = idx >> 3, ch = idx & 7;
            int kc = k0 + ch * 8;
            int ab = 2 * (K - kc); ab = ab < 0 ? 0 : (ab > 16 ? 16 : ab);
            int gn = bn + r;
            int bb = (gn < N) ? ab : 0;
            cp16(sb + A_HALVES * 2 + (r * SROW + ch * 8) * 2,
                 Bh + (long long)(gn < N ? gn : 0) * ldb + kc, bb);
        }
    };

    load_stage(0, 0); CP_COMMIT();
    if (ntiles > 1) load_stage(1, 1);
    CP_COMMIT();

    for (int t = 0; t < ntiles; t++) {
        CP_WAIT(1);
        __syncthreads();
        int ls = t + NSTAGE - 1;
        if (ls < ntiles) load_stage(ls % NSTAGE, ls);
        CP_COMMIT();

        uint32_t sb = sbase + (t % NSTAGE) * STAGE_B;
#pragma unroll
        for (int kk = 0; kk < 4; kk++) {
            uint32_t a[4][4], b[2][4];
#pragma unroll
            for (int mi = 0; mi < 4; mi++)
                ldmx4(a[mi][0], a[mi][1], a[mi][2], a[mi][3],
                      sb + a_base + (uint32_t)(mi * 16 * SROW * 2) + kk * 32);
#pragma unroll
            for (int p = 0; p < 2; p++)
                ldmx4(b[p][0], b[p][1], b[p][2], b[p][3],
                      sb + b_base + (uint32_t)(p * 16 * SROW * 2) + kk * 32);
#pragma unroll
            for (int mi = 0; mi < 4; mi++)
#pragma unroll
                for (int nj = 0; nj < 4; nj++)
                    mma16816(acc[mi][nj], a[mi], b[nj >> 1][(nj & 1) * 2],
                             b[nj >> 1][(nj & 1) * 2 + 1]);
        }
    }
    CP_WAIT(0);
    __syncthreads();

    float* stg = (float*)smem;
    const int gID = lane >> 2, t4 = lane & 3;

    if (epi == 5) {
        // ---- fused silu(gate)*up: nj even = gate, nj odd = up ----
#pragma unroll
        for (int p = 0; p < 2; p++) {
            int bc = bn + warp_n * 32 + p * 16 + 2 * t4;
            float bg0 = bias[bc],     bg1 = bias[bc + 1];
            float bu0 = bias[bc + 8], bu1 = bias[bc + 9];
            int hc = warp_n * 16 + p * 8 + 2 * t4;
#pragma unroll
            for (int mi = 0; mi < 4; mi++) {
                int r0 = warp_m * 64 + mi * 16 + gID;
                float o0 = silu_f(acc[mi][2*p][0] + bg0) * (acc[mi][2*p+1][0] + bu0);
                float o1 = silu_f(acc[mi][2*p][1] + bg1) * (acc[mi][2*p+1][1] + bu1);
                float o2 = silu_f(acc[mi][2*p][2] + bg0) * (acc[mi][2*p+1][2] + bu0);
                float o3 = silu_f(acc[mi][2*p][3] + bg1) * (acc[mi][2*p+1][3] + bu1);
                stg[r0 * SSTG + hc]           = o0;
                stg[r0 * SSTG + hc + 1]       = o1;
                stg[(r0 + 8) * SSTG + hc]     = o2;
                stg[(r0 + 8) * SSTG + hc + 1] = o3;
            }
        }
        __syncthreads();
        int hbase = bn >> 1;
#pragma unroll 4
        for (int it = 0; it < 32; it++) {
            int idx = tid + it * 256;
            int r = idx >> 6, c = idx & 63;
            int hcol = hbase + c;
            if (hcol < HFF)
                Ch[(long long)(bm + r) * ldch + hcol] = __float2half(stg[r * SSTG + c]);
        }
        return;
    }

    // ---- generic: single 128-col pass via SMEM staging ----
#pragma unroll
    for (int mi = 0; mi < 4; mi++)
#pragma unroll
        for (int nj = 0; nj < 4; nj++) {
            int r0 = warp_m * 64 + mi * 16 + gID;
            int c0 = warp_n * 32 + nj * 8 + 2 * t4;
            stg[r0 * SSTG + c0]           = acc[mi][nj][0];
            stg[r0 * SSTG + c0 + 1]       = acc[mi][nj][1];
            stg[(r0 + 8) * SSTG + c0]     = acc[mi][nj][2];
            stg[(r0 + 8) * SSTG + c0 + 1] = acc[mi][nj][3];
        }
    __syncthreads();

    if (epi == 1 && bn >= D_MODEL) {
        // k or v region: transposed coalesced store to KT/VT
        int reg = bn >> 10;                        // 1=k, 2=v
        fp16* T = (reg == 1) ? KT : VT;
        int dbase = bn - reg * 1024;
        int b = bm >> 12, s0v = bm & 4095;
        fp16* Tb = T + (size_t)b * D_MODEL * SEQ + s0v;
#pragma unroll 4
        for (int it = 0; it < 64; it++) {
            int idx = tid + it * 256;
            int c = idx >> 7, r = idx & 127;
            int gn = bn + c;
            float tv = stg[r * SSTG + c] + (bias ? bias[gn] : 0.f);
            if (reg == 1) tv = (tv > 0.f) ? tv + 1.f : expf(tv);
            Tb[(size_t)(dbase + c) * SEQ + r] = __float2half(tv);
        }
    } else {
#pragma unroll 4
        for (int it = 0; it < 64; it++) {
            int idx = tid + it * 256;
            int r = idx >> 7, c = idx & 127;
            int gm = bm + r, gn = bn + c;
            if (gn < N) {
                float tv = stg[r * SSTG + c] + (bias ? bias[gn] : 0.f);
                long long ci = (long long)gm * ldc + gn;
                float outv;
                if (epi == 0) {
                    outv = tv;
                } else if (epi == 1) {         // q cols: elu+1
                    outv = (tv > 0.f) ? tv + 1.f : expf(tv);
                } else {                       // 2: residual + normalize
                    outv = e2[ci] + tv / (e1[gm] + ATTN_EPS_F);
                }
                if (C) C[ci] = outv;
                if (Ch && gn < colLim)
                    Ch[(long long)gm * ldch + gn] = __float2half(outv);
            }
        }
    }
}

// ===================== merged prep kernel ===================================
#define NB_CONV (MTOT * D_MODEL / 1024)   // 16384
#define GX_QKV  (D3 / 32)                 // 96
#define NB_QKV  (GX_QKV * (D_MODEL / 32)) // 3072
#define GX_GU   ((HFF + 31) / 32)         // 86
#define NB_GU   (GX_GU * (D_MODEL / 32))  // 2752
#define GX_WD   (D_MODEL / 32)            // 32
#define NB_WD   (GX_WD * ((HFF + 31) / 32)) // 2752
#define NB_BIAS ((HFF + 255) / 256)       // 11
#define NB_PREP (NB_CONV + NB_QKV + 2 * NB_GU + NB_WD + NB_BIAS)

__global__ void __launch_bounds__(256) prep_kernel(
    const float* __restrict__ x, const float* __restrict__ Wqkv,
    const float* __restrict__ Wg, const float* __restrict__ Wu,
    const float* __restrict__ Wd, const float* __restrict__ bg,
    const float* __restrict__ bu)
{
    __shared__ float tile[32][33];
    int b = blockIdx.x;
    int t = threadIdx.x;

    if (b < NB_CONV) {                    // x -> fp16
        int i = b * 1024 + t * 4;
        float4 v = *(const float4*)(x + i);
        *(__half2*)(g_xh + i)     = __floats2half2_rn(v.x, v.y);
        *(__half2*)(g_xh + i + 2) = __floats2half2_rn(v.z, v.w);
        return;
    }
    b -= NB_CONV;

    const float* in; fp16* oh;
    int R, Ccols, ldi, ldo, map, bx, by;
    if (b < NB_QKV) {
        in = Wqkv; oh = g_WqkvT; R = D_MODEL; Ccols = D3; ldi = D3; ldo = D_MODEL;
        map = 0; bx = b % GX_QKV; by = b / GX_QKV;
    } else if ((b -= NB_QKV) < NB_GU) {
        in = Wg; oh = g_WguT; R = D_MODEL; Ccols = HFF; ldi = HFF; ldo = D_MODEL;
        map = 1; bx = b % GX_GU; by = b / GX_GU;
    } else if ((b -= NB_GU) < NB_GU) {
        in = Wu; oh = g_WguT; R = D_MODEL; Ccols = HFF; ldi = HFF; ldo = D_MODEL;
        map = 2; bx = b % GX_GU; by = b / GX_GU;
    } else if ((b -= NB_GU) < NB_WD) {
        in = Wd; oh = g_WdT; R = HFF; Ccols = D_MODEL; ldi = D_MODEL; ldo = HFFP;
        map = 0; bx = b % GX_WD; by = b / GX_WD;
    } else {                              // bias interleave
        b -= NB_WD;
        int n = b * 256 + t;
        if (n < HFF) {
            int o = ((n >> 3) << 4) + (n & 7);
            g_bgu[o] = bg[n];
            g_bgu[o + 8] = bu[n];
        }
        return;
    }

    int r0 = by * 32, c0 = bx * 32;
    int tx = t & 31, ty = t >> 5;
#pragma unroll
    for (int i = 0; i < 32; i += 8) {
        int r = r0 + ty + i, c = c0 + tx;
        tile[ty + i][tx] = (r < R && c < Ccols) ? in[(long long)r * ldi + c] : 0.f;
    }
    __syncthreads();
#pragma unroll
    for (int i = 0; i < 32; i += 8) {
        int r = c0 + ty + i, c = r0 + tx;
        if (r < Ccols && c < R) {
            int rr = r;
            if (map) rr = ((r >> 3) << 4) + (r & 7) + (map == 2 ? 8 : 0);
            oh[(long long)rr * ldo + c] = __float2half(tile[tx][ty + i]);
        }
    }
}

// ===================== small kernels ========================================
__global__ void ksum_kernel() {
    int row = blockIdx.x * 8 + (threadIdx.x >> 5);
    int lane = threadIdx.x & 31;
    const uint4* p = (const uint4*)(g_kpT + (size_t)row * SEQ);
    float s = 0.f;
#pragma unroll 4
    for (int i = lane; i < SEQ / 8; i += 32) {      // 16 iters, 16B loads
        uint4 v = p[i];
        float2 a0 = __half22float2(*(__half2*)&v.x);
        float2 a1 = __half22float2(*(__half2*)&v.y);
        float2 a2 = __half22float2(*(__half2*)&v.z);
        float2 a3 = __half22float2(*(__half2*)&v.w);
        s += (a0.x + a0.y) + (a1.x + a1.y) + (a2.x + a2.y) + (a3.x + a3.y);
    }
#pragma unroll
    for (int o = 16; o > 0; o >>= 1) s += __shfl_xor_sync(0xffffffffu, s, o);
    if (lane == 0) g_ksum[row] = s;
}
__global__ void den_kernel() {
    int m = blockIdx.x * 8 + (threadIdx.x >> 5);
    int lane = threadIdx.x & 31;
    const uint4* q = (const uint4*)(g_qkvh + (size_t)m * D3);   // q cols 0..1023
    const float4* ks = (const float4*)(g_ksum + (m / SEQ) * D_MODEL);
    float s = 0.f;
#pragma unroll
    for (int d = lane; d < D_MODEL / 8; d += 32) {  // 4 iters, 16B loads
        uint4 qv = q[d];
        float4 k0 = ks[2 * d], k1 = ks[2 * d + 1];
        float2 q0 = __half22float2(*(__half2*)&qv.x);
        float2 q1 = __half22float2(*(__half2*)&qv.y);
        float2 q2 = __half22float2(*(__half2*)&qv.z);
        float2 q3 = __half22float2(*(__half2*)&qv.w);
        s += q0.x * k0.x + q0.y * k0.y + q1.x * k0.z + q1.y * k0.w
           + q2.x * k1.x + q2.y * k1.y + q3.x * k1.z + q3.y * k1.w;
    }
#pragma unroll
    for (int o = 16; o > 0; o >>= 1) s += __shfl_xor_sync(0xffffffffu, s, o);
    if (lane == 0) g_den[m] = s;
}
// LN1: fp32 in -> fp16 out only
__global__ void ln1_kernel(const float* __restrict__ in1,
                           const float* __restrict__ gamma, const float* __restrict__ beta,
                           fp16* __restrict__ oh)
{
    int row = blockIdx.x;
    int t = threadIdx.x;
    long long base4 = (long long)row * (D_MODEL / 4);
    float4 v4 = ((const float4*)in1)[base4 + t];
    float s = v4.x + v4.y + v4.z + v4.w;
    __shared__ float red[256];
    red[t] = s; __syncthreads();
    for (int o = 128; o > 0; o >>= 1) { if (t < o) red[t] += red[t + o]; __syncthreads(); }
    float mu = red[0] * (1.f / D_MODEL);
    __syncthreads();
    float dx = v4.x - mu, dy = v4.y - mu, dz = v4.z - mu, dw = v4.w - mu;
    red[t] = dx * dx + dy * dy + dz * dz + dw * dw;
    __syncthreads();
    for (int o = 128; o > 0; o >>= 1) { if (t < o) red[t] += red[t + o]; __syncthreads(); }
    float inv = rsqrtf(red[0] * (1.f / D_MODEL) + LN_EPS_F);
    float4 g4 = ((const float4*)gamma)[t];
    float4 b4 = ((const float4*)beta)[t];
    ((__half2*)oh)[base4 * 2 + 2 * t] =
        __floats2half2_rn(dx * inv * g4.x + b4.x, dy * inv * g4.y + b4.y);
    ((__half2*)oh)[base4 * 2 + 2 * t + 1] =
        __floats2half2_rn(dz * inv * g4.z + b4.z, dw * inv * g4.w + b4.w);
}
// LN2: (fp16 in1 + fp16 in2) -> fp32 out
__global__ void ln2_kernel(const fp16* __restrict__ in1, const fp16* __restrict__ in2,
                           const float* __restrict__ gamma, const float* __restrict__ beta,
                           float* __restrict__ out)
{
    int row = blockIdx.x;
    int t = threadIdx.x;
    long long base2 = (long long)row * (D_MODEL / 2);
    float2 a0 = __half22float2(((const __half2*)in1)[base2 + 2 * t]);
    float2 a1 = __half22float2(((const __half2*)in1)[base2 + 2 * t + 1]);
    float2 c0 = __half22float2(((const __half2*)in2)[base2 + 2 * t]);
    float2 c1 = __half22float2(((const __half2*)in2)[base2 + 2 * t + 1]);
    float4 v4;
    v4.x = a0.x + c0.x; v4.y = a0.y + c0.y;
    v4.z = a1.x + c1.x; v4.w = a1.y + c1.y;
    float s = v4.x + v4.y + v4.z + v4.w;
    __shared__ float red[256];
    red[t] = s; __syncthreads();
    for (int o = 128; o > 0; o >>= 1) { if (t < o) red[t] += red[t + o]; __syncthreads(); }
    float mu = red[0] * (1.f / D_MODEL);
    __syncthreads();
    float dx = v4.x - mu, dy = v4.y - mu, dz = v4.z - mu, dw = v4.w - mu;
    red[t] = dx * dx + dy * dy + dz * dz + dw * dw;
    __syncthreads();
    for (int o = 128; o > 0; o >>= 1) { if (t < o) red[t] += red[t + o]; __syncthreads(); }
    float inv = rsqrtf(red[0] * (1.f / D_MODEL) + LN_EPS_F);
    float4 g4 = ((const float4*)gamma)[t];
    float4 b4 = ((const float4*)beta)[t];
    float4 o4;
    o4.x = dx * inv * g4.x + b4.x;
    o4.y = dy * inv * g4.y + b4.y;
    o4.z = dz * inv * g4.z + b4.z;
    o4.w = dw * inv * g4.w + b4.w;
    ((float4*)out)[(long long)row * (D_MODEL / 4) + t] = o4;
}

// ===================== launch ===============================================
extern "C" void kernel_launch(void* const* d_in, const int* in_sizes, int n_in,
                              void* d_out, int out_size)
{
    const float* x    = (const float*)d_in[0];
    const float* Wqkv = (const float*)d_in[1];
    const float* bqkv = (const float*)d_in[2];
    const float* Wg   = (const float*)d_in[3];
    const float* bg   = (const float*)d_in[4];
    const float* Wu   = (const float*)d_in[5];
    const float* bu   = (const float*)d_in[6];
    const float* Wd   = (const float*)d_in[7];
    const float* bd   = (const float*)d_in[8];
    const float* g1   = (const float*)d_in[9];
    const float* b1   = (const float*)d_in[10];
    const float* g2   = (const float*)d_in[11];
    const float* b2   = (const float*)d_in[12];
    float* out = (float*)d_out;

    float *den, *yb, *bgu;
    fp16 *qkvh,*xh,*WqkvT,*WguT,*WdT,*kpT,*vT,*kvh,*x1h,*hh,*ffnh;
    cudaGetSymbolAddress((void**)&qkvh, g_qkvh);
    cudaGetSymbolAddress((void**)&den,  g_den);
    cudaGetSymbolAddress((void**)&yb,   g_y);
    cudaGetSymbolAddress((void**)&bgu,  g_bgu);
    cudaGetSymbolAddress((void**)&xh,   g_xh);
    cudaGetSymbolAddress((void**)&WqkvT,g_WqkvT);
    cudaGetSymbolAddress((void**)&WguT, g_WguT);
    cudaGetSymbolAddress((void**)&WdT,  g_WdT);
    cudaGetSymbolAddress((void**)&kpT,  g_kpT);
    cudaGetSymbolAddress((void**)&vT,   g_vT);
    cudaGetSymbolAddress((void**)&kvh,  g_kvh);
    cudaGetSymbolAddress((void**)&x1h,  g_x1h);
    cudaGetSymbolAddress((void**)&hh,   g_hh);
    cudaGetSymbolAddress((void**)&ffnh, g_ffnh);

    cudaFuncSetAttribute(mma_gemm_kernel,
                         cudaFuncAttributeMaxDynamicSharedMemorySize, SMEM_SZ);

    dim3 blk(256);
    const long long SD3  = (long long)SEQ * D3;
    const long long SDM  = (long long)SEQ * D_MODEL;
    const long long DD   = (long long)D_MODEL * D_MODEL;
    const long long DS   = (long long)D_MODEL * SEQ;

    // ---- 0) merged prep: convert + transposes + bias interleave ----
    prep_kernel<<<NB_PREP, blk>>>(x, Wqkv, Wg, Wu, Wd, bg, bu);

    // ---- 1) qkv GEMM: q->qkvh (elu+1), k->kpT (elu+1, transposed), v->vT ----
    mma_gemm_kernel<<<dim3(D3/BN, MTOT/BM, 1), blk, SMEM_SZ>>>(
        xh, WqkvT, bqkv, nullptr, qkvh, kpT, vT,
        MTOT, D3, D_MODEL, D_MODEL, D_MODEL, D3, D3,
        0, 0, 0, 0, 1, D_MODEL, nullptr, nullptr, 0);

    // ---- ksum (rows of kpT), den ----
    ksum_kernel<<<512, blk>>>();
    den_kernel<<<MTOT/8, blk>>>();

    // ---- 2) kvh[e][d] = fp16(sum_s v[s,e] kp[s,d]) ----
    mma_gemm_kernel<<<dim3(D_MODEL/BN, D_MODEL/BM, BATCH), blk, SMEM_SZ>>>(
        vT, kpT, nullptr, nullptr, kvh, nullptr, nullptr,
        D_MODEL, D_MODEL, SEQ, SEQ, SEQ, D_MODEL, D_MODEL,
        DS, DS, DD, DD, 0, D_MODEL, nullptr, nullptr, 0);

    // ---- 3) y = x + (qp @ kv) / (den + eps)   (A = qkvh cols 0..1023) ----
    mma_gemm_kernel<<<dim3(D_MODEL/BN, SEQ/BM, BATCH), blk, SMEM_SZ>>>(
        qkvh, kvh, nullptr, yb, nullptr, nullptr, nullptr,
        SEQ, D_MODEL, D_MODEL, D3, D_MODEL, D_MODEL, D_MODEL,
        SD3, DD, SDM, 0, 2, 0, den, x, (long long)SEQ);

    // ---- 4) x1h = fp16(LN(y)) ----
    ln1_kernel<<<MTOT, blk>>>(yb, g1, b1, x1h);

    // ---- 5+6) hh = fp16(silu(x1@Wg+bg) * (x1@Wu+bu))  [one fused GEMM] ----
    mma_gemm_kernel<<<dim3((NGU+BN-1)/BN, MTOT/BM, 1), blk, SMEM_SZ>>>(
        x1h, WguT, bgu, nullptr, hh, nullptr, nullptr,
        MTOT, NGU, D_MODEL, D_MODEL, D_MODEL, NGU, HFFP,
        0, 0, 0, 0, 5, HFF, nullptr, nullptr, 0);

    // ---- 7) ffnh = fp16(h @ Wd + bd) ----
    mma_gemm_kernel<<<dim3(D_MODEL/BN, MTOT/BM, 1), blk, SMEM_SZ>>>(
        hh, WdT, bd, nullptr, ffnh, nullptr, nullptr,
        MTOT, D_MODEL, HFF, HFFP, HFFP, D_MODEL, D_MODEL,
        0, 0, 0, 0, 0, D_MODEL, nullptr, nullptr, 0);

    // ---- 8) out = LN(x1h + ffnh) ----
    ln2_kernel<<<MTOT, blk>>>(x1h, ffnh, g2, b2, out);
}

// round 12
// speedup vs baseline: 8.2733x; 1.0243x over previous
#include <cuda_runtime.h>
#include <cuda_fp16.h>
#include <cstdint>
#include <math.h>

#define D_MODEL 1024
#define D3      3072
#define HFF     2730
#define HFFP    2736                 // HFF padded to 8-element (16B) multiple
#define NGU     5472                 // interleaved gate/up N (2*2736)
#define BATCH   4
#define SEQ     4096
#define MTOT    (BATCH*SEQ)          // 16384

#define LN_EPS_F   1e-5f
#define ATTN_EPS_F 1e-6f

typedef __half fp16;

// ===================== scratch ==============================================
__device__ fp16  g_qkvh[(size_t)MTOT * D3];         // only q cols [0,1024) used
__device__ fp16  g_xh  [(size_t)MTOT * D_MODEL];
__device__ fp16  g_WqkvT[(size_t)D3 * D_MODEL];
__device__ fp16  g_WguT[(size_t)NGU * D_MODEL];     // interleaved gate/up rows (8-blocks)
__device__ float g_bgu [5632];                      // interleaved biases (zero padded)
__device__ fp16  g_WdT [(size_t)D_MODEL * HFFP];    // padded ld
__device__ fp16  g_kpT [(size_t)BATCH * D_MODEL * SEQ];
__device__ fp16  g_vT  [(size_t)BATCH * D_MODEL * SEQ];
__device__ fp16  g_kvh [(size_t)BATCH * D_MODEL * D_MODEL];
__device__ float g_ksum[BATCH * D_MODEL];
__device__ float g_y [(size_t)MTOT * D_MODEL];      // x + attn (pre-LN1, fp32)
__device__ fp16  g_x1h[(size_t)MTOT * D_MODEL];     // LN1 out (fp16 only)
__device__ fp16  g_hh[(size_t)MTOT * HFFP];         // fused silu(gate)*up, padded ld
__device__ fp16  g_ffnh[(size_t)MTOT * D_MODEL];    // down-proj out (fp16)

// ===================== helpers ==============================================
__device__ __forceinline__ uint32_t smem_u32(const void* p) {
    uint32_t a;
    asm("{ .reg .u64 t; cvta.to.shared.u64 t, %1; cvt.u32.u64 %0, t; }" : "=r"(a) : "l"(p));
    return a;
}
__device__ __forceinline__ void cp16(uint32_t dst, const void* src, int bytes) {
    asm volatile("cp.async.cg.shared.global [%0], [%1], 16, %2;\n"
        :: "r"(dst), "l"(src), "r"(bytes));
}
#define CP_COMMIT() asm volatile("cp.async.commit_group;\n" ::: "memory")
#define CP_WAIT(n)  asm volatile("cp.async.wait_group %0;\n" :: "n"(n) : "memory")

__device__ __forceinline__ void ldmx4(uint32_t& r0, uint32_t& r1, uint32_t& r2,
                                      uint32_t& r3, uint32_t addr) {
    asm volatile("ldmatrix.sync.aligned.m8n8.x4.shared.b16 {%0,%1,%2,%3}, [%4];"
        : "=r"(r0), "=r"(r1), "=r"(r2), "=r"(r3) : "r"(addr));
}
__device__ __forceinline__ void mma16816(float* c, const uint32_t* a, uint32_t b0, uint32_t b1) {
    asm volatile(
        "mma.sync.aligned.m16n8k16.row.col.f32.f16.f16.f32 "
        "{%0,%1,%2,%3}, {%4,%5,%6,%7}, {%8,%9}, {%0,%1,%2,%3};"
        : "+f"(c[0]), "+f"(c[1]), "+f"(c[2]), "+f"(c[3])
        : "r"(a[0]), "r"(a[1]), "r"(a[2]), "r"(a[3]), "r"(b0), "r"(b1));
}
__device__ __forceinline__ float silu_f(float g) { return g / (1.f + expf(-g)); }

// ===================== mma.sync fp16 GEMM (fp32 accum) ======================
// C[m,n] = sum_k A[m,k] * Bt[n,k]  (fp16, Bt = B^T [N][K] row-major)
// BM=128, BN=128, BK=64. 8 warps: 2 m-warps x 4 n-warps, 64x32 warp tile.
// 2 CTAs/SM (regs <=128). 3-stage cp.async pipeline.
// epi: 0 plain(+bias); 1 qkv (q->qkvh elu+1, k->KT elu+1 transposed, v->VT);
//      2 residual+attn-div (den computed in-prologue from e1=ksum);
//      5 fused silu(gate)*up (interleaved B) -> Ch only;
//      6 like 0, plus by==0 CTAs write ksum of B rows into (float*)e1.
#define BM 128
#define BN 128
#define BK 64
#define SROW 72                       // halves per smem row (64 + 8 pad)
#define A_HALVES (128 * SROW)         // 9216
#define B_HALVES (128 * SROW)         // 9216
#define STAGE_B ((A_HALVES + B_HALVES) * 2)   // 36864 bytes
#define NSTAGE 3
#define SMEM_SZ (NSTAGE * STAGE_B)    // 110592; epilogue staging 68096 fits
#define SMEM_SZ_DEN (SMEM_SZ + 512)   // +128 floats den scratch (epi 2)
#define SSTG 133                      // staging stride (conflict-free transposed reads)

__global__ void __launch_bounds__(256, 2) mma_gemm_kernel(
    const fp16* __restrict__ Ah, const fp16* __restrict__ Bh,
    const float* __restrict__ bias, float* __restrict__ C,
    fp16* __restrict__ Ch, fp16* __restrict__ KT, fp16* __restrict__ VT,
    int M, int N, int K, int lda, int ldb, int ldc, int ldch,
    long long sA, long long sB, long long sC, long long sCh,
    int epi, int colLim,
    const float* __restrict__ e1, const float* __restrict__ e2, long long sE1)
{
    extern __shared__ __align__(16) char smem[];
    const uint32_t sbase = smem_u32(smem);
    const int tid = threadIdx.x;
    const int wid = tid >> 5;
    const int lane = tid & 31;
    const int warp_m = wid & 1;        // 2 m-warps of 64 rows
    const int warp_n = wid >> 1;       // 4 n-warps of 32 cols
    const int bz = blockIdx.z;
    Ah += sA * bz;  Bh += sB * bz;
    if (C)  C  += sC * bz;
    if (Ch) Ch += sCh * bz;
    if (e1) e1 += sE1 * bz;
    if (e2) e2 += sC * bz;
    const int bm = blockIdx.y * BM;
    const int bn = blockIdx.x * BN;

    float acc[4][4][4];
#pragma unroll
    for (int i = 0; i < 4; i++)
#pragma unroll
        for (int j = 0; j < 4; j++)
#pragma unroll
            for (int v = 0; v < 4; v++) acc[i][j][v] = 0.f;

    const uint32_t a_base =
        ((uint32_t)(warp_m * 64 + (lane & 15)) * SROW + ((lane >> 4) * 8)) * 2;
    const uint32_t b_base = (uint32_t)A_HALVES * 2 +
        (((uint32_t)(warp_n * 32 + ((lane >> 4) & 1) * 8 + (lane & 7))) * SROW +
         (((lane >> 3) & 1) * 8)) * 2;

    const int ntiles = (K + BK - 1) / BK;

    auto load_stage = [&](int s, int t) {
        uint32_t sb = sbase + s * STAGE_B;
        int k0 = t * BK;
#pragma unroll
        for (int j = 0; j < 4; j++) {
            int idx = tid + j * 256;
            int r = idx >> 3, ch = idx & 7;
            int kc = k0 + ch * 8;
            int ab = 2 * (K - kc); ab = ab < 0 ? 0 : (ab > 16 ? 16 : ab);
            cp16(sb + (r * SROW + ch * 8) * 2, Ah + (long long)(bm + r) * lda + kc, ab);
        }
#pragma unroll
        for (int j = 0; j < 4; j++) {
            int idx = tid + j * 256;
            int r = idx >> 3, ch = idx & 7;
            int kc = k0 + ch * 8;
            int ab = 2 * (K - kc); ab = ab < 0 ? 0 : (ab > 16 ? 16 : ab);
            int gn = bn + r;
            int bb = (gn < N) ? ab : 0;
            cp16(sb + A_HALVES * 2 + (r * SROW + ch * 8) * 2,
                 Bh + (long long)(gn < N ? gn : 0) * ldb + kc, bb);
        }
    };

    load_stage(0, 0); CP_COMMIT();
    if (ntiles > 1) load_stage(1, 1);
    CP_COMMIT();

    // ---- fused prologues (overlap the first prefetches' latency) ----
    float* den_s = (float*)(smem + SMEM_SZ);
    if (epi == 2) {
        // den_s[r] = dot(qp[bm+r, :], ksum[:])  (e1 = ksum, D_MODEL floats)
        const float4* ks4 = (const float4*)e1;
#pragma unroll 2
        for (int rr = 0; rr < 16; rr++) {
            int r = rr * 8 + wid;
            const uint4* q = (const uint4*)(Ah + (long long)(bm + r) * lda);
            float s = 0.f;
#pragma unroll
            for (int d = lane; d < D_MODEL / 8; d += 32) {
                uint4 qv = q[d];
                float4 k0 = ks4[2 * d], k1 = ks4[2 * d + 1];
                float2 q0 = __half22float2(*(__half2*)&qv.x);
                float2 q1 = __half22float2(*(__half2*)&qv.y);
                float2 q2 = __half22float2(*(__half2*)&qv.z);
                float2 q3 = __half22float2(*(__half2*)&qv.w);
                s += q0.x * k0.x + q0.y * k0.y + q1.x * k0.z + q1.y * k0.w
                   + q2.x * k1.x + q2.y * k1.y + q3.x * k1.z + q3.y * k1.w;
            }
#pragma unroll
            for (int o = 16; o > 0; o >>= 1) s += __shfl_xor_sync(0xffffffffu, s, o);
            if (lane == 0) den_s[r] = s;
        }
    } else if (epi == 6 && blockIdx.y == 0) {
        // ksum: (float*)e1[bn+r] = sum_k Bh[bn+r, k]   (Bh = kpT rows)
        float* ksw = (float*)e1;
#pragma unroll 2
        for (int rr = 0; rr < 16; rr++) {
            int r = rr * 8 + wid;
            const uint4* p = (const uint4*)(Bh + (long long)(bn + r) * ldb);
            float s = 0.f;
            for (int i = lane; i < K / 8; i += 32) {
                uint4 v = p[i];
                float2 a0 = __half22float2(*(__half2*)&v.x);
                float2 a1 = __half22float2(*(__half2*)&v.y);
                float2 a2 = __half22float2(*(__half2*)&v.z);
                float2 a3 = __half22float2(*(__half2*)&v.w);
                s += (a0.x + a0.y) + (a1.x + a1.y) + (a2.x + a2.y) + (a3.x + a3.y);
            }
#pragma unroll
            for (int o = 16; o > 0; o >>= 1) s += __shfl_xor_sync(0xffffffffu, s, o);
            if (lane == 0) ksw[bn + r] = s;
        }
    }

    for (int t = 0; t < ntiles; t++) {
        CP_WAIT(1);
        __syncthreads();
        int ls = t + NSTAGE - 1;
        if (ls < ntiles) load_stage(ls % NSTAGE, ls);
        CP_COMMIT();

        uint32_t sb = sbase + (t % NSTAGE) * STAGE_B;
#pragma unroll
        for (int kk = 0; kk < 4; kk++) {
            uint32_t a[4][4], b[2][4];
#pragma unroll
            for (int mi = 0; mi < 4; mi++)
                ldmx4(a[mi][0], a[mi][1], a[mi][2], a[mi][3],
                      sb + a_base + (uint32_t)(mi * 16 * SROW * 2) + kk * 32);
#pragma unroll
            for (int p = 0; p < 2; p++)
                ldmx4(b[p][0], b[p][1], b[p][2], b[p][3],
                      sb + b_base + (uint32_t)(p * 16 * SROW * 2) + kk * 32);
#pragma unroll
            for (int mi = 0; mi < 4; mi++)
#pragma unroll
                for (int nj = 0; nj < 4; nj++)
                    mma16816(acc[mi][nj], a[mi], b[nj >> 1][(nj & 1) * 2],
                             b[nj >> 1][(nj & 1) * 2 + 1]);
        }
    }
    CP_WAIT(0);
    __syncthreads();

    float* stg = (float*)smem;
    const int gID = lane >> 2, t4 = lane & 3;

    if (epi == 5) {
        // ---- fused silu(gate)*up: nj even = gate, nj odd = up ----
#pragma unroll
        for (int p = 0; p < 2; p++) {
            int bc = bn + warp_n * 32 + p * 16 + 2 * t4;
            float bg0 = bias[bc],     bg1 = bias[bc + 1];
            float bu0 = bias[bc + 8], bu1 = bias[bc + 9];
            int hc = warp_n * 16 + p * 8 + 2 * t4;
#pragma unroll
            for (int mi = 0; mi < 4; mi++) {
                int r0 = warp_m * 64 + mi * 16 + gID;
                float o0 = silu_f(acc[mi][2*p][0] + bg0) * (acc[mi][2*p+1][0] + bu0);
                float o1 = silu_f(acc[mi][2*p][1] + bg1) * (acc[mi][2*p+1][1] + bu1);
                float o2 = silu_f(acc[mi][2*p][2] + bg0) * (acc[mi][2*p+1][2] + bu0);
                float o3 = silu_f(acc[mi][2*p][3] + bg1) * (acc[mi][2*p+1][3] + bu1);
                stg[r0 * SSTG + hc]           = o0;
                stg[r0 * SSTG + hc + 1]       = o1;
                stg[(r0 + 8) * SSTG + hc]     = o2;
                stg[(r0 + 8) * SSTG + hc + 1] = o3;
            }
        }
        __syncthreads();
        int hbase = bn >> 1;
#pragma unroll 4
        for (int it = 0; it < 32; it++) {
            int idx = tid + it * 256;
            int r = idx >> 6, c = idx & 63;
            int hcol = hbase + c;
            if (hcol < HFF)
                Ch[(long long)(bm + r) * ldch + hcol] = __float2half(stg[r * SSTG + c]);
        }
        return;
    }

    // ---- generic: single 128-col pass via SMEM staging ----
#pragma unroll
    for (int mi = 0; mi < 4; mi++)
#pragma unroll
        for (int nj = 0; nj < 4; nj++) {
            int r0 = warp_m * 64 + mi * 16 + gID;
            int c0 = warp_n * 32 + nj * 8 + 2 * t4;
            stg[r0 * SSTG + c0]           = acc[mi][nj][0];
            stg[r0 * SSTG + c0 + 1]       = acc[mi][nj][1];
            stg[(r0 + 8) * SSTG + c0]     = acc[mi][nj][2];
            stg[(r0 + 8) * SSTG + c0 + 1] = acc[mi][nj][3];
        }
    __syncthreads();

    if (epi == 1 && bn >= D_MODEL) {
        // k or v region: transposed coalesced store to KT/VT
        int reg = bn >> 10;                        // 1=k, 2=v
        fp16* T = (reg == 1) ? KT : VT;
        int dbase = bn - reg * 1024;
        int b = bm >> 12, s0v = bm & 4095;
        fp16* Tb = T + (size_t)b * D_MODEL * SEQ + s0v;
#pragma unroll 4
        for (int it = 0; it < 64; it++) {
            int idx = tid + it * 256;
            int c = idx >> 7, r = idx & 127;
            int gn = bn + c;
            float tv = stg[r * SSTG + c] + (bias ? bias[gn] : 0.f);
            if (reg == 1) tv = (tv > 0.f) ? tv + 1.f : expf(tv);
            Tb[(size_t)(dbase + c) * SEQ + r] = __float2half(tv);
        }
    } else {
#pragma unroll 4
        for (int it = 0; it < 64; it++) {
            int idx = tid + it * 256;
            int r = idx >> 7, c = idx & 127;
            int gm = bm + r, gn = bn + c;
            if (gn < N) {
                float tv = stg[r * SSTG + c] + (bias ? bias[gn] : 0.f);
                long long ci = (long long)gm * ldc + gn;
                float outv;
                if (epi == 2) {                // residual + normalize (local den)
                    outv = e2[ci] + tv / (den_s[r] + ATTN_EPS_F);
                } else if (epi == 1) {         // q cols: elu+1
                    outv = (tv > 0.f) ? tv + 1.f : expf(tv);
                } else {                       // 0 / 6: plain
                    outv = tv;
                }
                if (C) C[ci] = outv;
                if (Ch && gn < colLim)
                    Ch[(long long)gm * ldch + gn] = __float2half(outv);
            }
        }
    }
}

// ===================== merged prep kernel ===================================
#define NB_CONV (MTOT * D_MODEL / 1024)   // 16384
#define GX_QKV  (D3 / 32)                 // 96
#define NB_QKV  (GX_QKV * (D_MODEL / 32)) // 3072
#define GX_GU   ((HFF + 31) / 32)         // 86
#define NB_GU   (GX_GU * (D_MODEL / 32))  // 2752
#define GX_WD   (D_MODEL / 32)            // 32
#define NB_WD   (GX_WD * ((HFF + 31) / 32)) // 2752
#define NB_BIAS ((HFF + 255) / 256)       // 11
#define NB_PREP (NB_CONV + NB_QKV + 2 * NB_GU + NB_WD + NB_BIAS)

__global__ void __launch_bounds__(256) prep_kernel(
    const float* __restrict__ x, const float* __restrict__ Wqkv,
    const float* __restrict__ Wg, const float* __restrict__ Wu,
    const float* __restrict__ Wd, const float* __restrict__ bg,
    const float* __restrict__ bu)
{
    __shared__ float tile[32][33];
    int b = blockIdx.x;
    int t = threadIdx.x;

    if (b < NB_CONV) {                    // x -> fp16
        int i = b * 1024 + t * 4;
        float4 v = *(const float4*)(x + i);
        *(__half2*)(g_xh + i)     = __floats2half2_rn(v.x, v.y);
        *(__half2*)(g_xh + i + 2) = __floats2half2_rn(v.z, v.w);
        return;
    }
    b -= NB_CONV;

    const float* in; fp16* oh;
    int R, Ccols, ldi, ldo, map, bx, by;
    if (b < NB_QKV) {
        in = Wqkv; oh = g_WqkvT; R = D_MODEL; Ccols = D3; ldi = D3; ldo = D_MODEL;
        map = 0; bx = b % GX_QKV; by = b / GX_QKV;
    } else if ((b -= NB_QKV) < NB_GU) {
        in = Wg; oh = g_WguT; R = D_MODEL; Ccols = HFF; ldi = HFF; ldo = D_MODEL;
        map = 1; bx = b % GX_GU; by = b / GX_GU;
    } else if ((b -= NB_GU) < NB_GU) {
        in = Wu; oh = g_WguT; R = D_MODEL; Ccols = HFF; ldi = HFF; ldo = D_MODEL;
        map = 2; bx = b % GX_GU; by = b / GX_GU;
    } else if ((b -= NB_GU) < NB_WD) {
        in = Wd; oh = g_WdT; R = HFF; Ccols = D_MODEL; ldi = D_MODEL; ldo = HFFP;
        map = 0; bx = b % GX_WD; by = b / GX_WD;
    } else {                              // bias interleave
        b -= NB_WD;
        int n = b * 256 + t;
        if (n < HFF) {
            int o = ((n >> 3) << 4) + (n & 7);
            g_bgu[o] = bg[n];
            g_bgu[o + 8] = bu[n];
        }
        return;
    }

    int r0 = by * 32, c0 = bx * 32;
    int tx = t & 31, ty = t >> 5;
#pragma unroll
    for (int i = 0; i < 32; i += 8) {
        int r = r0 + ty + i, c = c0 + tx;
        tile[ty + i][tx] = (r < R && c < Ccols) ? in[(long long)r * ldi + c] : 0.f;
    }
    __syncthreads();
#pragma unroll
    for (int i = 0; i < 32; i += 8) {
        int r = c0 + ty + i, c = r0 + tx;
        if (r < Ccols && c < R) {
            int rr = r;
            if (map) rr = ((r >> 3) << 4) + (r & 7) + (map == 2 ? 8 : 0);
            oh[(long long)rr * ldo + c] = __float2half(tile[tx][ty + i]);
        }
    }
}

// ===================== layernorms ===========================================
__global__ void ln1_kernel(const float* __restrict__ in1,
                           const float* __restrict__ gamma, const float* __restrict__ beta,
                           fp16* __restrict__ oh)
{
    int row = blockIdx.x;
    int t = threadIdx.x;
    long long base4 = (long long)row * (D_MODEL / 4);
    float4 v4 = ((const float4*)in1)[base4 + t];
    float s = v4.x + v4.y + v4.z + v4.w;
    __shared__ float red[256];
    red[t] = s; __syncthreads();
    for (int o = 128; o > 0; o >>= 1) { if (t < o) red[t] += red[t + o]; __syncthreads(); }
    float mu = red[0] * (1.f / D_MODEL);
    __syncthreads();
    float dx = v4.x - mu, dy = v4.y - mu, dz = v4.z - mu, dw = v4.w - mu;
    red[t] = dx * dx + dy * dy + dz * dz + dw * dw;
    __syncthreads();
    for (int o = 128; o > 0; o >>= 1) { if (t < o) red[t] += red[t + o]; __syncthreads(); }
    float inv = rsqrtf(red[0] * (1.f / D_MODEL) + LN_EPS_F);
    float4 g4 = ((const float4*)gamma)[t];
    float4 b4 = ((const float4*)beta)[t];
    ((__half2*)oh)[base4 * 2 + 2 * t] =
        __floats2half2_rn(dx * inv * g4.x + b4.x, dy * inv * g4.y + b4.y);
    ((__half2*)oh)[base4 * 2 + 2 * t + 1] =
        __floats2half2_rn(dz * inv * g4.z + b4.z, dw * inv * g4.w + b4.w);
}
__global__ void ln2_kernel(const fp16* __restrict__ in1, const fp16* __restrict__ in2,
                           const float* __restrict__ gamma, const float* __restrict__ beta,
                           float* __restrict__ out)
{
    int row = blockIdx.x;
    int t = threadIdx.x;
    long long base2 = (long long)row * (D_MODEL / 2);
    float2 a0 = __half22float2(((const __half2*)in1)[base2 + 2 * t]);
    float2 a1 = __half22float2(((const __half2*)in1)[base2 + 2 * t + 1]);
    float2 c0 = __half22float2(((const __half2*)in2)[base2 + 2 * t]);
    float2 c1 = __half22float2(((const __half2*)in2)[base2 + 2 * t + 1]);
    float4 v4;
    v4.x = a0.x + c0.x; v4.y = a0.y + c0.y;
    v4.z = a1.x + c1.x; v4.w = a1.y + c1.y;
    float s = v4.x + v4.y + v4.z + v4.w;
    __shared__ float red[256];
    red[t] = s; __syncthreads();
    for (int o = 128; o > 0; o >>= 1) { if (t < o) red[t] += red[t + o]; __syncthreads(); }
    float mu = red[0] * (1.f / D_MODEL);
    __syncthreads();
    float dx = v4.x - mu, dy = v4.y - mu, dz = v4.z - mu, dw = v4.w - mu;
    red[t] = dx * dx + dy * dy + dz * dz + dw * dw;
    __syncthreads();
    for (int o = 128; o > 0; o >>= 1) { if (t < o) red[t] += red[t + o]; __syncthreads(); }
    float inv = rsqrtf(red[0] * (1.f / D_MODEL) + LN_EPS_F);
    float4 g4 = ((const float4*)gamma)[t];
    float4 b4 = ((const float4*)beta)[t];
    float4 o4;
    o4.x = dx * inv * g4.x + b4.x;
    o4.y = dy * inv * g4.y + b4.y;
    o4.z = dz * inv * g4.z + b4.z;
    o4.w = dw * inv * g4.w + b4.w;
    ((float4*)out)[(long long)row * (D_MODEL / 4) + t] = o4;
}

// ===================== launch ===============================================
extern "C" void kernel_launch(void* const* d_in, const int* in_sizes, int n_in,
                              void* d_out, int out_size)
{
    const float* x    = (const float*)d_in[0];
    const float* Wqkv = (const float*)d_in[1];
    const float* bqkv = (const float*)d_in[2];
    const float* Wg   = (const float*)d_in[3];
    const float* bg   = (const float*)d_in[4];
    const float* Wu   = (const float*)d_in[5];
    const float* bu   = (const float*)d_in[6];
    const float* Wd   = (const float*)d_in[7];
    const float* bd   = (const float*)d_in[8];
    const float* g1   = (const float*)d_in[9];
    const float* b1   = (const float*)d_in[10];
    const float* g2   = (const float*)d_in[11];
    const float* b2   = (const float*)d_in[12];
    float* out = (float*)d_out;

    float *yb, *bgu, *ksum;
    fp16 *qkvh,*xh,*WqkvT,*WguT,*WdT,*kpT,*vT,*kvh,*x1h,*hh,*ffnh;
    cudaGetSymbolAddress((void**)&qkvh, g_qkvh);
    cudaGetSymbolAddress((void**)&yb,   g_y);
    cudaGetSymbolAddress((void**)&bgu,  g_bgu);
    cudaGetSymbolAddress((void**)&ksum, g_ksum);
    cudaGetSymbolAddress((void**)&xh,   g_xh);
    cudaGetSymbolAddress((void**)&WqkvT,g_WqkvT);
    cudaGetSymbolAddress((void**)&WguT, g_WguT);
    cudaGetSymbolAddress((void**)&WdT,  g_WdT);
    cudaGetSymbolAddress((void**)&kpT,  g_kpT);
    cudaGetSymbolAddress((void**)&vT,   g_vT);
    cudaGetSymbolAddress((void**)&kvh,  g_kvh);
    cudaGetSymbolAddress((void**)&x1h,  g_x1h);
    cudaGetSymbolAddress((void**)&hh,   g_hh);
    cudaGetSymbolAddress((void**)&ffnh, g_ffnh);

    cudaFuncSetAttribute(mma_gemm_kernel,
                         cudaFuncAttributeMaxDynamicSharedMemorySize, SMEM_SZ_DEN);

    dim3 blk(256);
    const long long SD3  = (long long)SEQ * D3;
    const long long SDM  = (long long)SEQ * D_MODEL;
    const long long DD   = (long long)D_MODEL * D_MODEL;
    const long long DS   = (long long)D_MODEL * SEQ;

    // ---- 0) merged prep: convert + transposes + bias interleave ----
    prep_kernel<<<NB_PREP, blk>>>(x, Wqkv, Wg, Wu, Wd, bg, bu);

    // ---- 1) qkv GEMM: q->qkvh (elu+1), k->kpT (elu+1, transposed), v->vT ----
    mma_gemm_kernel<<<dim3(D3/BN, MTOT/BM, 1), blk, SMEM_SZ>>>(
        xh, WqkvT, bqkv, nullptr, qkvh, kpT, vT,
        MTOT, D3, D_MODEL, D_MODEL, D_MODEL, D3, D3,
        0, 0, 0, 0, 1, D_MODEL, nullptr, nullptr, 0);

    // ---- 2) kvh = fp16(v^T @ kp); by==0 CTAs also write ksum (epi 6) ----
    mma_gemm_kernel<<<dim3(D_MODEL/BN, D_MODEL/BM, BATCH), blk, SMEM_SZ>>>(
        vT, kpT, nullptr, nullptr, kvh, nullptr, nullptr,
        D_MODEL, D_MODEL, SEQ, SEQ, SEQ, D_MODEL, D_MODEL,
        DS, DS, DD, DD, 6, D_MODEL, ksum, nullptr, (long long)D_MODEL);

    // ---- 3) y = x + (qp @ kv) / (den + eps); den computed in-prologue ----
    mma_gemm_kernel<<<dim3(D_MODEL/BN, SEQ/BM, BATCH), blk, SMEM_SZ_DEN>>>(
        qkvh, kvh, nullptr, yb, nullptr, nullptr, nullptr,
        SEQ, D_MODEL, D_MODEL, D3, D_MODEL, D_MODEL, D_MODEL,
        SD3, DD, SDM, 0, 2, 0, ksum, x, (long long)D_MODEL);

    // ---- 4) x1h = fp16(LN(y)) ----
    ln1_kernel<<<MTOT, blk>>>(yb, g1, b1, x1h);

    // ---- 5+6) hh = fp16(silu(x1@Wg+bg) * (x1@Wu+bu))  [one fused GEMM] ----
    mma_gemm_kernel<<<dim3((NGU+BN-1)/BN, MTOT/BM, 1), blk, SMEM_SZ>>>(
        x1h, WguT, bgu, nullptr, hh, nullptr, nullptr,
        MTOT, NGU, D_MODEL, D_MODEL, D_MODEL, NGU, HFFP,
        0, 0, 0, 0, 5, HFF, nullptr, nullptr, 0);

    // ---- 7) ffnh = fp16(h @ Wd + bd) ----
    mma_gemm_kernel<<<dim3(D_MODEL/BN, MTOT/BM, 1), blk, SMEM_SZ>>>(
        hh, WdT, bd, nullptr, ffnh, nullptr, nullptr,
        MTOT, D_MODEL, HFF, HFFP, HFFP, D_MODEL, D_MODEL,
        0, 0, 0, 0, 0, D_MODEL, nullptr, nullptr, 0);

    // ---- 8) out = LN(x1h + ffnh) ----
    ln2_kernel<<<MTOT, blk>>>(x1h, ffnh, g2, b2, out);
}

// round 13
// speedup vs baseline: 8.7643x; 1.0594x over previous
#include <cuda_runtime.h>
#include <cuda_fp16.h>
#include <cstdint>
#include <math.h>

#define D_MODEL 1024
#define D3      3072
#define HFF     2730
#define HFFP    2736                 // HFF padded to 8-element (16B) multiple
#define NGU     5472                 // interleaved gate/up N (2*2736)
#define BATCH   4
#define SEQ     4096
#define MTOT    (BATCH*SEQ)          // 16384
#define DP      1152                 // padded e-dim (1025 rounded to CTA grid)
#define YLD     1032                 // y row stride (1024 num + den + pad)

#define LN_EPS_F   1e-5f
#define ATTN_EPS_F 1e-6f

typedef __half fp16;

// ===================== scratch ==============================================
__device__ fp16  g_qkvh[(size_t)MTOT * D3];         // only q cols [0,1024) used
__device__ fp16  g_xh  [(size_t)MTOT * D_MODEL];
__device__ fp16  g_WqkvT[(size_t)D3 * D_MODEL];
__device__ fp16  g_WguT[(size_t)NGU * D_MODEL];     // interleaved gate/up rows
__device__ float g_bgu [5632];                      // interleaved biases
__device__ fp16  g_WdT [(size_t)D_MODEL * HFFP];    // padded ld
__device__ fp16  g_kpT [(size_t)BATCH * D_MODEL * SEQ];
__device__ fp16  g_vT  [(size_t)BATCH * DP * SEQ];  // row 1024 = ones; 1025+ zero
__device__ fp16  g_kvh [(size_t)BATCH * DP * D_MODEL]; // row 1024 = ksum
__device__ float g_y [(size_t)MTOT * YLD];          // num cols 0..1023, den col 1024
__device__ fp16  g_x1h[(size_t)MTOT * D_MODEL];     // LN1 out (fp16 only)
__device__ fp16  g_hh[(size_t)MTOT * HFFP];         // fused silu(gate)*up
__device__ fp16  g_ffnh[(size_t)MTOT * D_MODEL];    // down-proj out (fp16)

// ===================== helpers ==============================================
__device__ __forceinline__ uint32_t smem_u32(const void* p) {
    uint32_t a;
    asm("{ .reg .u64 t; cvta.to.shared.u64 t, %1; cvt.u32.u64 %0, t; }" : "=r"(a) : "l"(p));
    return a;
}
__device__ __forceinline__ void cp16(uint32_t dst, const void* src, int bytes) {
    asm volatile("cp.async.cg.shared.global [%0], [%1], 16, %2;\n"
        :: "r"(dst), "l"(src), "r"(bytes));
}
#define CP_COMMIT() asm volatile("cp.async.commit_group;\n" ::: "memory")
#define CP_WAIT(n)  asm volatile("cp.async.wait_group %0;\n" :: "n"(n) : "memory")

__device__ __forceinline__ void ldmx4(uint32_t& r0, uint32_t& r1, uint32_t& r2,
                                      uint32_t& r3, uint32_t addr) {
    asm volatile("ldmatrix.sync.aligned.m8n8.x4.shared.b16 {%0,%1,%2,%3}, [%4];"
        : "=r"(r0), "=r"(r1), "=r"(r2), "=r"(r3) : "r"(addr));
}
__device__ __forceinline__ void mma16816(float* c, const uint32_t* a, uint32_t b0, uint32_t b1) {
    asm volatile(
        "mma.sync.aligned.m16n8k16.row.col.f32.f16.f16.f32 "
        "{%0,%1,%2,%3}, {%4,%5,%6,%7}, {%8,%9}, {%0,%1,%2,%3};"
        : "+f"(c[0]), "+f"(c[1]), "+f"(c[2]), "+f"(c[3])
        : "r"(a[0]), "r"(a[1]), "r"(a[2]), "r"(a[3]), "r"(b0), "r"(b1));
}
__device__ __forceinline__ float silu_f(float g) { return g / (1.f + expf(-g)); }

// ===================== mma.sync fp16 GEMM (fp32 accum) ======================
// C[m,n] = sum_k A[m,k] * Bt[n,k]  (fp16, Bt = B^T [N][K] row-major)
// BM=128, BN=128, BK=64. 8 warps: 2 m-warps x 4 n-warps, 64x32 warp tile.
// 2 CTAs/SM (regs <=128). 3-stage cp.async pipeline.
// epi: 0 plain(+bias); 1 qkv (q->qkvh elu+1, k->KT elu+1 transposed, v->VT);
//      5 fused silu(gate)*up (interleaved B) -> Ch only.
#define BM 128
#define BN 128
#define BK 64
#define SROW 72                       // halves per smem row (64 + 8 pad)
#define A_HALVES (128 * SROW)         // 9216
#define B_HALVES (128 * SROW)         // 9216
#define STAGE_B ((A_HALVES + B_HALVES) * 2)   // 36864 bytes
#define NSTAGE 3
#define SMEM_SZ (NSTAGE * STAGE_B)    // 110592; epilogue staging 68096 fits
#define SSTG 133                      // staging stride (conflict-free transposed reads)

__global__ void __launch_bounds__(256, 2) mma_gemm_kernel(
    const fp16* __restrict__ Ah, const fp16* __restrict__ Bh,
    const float* __restrict__ bias, float* __restrict__ C,
    fp16* __restrict__ Ch, fp16* __restrict__ KT, fp16* __restrict__ VT,
    int M, int N, int K, int lda, int ldb, int ldc, int ldch,
    long long sA, long long sB, long long sC, long long sCh,
    int epi, int colLim)
{
    extern __shared__ __align__(16) char smem[];
    const uint32_t sbase = smem_u32(smem);
    const int tid = threadIdx.x;
    const int wid = tid >> 5;
    const int lane = tid & 31;
    const int warp_m = wid & 1;        // 2 m-warps of 64 rows
    const int warp_n = wid >> 1;       // 4 n-warps of 32 cols
    const int bz = blockIdx.z;
    Ah += sA * bz;  Bh += sB * bz;
    if (C)  C  += sC * bz;
    if (Ch) Ch += sCh * bz;
    const int bm = blockIdx.y * BM;
    const int bn = blockIdx.x * BN;

    float acc[4][4][4];
#pragma unroll
    for (int i = 0; i < 4; i++)
#pragma unroll
        for (int j = 0; j < 4; j++)
#pragma unroll
            for (int v = 0; v < 4; v++) acc[i][j][v] = 0.f;

    const uint32_t a_base =
        ((uint32_t)(warp_m * 64 + (lane & 15)) * SROW + ((lane >> 4) * 8)) * 2;
    const uint32_t b_base = (uint32_t)A_HALVES * 2 +
        (((uint32_t)(warp_n * 32 + ((lane >> 4) & 1) * 8 + (lane & 7))) * SROW +
         (((lane >> 3) & 1) * 8)) * 2;

    const int ntiles = (K + BK - 1) / BK;

    auto load_stage = [&](int s, int t) {
        uint32_t sb = sbase + s * STAGE_B;
        int k0 = t * BK;
#pragma unroll
        for (int j = 0; j < 4; j++) {
            int idx = tid + j * 256;
            int r = idx >> 3, ch = idx & 7;
            int kc = k0 + ch * 8;
            int ab = 2 * (K - kc); ab = ab < 0 ? 0 : (ab > 16 ? 16 : ab);
            cp16(sb + (r * SROW + ch * 8) * 2, Ah + (long long)(bm + r) * lda + kc, ab);
        }
#pragma unroll
        for (int j = 0; j < 4; j++) {
            int idx = tid + j * 256;
            int r = idx >> 3, ch = idx & 7;
            int kc = k0 + ch * 8;
            int ab = 2 * (K - kc); ab = ab < 0 ? 0 : (ab > 16 ? 16 : ab);
            int gn = bn + r;
            int bb = (gn < N) ? ab : 0;
            cp16(sb + A_HALVES * 2 + (r * SROW + ch * 8) * 2,
                 Bh + (long long)(gn < N ? gn : 0) * ldb + kc, bb);
        }
    };

    load_stage(0, 0); CP_COMMIT();
    if (ntiles > 1) load_stage(1, 1);
    CP_COMMIT();

    for (int t = 0; t < ntiles; t++) {
        CP_WAIT(1);
        __syncthreads();
        int ls = t + NSTAGE - 1;
        if (ls < ntiles) load_stage(ls % NSTAGE, ls);
        CP_COMMIT();

        uint32_t sb = sbase + (t % NSTAGE) * STAGE_B;
#pragma unroll
        for (int kk = 0; kk < 4; kk++) {
            uint32_t a[4][4], b[2][4];
#pragma unroll
            for (int mi = 0; mi < 4; mi++)
                ldmx4(a[mi][0], a[mi][1], a[mi][2], a[mi][3],
                      sb + a_base + (uint32_t)(mi * 16 * SROW * 2) + kk * 32);
#pragma unroll
            for (int p = 0; p < 2; p++)
                ldmx4(b[p][0], b[p][1], b[p][2], b[p][3],
                      sb + b_base + (uint32_t)(p * 16 * SROW * 2) + kk * 32);
#pragma unroll
            for (int mi = 0; mi < 4; mi++)
#pragma unroll
                for (int nj = 0; nj < 4; nj++)
                    mma16816(acc[mi][nj], a[mi], b[nj >> 1][(nj & 1) * 2],
                             b[nj >> 1][(nj & 1) * 2 + 1]);
        }
    }
    CP_WAIT(0);
    __syncthreads();

    float* stg = (float*)smem;
    const int gID = lane >> 2, t4 = lane & 3;

    if (epi == 5) {
        // ---- fused silu(gate)*up: nj even = gate, nj odd = up ----
#pragma unroll
        for (int p = 0; p < 2; p++) {
            int bc = bn + warp_n * 32 + p * 16 + 2 * t4;
            float bg0 = bias[bc],     bg1 = bias[bc + 1];
            float bu0 = bias[bc + 8], bu1 = bias[bc + 9];
            int hc = warp_n * 16 + p * 8 + 2 * t4;
#pragma unroll
            for (int mi = 0; mi < 4; mi++) {
                int r0 = warp_m * 64 + mi * 16 + gID;
                float o0 = silu_f(acc[mi][2*p][0] + bg0) * (acc[mi][2*p+1][0] + bu0);
                float o1 = silu_f(acc[mi][2*p][1] + bg1) * (acc[mi][2*p+1][1] + bu1);
                float o2 = silu_f(acc[mi][2*p][2] + bg0) * (acc[mi][2*p+1][2] + bu0);
                float o3 = silu_f(acc[mi][2*p][3] + bg1) * (acc[mi][2*p+1][3] + bu1);
                stg[r0 * SSTG + hc]           = o0;
                stg[r0 * SSTG + hc + 1]       = o1;
                stg[(r0 + 8) * SSTG + hc]     = o2;
                stg[(r0 + 8) * SSTG + hc + 1] = o3;
            }
        }
        __syncthreads();
        int hbase = bn >> 1;
#pragma unroll 4
        for (int it = 0; it < 32; it++) {
            int idx = tid + it * 256;
            int r = idx >> 6, c = idx & 63;
            int hcol = hbase + c;
            if (hcol < HFF)
                Ch[(long long)(bm + r) * ldch + hcol] = __float2half(stg[r * SSTG + c]);
        }
        return;
    }

    // ---- generic: single 128-col pass via SMEM staging ----
#pragma unroll
    for (int mi = 0; mi < 4; mi++)
#pragma unroll
        for (int nj = 0; nj < 4; nj++) {
            int r0 = warp_m * 64 + mi * 16 + gID;
            int c0 = warp_n * 32 + nj * 8 + 2 * t4;
            stg[r0 * SSTG + c0]           = acc[mi][nj][0];
            stg[r0 * SSTG + c0 + 1]       = acc[mi][nj][1];
            stg[(r0 + 8) * SSTG + c0]     = acc[mi][nj][2];
            stg[(r0 + 8) * SSTG + c0 + 1] = acc[mi][nj][3];
        }
    __syncthreads();

    if (epi == 1 && bn >= D_MODEL) {
        // k or v region: transposed coalesced store to KT/VT
        int reg = bn >> 10;                        // 1=k, 2=v
        fp16* T = (reg == 1) ? KT : VT;
        long long tstride = (reg == 1) ? (long long)D_MODEL * SEQ : (long long)DP * SEQ;
        int dbase = bn - reg * 1024;
        int b = bm >> 12, s0v = bm & 4095;
        fp16* Tb = T + (size_t)b * tstride + s0v;
#pragma unroll 4
        for (int it = 0; it < 64; it++) {
            int idx = tid + it * 256;
            int c = idx >> 7, r = idx & 127;
            int gn = bn + c;
            float tv = stg[r * SSTG + c] + (bias ? bias[gn] : 0.f);
            if (reg == 1) tv = (tv > 0.f) ? tv + 1.f : expf(tv);
            Tb[(size_t)(dbase + c) * SEQ + r] = __float2half(tv);
        }
    } else {
#pragma unroll 4
        for (int it = 0; it < 64; it++) {
            int idx = tid + it * 256;
            int r = idx >> 7, c = idx & 127;
            int gm = bm + r, gn = bn + c;
            if (gn < N) {
                float tv = stg[r * SSTG + c] + (bias ? bias[gn] : 0.f);
                float outv;
                if (epi == 1) {                // q cols: elu+1
                    outv = (tv > 0.f) ? tv + 1.f : expf(tv);
                } else {                       // 0: plain
                    outv = tv;
                }
                if (C) C[(long long)gm * ldc + gn] = outv;
                if (Ch && gn < colLim)
                    Ch[(long long)gm * ldch + gn] = __float2half(outv);
            }
        }
    }
}

// ===================== merged prep kernel ===================================
#define NB_CONV (MTOT * D_MODEL / 1024)   // 16384
#define GX_QKV  (D3 / 32)                 // 96
#define NB_QKV  (GX_QKV * (D_MODEL / 32)) // 3072
#define GX_GU   ((HFF + 31) / 32)         // 86
#define NB_GU   (GX_GU * (D_MODEL / 32))  // 2752
#define GX_WD   (D_MODEL / 32)            // 32
#define NB_WD   (GX_WD * ((HFF + 31) / 32)) // 2752
#define NB_BIAS ((HFF + 255) / 256)       // 11
#define NB_ONES (BATCH * SEQ / 1024)      // 64 (ones row of vT)
#define NB_PREP (NB_CONV + NB_QKV + 2 * NB_GU + NB_WD + NB_BIAS + NB_ONES)

__global__ void __launch_bounds__(256) prep_kernel(
    const float* __restrict__ x, const float* __restrict__ Wqkv,
    const float* __restrict__ Wg, const float* __restrict__ Wu,
    const float* __restrict__ Wd, const float* __restrict__ bg,
    const float* __restrict__ bu)
{
    __shared__ float tile[32][33];
    int b = blockIdx.x;
    int t = threadIdx.x;

    if (b < NB_CONV) {                    // x -> fp16
        int i = b * 1024 + t * 4;
        float4 v = *(const float4*)(x + i);
        *(__half2*)(g_xh + i)     = __floats2half2_rn(v.x, v.y);
        *(__half2*)(g_xh + i + 2) = __floats2half2_rn(v.z, v.w);
        return;
    }
    b -= NB_CONV;

    const float* in; fp16* oh;
    int R, Ccols, ldi, ldo, map, bx, by;
    if (b < NB_QKV) {
        in = Wqkv; oh = g_WqkvT; R = D_MODEL; Ccols = D3; ldi = D3; ldo = D_MODEL;
        map = 0; bx = b % GX_QKV; by = b / GX_QKV;
    } else if ((b -= NB_QKV) < NB_GU) {
        in = Wg; oh = g_WguT; R = D_MODEL; Ccols = HFF; ldi = HFF; ldo = D_MODEL;
        map = 1; bx = b % GX_GU; by = b / GX_GU;
    } else if ((b -= NB_GU) < NB_GU) {
        in = Wu; oh = g_WguT; R = D_MODEL; Ccols = HFF; ldi = HFF; ldo = D_MODEL;
        map = 2; bx = b % GX_GU; by = b / GX_GU;
    } else if ((b -= NB_GU) < NB_WD) {
        in = Wd; oh = g_WdT; R = HFF; Ccols = D_MODEL; ldi = D_MODEL; ldo = HFFP;
        map = 0; bx = b % GX_WD; by = b / GX_WD;
    } else if ((b -= NB_WD) < NB_BIAS) {  // bias interleave
        int n = b * 256 + t;
        if (n < HFF) {
            int o = ((n >> 3) << 4) + (n & 7);
            g_bgu[o] = bg[n];
            g_bgu[o + 8] = bu[n];
        }
        return;
    } else {                              // vT ones row (e = 1024)
        b -= NB_BIAS;
        int i = b * 1024 + t * 4;         // i in [0, BATCH*SEQ)
        int bb = i >> 12, s = i & 4095;
        fp16* p = g_vT + (size_t)bb * DP * SEQ + (size_t)1024 * SEQ + s;
        __half2 one2 = __floats2half2_rn(1.f, 1.f);
        *(__half2*)p       = one2;
        *(__half2*)(p + 2) = one2;
        return;
    }

    int r0 = by * 32, c0 = bx * 32;
    int tx = t & 31, ty = t >> 5;
#pragma unroll
    for (int i = 0; i < 32; i += 8) {
        int r = r0 + ty + i, c = c0 + tx;
        tile[ty + i][tx] = (r < R && c < Ccols) ? in[(long long)r * ldi + c] : 0.f;
    }
    __syncthreads();
#pragma unroll
    for (int i = 0; i < 32; i += 8) {
        int r = c0 + ty + i, c = r0 + tx;
        if (r < Ccols && c < R) {
            int rr = r;
            if (map) rr = ((r >> 3) << 4) + (r & 7) + (map == 2 ? 8 : 0);
            oh[(long long)rr * ldo + c] = __float2half(tile[tx][ty + i]);
        }
    }
}

// ===================== layernorms ===========================================
// LN1: v = x + num/(den+eps); LN(v) -> fp16 x1h.  num/den from y (ld YLD).
__global__ void ln1_kernel(const float* __restrict__ y, const float* __restrict__ x,
                           const float* __restrict__ gamma, const float* __restrict__ beta,
                           fp16* __restrict__ oh)
{
    int row = blockIdx.x;
    int t = threadIdx.x;
    const float4* y4 = (const float4*)(y + (long long)row * YLD);
    float den = y[(long long)row * YLD + 1024] + ATTN_EPS_F;
    float rden = 1.f / den;
    long long base4 = (long long)row * (D_MODEL / 4);
    float4 n4 = y4[t];
    float4 xv = ((const float4*)x)[base4 + t];
    float4 v4;
    v4.x = xv.x + n4.x * rden;
    v4.y = xv.y + n4.y * rden;
    v4.z = xv.z + n4.z * rden;
    v4.w = xv.w + n4.w * rden;
    float s = v4.x + v4.y + v4.z + v4.w;
    __shared__ float red[256];
    red[t] = s; __syncthreads();
    for (int o = 128; o > 0; o >>= 1) { if (t < o) red[t] += red[t + o]; __syncthreads(); }
    float mu = red[0] * (1.f / D_MODEL);
    __syncthreads();
    float dx = v4.x - mu, dy = v4.y - mu, dz = v4.z - mu, dw = v4.w - mu;
    red[t] = dx * dx + dy * dy + dz * dz + dw * dw;
    __syncthreads();
    for (int o = 128; o > 0; o >>= 1) { if (t < o) red[t] += red[t + o]; __syncthreads(); }
    float inv = rsqrtf(red[0] * (1.f / D_MODEL) + LN_EPS_F);
    float4 g4 = ((const float4*)gamma)[t];
    float4 b4 = ((const float4*)beta)[t];
    ((__half2*)oh)[base4 * 2 + 2 * t] =
        __floats2half2_rn(dx * inv * g4.x + b4.x, dy * inv * g4.y + b4.y);
    ((__half2*)oh)[base4 * 2 + 2 * t + 1] =
        __floats2half2_rn(dz * inv * g4.z + b4.z, dw * inv * g4.w + b4.w);
}
__global__ void ln2_kernel(const fp16* __restrict__ in1, const fp16* __restrict__ in2,
                           const float* __restrict__ gamma, const float* __restrict__ beta,
                           float* __restrict__ out)
{
    int row = blockIdx.x;
    int t = threadIdx.x;
    long long base2 = (long long)row * (D_MODEL / 2);
    float2 a0 = __half22float2(((const __half2*)in1)[base2 + 2 * t]);
    float2 a1 = __half22float2(((const __half2*)in1)[base2 + 2 * t + 1]);
    float2 c0 = __half22float2(((const __half2*)in2)[base2 + 2 * t]);
    float2 c1 = __half22float2(((const __half2*)in2)[base2 + 2 * t + 1]);
    float4 v4;
    v4.x = a0.x + c0.x; v4.y = a0.y + c0.y;
    v4.z = a1.x + c1.x; v4.w = a1.y + c1.y;
    float s = v4.x + v4.y + v4.z + v4.w;
    __shared__ float red[256];
    red[t] = s; __syncthreads();
    for (int o = 128; o > 0; o >>= 1) { if (t < o) red[t] += red[t + o]; __syncthreads(); }
    float mu = red[0] * (1.f / D_MODEL);
    __syncthreads();
    float dx = v4.x - mu, dy = v4.y - mu, dz = v4.z - mu, dw = v4.w - mu;
    red[t] = dx * dx + dy * dy + dz * dz + dw * dw;
    __syncthreads();
    for (int o = 128; o > 0; o >>= 1) { if (t < o) red[t] += red[t + o]; __syncthreads(); }
    float inv = rsqrtf(red[0] * (1.f / D_MODEL) + LN_EPS_F);
    float4 g4 = ((const float4*)gamma)[t];
    float4 b4 = ((const float4*)beta)[t];
    float4 o4;
    o4.x = dx * inv * g4.x + b4.x;
    o4.y = dy * inv * g4.y + b4.y;
    o4.z = dz * inv * g4.z + b4.z;
    o4.w = dw * inv * g4.w + b4.w;
    ((float4*)out)[(long long)row * (D_MODEL / 4) + t] = o4;
}

// ===================== launch ===============================================
extern "C" void kernel_launch(void* const* d_in, const int* in_sizes, int n_in,
                              void* d_out, int out_size)
{
    const float* x    = (const float*)d_in[0];
    const float* Wqkv = (const float*)d_in[1];
    const float* bqkv = (const float*)d_in[2];
    const float* Wg   = (const float*)d_in[3];
    const float* bg   = (const float*)d_in[4];
    const float* Wu   = (const float*)d_in[5];
    const float* bu   = (const float*)d_in[6];
    const float* Wd   = (const float*)d_in[7];
    const float* bd   = (const float*)d_in[8];
    const float* g1   = (const float*)d_in[9];
    const float* b1   = (const float*)d_in[10];
    const float* g2   = (const float*)d_in[11];
    const float* b2   = (const float*)d_in[12];
    float* out = (float*)d_out;

    float *yb, *bgu;
    fp16 *qkvh,*xh,*WqkvT,*WguT,*WdT,*kpT,*vT,*kvh,*x1h,*hh,*ffnh;
    cudaGetSymbolAddress((void**)&qkvh, g_qkvh);
    cudaGetSymbolAddress((void**)&yb,   g_y);
    cudaGetSymbolAddress((void**)&bgu,  g_bgu);
    cudaGetSymbolAddress((void**)&xh,   g_xh);
    cudaGetSymbolAddress((void**)&WqkvT,g_WqkvT);
    cudaGetSymbolAddress((void**)&WguT, g_WguT);
    cudaGetSymbolAddress((void**)&WdT,  g_WdT);
    cudaGetSymbolAddress((void**)&kpT,  g_kpT);
    cudaGetSymbolAddress((void**)&vT,   g_vT);
    cudaGetSymbolAddress((void**)&kvh,  g_kvh);
    cudaGetSymbolAddress((void**)&x1h,  g_x1h);
    cudaGetSymbolAddress((void**)&hh,   g_hh);
    cudaGetSymbolAddress((void**)&ffnh, g_ffnh);

    cudaFuncSetAttribute(mma_gemm_kernel,
                         cudaFuncAttributeMaxDynamicSharedMemorySize, SMEM_SZ);

    dim3 blk(256);
    const long long SD3  = (long long)SEQ * D3;
    const long long DS   = (long long)D_MODEL * SEQ;
    const long long VS   = (long long)DP * SEQ;
    const long long KVS  = (long long)DP * D_MODEL;
    const long long YS   = (long long)SEQ * YLD;

    // ---- 0) merged prep (incl. vT ones-row) ----
    prep_kernel<<<NB_PREP, blk>>>(x, Wqkv, Wg, Wu, Wd, bg, bu);

    // ---- 1) qkv GEMM: q->qkvh (elu+1), k->kpT (elu+1, transposed), v->vT ----
    mma_gemm_kernel<<<dim3(D3/BN, MTOT/BM, 1), blk, SMEM_SZ>>>(
        xh, WqkvT, bqkv, nullptr, qkvh, kpT, vT,
        MTOT, D3, D_MODEL, D_MODEL, D_MODEL, D3, D3,
        0, 0, 0, 0, 1, D_MODEL);

    // ---- 2) kvh[e][d] = fp16(sum_s vT'[e,s] kp[s,d]), e in [0,1025)
    //         (row 1024 of vT is ones -> kvh row 1024 = ksum) ----
    mma_gemm_kernel<<<dim3(D_MODEL/BN, (1025 + BM - 1)/BM, BATCH), blk, SMEM_SZ>>>(
        vT, kpT, nullptr, nullptr, kvh, nullptr, nullptr,
        1025, D_MODEL, SEQ, SEQ, SEQ, D_MODEL, D_MODEL,
        VS, DS, KVS, KVS, 0, D_MODEL);

    // ---- 3) y[:, 0:1024] = qp @ kv ; y[:, 1024] = qp @ ksum = den ----
    mma_gemm_kernel<<<dim3((1025 + BN - 1)/BN, SEQ/BM, BATCH), blk, SMEM_SZ>>>(
        qkvh, kvh, nullptr, yb, nullptr, nullptr, nullptr,
        SEQ, 1025, D_MODEL, D3, D_MODEL, YLD, YLD,
        SD3, KVS, YS, YS, 0, 0);

    // ---- 4) x1h = fp16(LN(x + num/den)) ----
    ln1_kernel<<<MTOT, blk>>>(yb, x, g1, b1, x1h);

    // ---- 5+6) hh = fp16(silu(x1@Wg+bg) * (x1@Wu+bu)) ----
    mma_gemm_kernel<<<dim3((NGU+BN-1)/BN, MTOT/BM, 1), blk, SMEM_SZ>>>(
        x1h, WguT, bgu, nullptr, hh, nullptr, nullptr,
        MTOT, NGU, D_MODEL, D_MODEL, D_MODEL, NGU, HFFP,
        0, 0, 0, 0, 5, HFF);

    // ---- 7) ffnh = fp16(h @ Wd + bd) ----
    mma_gemm_kernel<<<dim3(D_MODEL/BN, MTOT/BM, 1), blk, SMEM_SZ>>>(
        hh, WdT, bd, nullptr, ffnh, nullptr, nullptr,
        MTOT, D_MODEL, HFF, HFFP, HFFP, D_MODEL, D_MODEL,
        0, 0, 0, 0, 0, D_MODEL);

    // ---- 8) out = LN(x1h + ffnh) ----
    ln2_kernel<<<MTOT, blk>>>(x1h, ffnh, g2, b2, out);
}

// round 14
// speedup vs baseline: 10.0206x; 1.1433x over previous
#include <cuda_runtime.h>
#include <cuda_fp16.h>
#include <cstdint>
#include <math.h>

#define D_MODEL 1024
#define D3      3072
#define HFF     2730
#define HFFP    2736                 // HFF padded to 8-element (16B) multiple
#define NGU     5472                 // interleaved gate/up N (2*2736)
#define BATCH   4
#define SEQ     4096
#define MTOT    (BATCH*SEQ)          // 16384
#define DP      1152                 // padded e-dim (1025 rounded up)
#define YLD     1032                 // y row stride (1024 num + den + pad)

#define LN_EPS_F   1e-5f
#define ATTN_EPS_F 1e-6f

typedef __half fp16;

// ===================== scratch ==============================================
__device__ fp16  g_qkvh[(size_t)MTOT * D3];         // only q cols [0,1024) used
__device__ fp16  g_xh  [(size_t)MTOT * D_MODEL];
__device__ fp16  g_WqkvT[(size_t)D3 * D_MODEL];
__device__ fp16  g_WguT[(size_t)NGU * D_MODEL];     // interleaved gate/up rows
__device__ float g_bgu [5632];                      // interleaved biases
__device__ fp16  g_WdT [(size_t)D_MODEL * HFFP];    // padded ld
__device__ fp16  g_kpT [(size_t)BATCH * D_MODEL * SEQ];
__device__ fp16  g_vT  [(size_t)BATCH * DP * SEQ];  // row 1024 = ones; 1025+ zero
__device__ fp16  g_kvh [(size_t)BATCH * DP * D_MODEL]; // row 1024 = ksum
__device__ float g_y [(size_t)MTOT * YLD];          // num cols 0..1023, den col 1024
__device__ fp16  g_x1h[(size_t)MTOT * D_MODEL];     // LN1 out (fp16 only)
__device__ fp16  g_hh[(size_t)MTOT * HFFP];         // fused silu(gate)*up
__device__ fp16  g_ffnh[(size_t)MTOT * D_MODEL];    // down-proj out (fp16)

// ===================== helpers ==============================================
__device__ __forceinline__ uint32_t smem_u32(const void* p) {
    uint32_t a;
    asm("{ .reg .u64 t; cvta.to.shared.u64 t, %1; cvt.u32.u64 %0, t; }" : "=r"(a) : "l"(p));
    return a;
}
__device__ __forceinline__ void cp16(uint32_t dst, const void* src, int bytes) {
    asm volatile("cp.async.cg.shared.global [%0], [%1], 16, %2;\n"
        :: "r"(dst), "l"(src), "r"(bytes));
}
#define CP_COMMIT() asm volatile("cp.async.commit_group;\n" ::: "memory")
#define CP_WAIT(n)  asm volatile("cp.async.wait_group %0;\n" :: "n"(n) : "memory")

__device__ __forceinline__ void ldmx4(uint32_t& r0, uint32_t& r1, uint32_t& r2,
                                      uint32_t& r3, uint32_t addr) {
    asm volatile("ldmatrix.sync.aligned.m8n8.x4.shared.b16 {%0,%1,%2,%3}, [%4];"
        : "=r"(r0), "=r"(r1), "=r"(r2), "=r"(r3) : "r"(addr));
}
__device__ __forceinline__ void mma16816(float* c, const uint32_t* a, uint32_t b0, uint32_t b1) {
    asm volatile(
        "mma.sync.aligned.m16n8k16.row.col.f32.f16.f16.f32 "
        "{%0,%1,%2,%3}, {%4,%5,%6,%7}, {%8,%9}, {%0,%1,%2,%3};"
        : "+f"(c[0]), "+f"(c[1]), "+f"(c[2]), "+f"(c[3])
        : "r"(a[0]), "r"(a[1]), "r"(a[2]), "r"(a[3]), "r"(b0), "r"(b1));
}
__device__ __forceinline__ float silu_f(float g) { return g / (1.f + expf(-g)); }

// ===================== mma.sync fp16 GEMM (fp32 accum) ======================
#define BM 128
#define BN 128
#define BK 64
#define SROW 72                       // halves per smem row (64 + 8 pad)
#define A_HALVES (128 * SROW)         // 9216
#define B_HALVES (128 * SROW)         // 9216
#define STAGE_B ((A_HALVES + B_HALVES) * 2)   // 36864 bytes
#define NSTAGE 3
#define SMEM_SZ (NSTAGE * STAGE_B)    // 110592; epilogue staging 68096 fits
#define SSTG 133                      // staging stride

__global__ void __launch_bounds__(256, 2) mma_gemm_kernel(
    const fp16* __restrict__ Ah, const fp16* __restrict__ Bh,
    const float* __restrict__ bias, float* __restrict__ C,
    fp16* __restrict__ Ch, fp16* __restrict__ KT, fp16* __restrict__ VT,
    int M, int N, int K, int lda, int ldb, int ldc, int ldch,
    long long sA, long long sB, long long sC, long long sCh,
    int epi, int colLim)
{
    extern __shared__ __align__(16) char smem[];
    const uint32_t sbase = smem_u32(smem);
    const int tid = threadIdx.x;
    const int wid = tid >> 5;
    const int lane = tid & 31;
    const int warp_m = wid & 1;        // 2 m-warps of 64 rows
    const int warp_n = wid >> 1;       // 4 n-warps of 32 cols
    const int bz = blockIdx.z;
    Ah += sA * bz;  Bh += sB * bz;
    if (C)  C  += sC * bz;
    if (Ch) Ch += sCh * bz;
    const int bm = blockIdx.y * BM;
    const int bn = blockIdx.x * BN;

    float acc[4][4][4];
#pragma unroll
    for (int i = 0; i < 4; i++)
#pragma unroll
        for (int j = 0; j < 4; j++)
#pragma unroll
            for (int v = 0; v < 4; v++) acc[i][j][v] = 0.f;

    const uint32_t a_base =
        ((uint32_t)(warp_m * 64 + (lane & 15)) * SROW + ((lane >> 4) * 8)) * 2;
    const uint32_t b_base = (uint32_t)A_HALVES * 2 +
        (((uint32_t)(warp_n * 32 + ((lane >> 4) & 1) * 8 + (lane & 7))) * SROW +
         (((lane >> 3) & 1) * 8)) * 2;

    const int ntiles = (K + BK - 1) / BK;

    // issue one quarter (chunk) of a stage's loads
    auto load_chunk = [&](uint32_t sb, int t, int chunk) {
        int k0 = t * BK;
        {
            int idx = tid + chunk * 256;
            int r = idx >> 3, ch = idx & 7;
            int kc = k0 + ch * 8;
            int ab = 2 * (K - kc); ab = ab < 0 ? 0 : (ab > 16 ? 16 : ab);
            cp16(sb + (r * SROW + ch * 8) * 2, Ah + (long long)(bm + r) * lda + kc, ab);
        }
        {
            int idx = tid + chunk * 256;
            int r = idx >> 3, ch = idx & 7;
            int kc = k0 + ch * 8;
            int ab = 2 * (K - kc); ab = ab < 0 ? 0 : (ab > 16 ? 16 : ab);
            int gn = bn + r;
            int bb = (gn < N) ? ab : 0;
            cp16(sb + A_HALVES * 2 + (r * SROW + ch * 8) * 2,
                 Bh + (long long)(gn < N ? gn : 0) * ldb + kc, bb);
        }
    };
    auto load_stage = [&](int s, int t) {
        uint32_t sb = sbase + s * STAGE_B;
#pragma unroll
        for (int c = 0; c < 4; c++) load_chunk(sb, t, c);
    };

    load_stage(0, 0); CP_COMMIT();
    if (ntiles > 1) load_stage(1, 1);
    CP_COMMIT();

    for (int t = 0; t < ntiles; t++) {
        CP_WAIT(1);
        __syncthreads();
        int ls = t + NSTAGE - 1;
        bool doload = ls < ntiles;
        uint32_t lsb = sbase + (ls % NSTAGE) * STAGE_B;
        uint32_t sb = sbase + (t % NSTAGE) * STAGE_B;
#pragma unroll
        for (int kk = 0; kk < 4; kk++) {
            if (doload) load_chunk(lsb, ls, kk);   // interleaved prefetch issue
            uint32_t a[4][4], b[2][4];
#pragma unroll
            for (int mi = 0; mi < 4; mi++)
                ldmx4(a[mi][0], a[mi][1], a[mi][2], a[mi][3],
                      sb + a_base + (uint32_t)(mi * 16 * SROW * 2) + kk * 32);
#pragma unroll
            for (int p = 0; p < 2; p++)
                ldmx4(b[p][0], b[p][1], b[p][2], b[p][3],
                      sb + b_base + (uint32_t)(p * 16 * SROW * 2) + kk * 32);
#pragma unroll
            for (int mi = 0; mi < 4; mi++)
#pragma unroll
                for (int nj = 0; nj < 4; nj++)
                    mma16816(acc[mi][nj], a[mi], b[nj >> 1][(nj & 1) * 2],
                             b[nj >> 1][(nj & 1) * 2 + 1]);
        }
        CP_COMMIT();
    }
    CP_WAIT(0);
    __syncthreads();

    float* stg = (float*)smem;
    const int gID = lane >> 2, t4 = lane & 3;

    if (epi == 5) {
        // ---- fused silu(gate)*up: nj even = gate, nj odd = up ----
#pragma unroll
        for (int p = 0; p < 2; p++) {
            int bc = bn + warp_n * 32 + p * 16 + 2 * t4;
            float bg0 = bias[bc],     bg1 = bias[bc + 1];
            float bu0 = bias[bc + 8], bu1 = bias[bc + 9];
            int hc = warp_n * 16 + p * 8 + 2 * t4;
#pragma unroll
            for (int mi = 0; mi < 4; mi++) {
                int r0 = warp_m * 64 + mi * 16 + gID;
                float o0 = silu_f(acc[mi][2*p][0] + bg0) * (acc[mi][2*p+1][0] + bu0);
                float o1 = silu_f(acc[mi][2*p][1] + bg1) * (acc[mi][2*p+1][1] + bu1);
                float o2 = silu_f(acc[mi][2*p][2] + bg0) * (acc[mi][2*p+1][2] + bu0);
                float o3 = silu_f(acc[mi][2*p][3] + bg1) * (acc[mi][2*p+1][3] + bu1);
                stg[r0 * SSTG + hc]           = o0;
                stg[r0 * SSTG + hc + 1]       = o1;
                stg[(r0 + 8) * SSTG + hc]     = o2;
                stg[(r0 + 8) * SSTG + hc + 1] = o3;
            }
        }
        __syncthreads();
        int hbase = bn >> 1;
#pragma unroll 4
        for (int it = 0; it < 32; it++) {
            int idx = tid + it * 256;
            int r = idx >> 6, c = idx & 63;
            int hcol = hbase + c;
            if (hcol < HFF)
                Ch[(long long)(bm + r) * ldch + hcol] = __float2half(stg[r * SSTG + c]);
        }
        return;
    }

    // ---- generic: single 128-col pass via SMEM staging ----
#pragma unroll
    for (int mi = 0; mi < 4; mi++)
#pragma unroll
        for (int nj = 0; nj < 4; nj++) {
            int r0 = warp_m * 64 + mi * 16 + gID;
            int c0 = warp_n * 32 + nj * 8 + 2 * t4;
            stg[r0 * SSTG + c0]           = acc[mi][nj][0];
            stg[r0 * SSTG + c0 + 1]       = acc[mi][nj][1];
            stg[(r0 + 8) * SSTG + c0]     = acc[mi][nj][2];
            stg[(r0 + 8) * SSTG + c0 + 1] = acc[mi][nj][3];
        }
    __syncthreads();

    if (epi == 1 && bn >= D_MODEL) {
        // k or v region: transposed coalesced store to KT/VT
        int reg = bn >> 10;                        // 1=k, 2=v
        fp16* T = (reg == 1) ? KT : VT;
        long long tstride = (reg == 1) ? (long long)D_MODEL * SEQ : (long long)DP * SEQ;
        int dbase = bn - reg * 1024;
        int b = bm >> 12, s0v = bm & 4095;
        fp16* Tb = T + (size_t)b * tstride + s0v;
#pragma unroll 4
        for (int it = 0; it < 64; it++) {
            int idx = tid + it * 256;
            int c = idx >> 7, r = idx & 127;
            int gn = bn + c;
            float tv = stg[r * SSTG + c] + (bias ? bias[gn] : 0.f);
            if (reg == 1) tv = (tv > 0.f) ? tv + 1.f : expf(tv);
            Tb[(size_t)(dbase + c) * SEQ + r] = __float2half(tv);
        }
    } else {
#pragma unroll 4
        for (int it = 0; it < 64; it++) {
            int idx = tid + it * 256;
            int r = idx >> 7, c = idx & 127;
            int gm = bm + r, gn = bn + c;
            if (gn < N) {
                float tv = stg[r * SSTG + c] + (bias ? bias[gn] : 0.f);
                float outv;
                if (epi == 1) {
                    outv = (tv > 0.f) ? tv + 1.f : expf(tv);
                } else {
                    outv = tv;
                }
                if (C) C[(long long)gm * ldc + gn] = outv;
                if (Ch && gn < colLim)
                    Ch[(long long)gm * ldch + gn] = __float2half(outv);
            }
        }
    }
}

// ===================== prep kernels (split for stream overlap) ==============
#define NB_CONV (MTOT * D_MODEL / 1024)   // 16384
#define GX_QKV  (D3 / 32)                 // 96
#define NB_QKV  (GX_QKV * (D_MODEL / 32)) // 3072
#define NB_ONES (BATCH * SEQ / 1024)      // 64
#define NB_PREP1 (NB_CONV + NB_QKV + NB_ONES)
#define GX_GU   ((HFF + 31) / 32)         // 86
#define NB_GU   (GX_GU * (D_MODEL / 32))  // 2752
#define GX_WD   (D_MODEL / 32)            // 32
#define NB_WD   (GX_WD * ((HFF + 31) / 32)) // 2752
#define NB_BIAS ((HFF + 255) / 256)       // 11
#define NB_PREP2 (2 * NB_GU + NB_WD + NB_BIAS)

__device__ __forceinline__ void transpose_body(
    const float* in, fp16* oh, int R, int Ccols, int ldi, int ldo,
    int map, int bx, int by, int t, float (*tile)[33])
{
    int r0 = by * 32, c0 = bx * 32;
    int tx = t & 31, ty = t >> 5;
#pragma unroll
    for (int i = 0; i < 32; i += 8) {
        int r = r0 + ty + i, c = c0 + tx;
        tile[ty + i][tx] = (r < R && c < Ccols) ? in[(long long)r * ldi + c] : 0.f;
    }
    __syncthreads();
#pragma unroll
    for (int i = 0; i < 32; i += 8) {
        int r = c0 + ty + i, c = r0 + tx;
        if (r < Ccols && c < R) {
            int rr = r;
            if (map) rr = ((r >> 3) << 4) + (r & 7) + (map == 2 ? 8 : 0);
            oh[(long long)rr * ldo + c] = __float2half(tile[tx][ty + i]);
        }
    }
}

__global__ void __launch_bounds__(256) prep1_kernel(
    const float* __restrict__ x, const float* __restrict__ Wqkv)
{
    __shared__ float tile[32][33];
    int b = blockIdx.x;
    int t = threadIdx.x;
    if (b < NB_CONV) {                    // x -> fp16
        int i = b * 1024 + t * 4;
        float4 v = *(const float4*)(x + i);
        *(__half2*)(g_xh + i)     = __floats2half2_rn(v.x, v.y);
        *(__half2*)(g_xh + i + 2) = __floats2half2_rn(v.z, v.w);
        return;
    }
    b -= NB_CONV;
    if (b < NB_QKV) {
        transpose_body(Wqkv, g_WqkvT, D_MODEL, D3, D3, D_MODEL, 0,
                       b % GX_QKV, b / GX_QKV, t, tile);
        return;
    }
    b -= NB_QKV;
    {                                     // vT ones row (e = 1024)
        int i = b * 1024 + t * 4;
        int bb = i >> 12, s = i & 4095;
        fp16* p = g_vT + (size_t)bb * DP * SEQ + (size_t)1024 * SEQ + s;
        __half2 one2 = __floats2half2_rn(1.f, 1.f);
        *(__half2*)p       = one2;
        *(__half2*)(p + 2) = one2;
    }
}

__global__ void __launch_bounds__(256) prep2_kernel(
    const float* __restrict__ Wg, const float* __restrict__ Wu,
    const float* __restrict__ Wd, const float* __restrict__ bg,
    const float* __restrict__ bu)
{
    __shared__ float tile[32][33];
    int b = blockIdx.x;
    int t = threadIdx.x;
    if (b < NB_GU) {
        transpose_body(Wg, g_WguT, D_MODEL, HFF, HFF, D_MODEL, 1,
                       b % GX_GU, b / GX_GU, t, tile);
        return;
    }
    b -= NB_GU;
    if (b < NB_GU) {
        transpose_body(Wu, g_WguT, D_MODEL, HFF, HFF, D_MODEL, 2,
                       b % GX_GU, b / GX_GU, t, tile);
        return;
    }
    b -= NB_GU;
    if (b < NB_WD) {
        transpose_body(Wd, g_WdT, HFF, D_MODEL, D_MODEL, HFFP, 0,
                       b % GX_WD, b / GX_WD, t, tile);
        return;
    }
    b -= NB_WD;
    {
        int n = b * 256 + t;
        if (n < HFF) {
            int o = ((n >> 3) << 4) + (n & 7);
            g_bgu[o] = bg[n];
            g_bgu[o + 8] = bu[n];
        }
    }
}

// ===================== layernorms ===========================================
__global__ void ln1_kernel(const float* __restrict__ y, const float* __restrict__ x,
                           const float* __restrict__ gamma, const float* __restrict__ beta,
                           fp16* __restrict__ oh)
{
    int row = blockIdx.x;
    int t = threadIdx.x;
    const float4* y4 = (const float4*)(y + (long long)row * YLD);
    float den = y[(long long)row * YLD + 1024] + ATTN_EPS_F;
    float rden = 1.f / den;
    long long base4 = (long long)row * (D_MODEL / 4);
    float4 n4 = y4[t];
    float4 xv = ((const float4*)x)[base4 + t];
    float4 v4;
    v4.x = xv.x + n4.x * rden;
    v4.y = xv.y + n4.y * rden;
    v4.z = xv.z + n4.z * rden;
    v4.w = xv.w + n4.w * rden;
    float s = v4.x + v4.y + v4.z + v4.w;
    __shared__ float red[256];
    red[t] = s; __syncthreads();
    for (int o = 128; o > 0; o >>= 1) { if (t < o) red[t] += red[t + o]; __syncthreads(); }
    float mu = red[0] * (1.f / D_MODEL);
    __syncthreads();
    float dx = v4.x - mu, dy = v4.y - mu, dz = v4.z - mu, dw = v4.w - mu;
    red[t] = dx * dx + dy * dy + dz * dz + dw * dw;
    __syncthreads();
    for (int o = 128; o > 0; o >>= 1) { if (t < o) red[t] += red[t + o]; __syncthreads(); }
    float inv = rsqrtf(red[0] * (1.f / D_MODEL) + LN_EPS_F);
    float4 g4 = ((const float4*)gamma)[t];
    float4 b4 = ((const float4*)beta)[t];
    ((__half2*)oh)[base4 * 2 + 2 * t] =
        __floats2half2_rn(dx * inv * g4.x + b4.x, dy * inv * g4.y + b4.y);
    ((__half2*)oh)[base4 * 2 + 2 * t + 1] =
        __floats2half2_rn(dz * inv * g4.z + b4.z, dw * inv * g4.w + b4.w);
}
__global__ void ln2_kernel(const fp16* __restrict__ in1, const fp16* __restrict__ in2,
                           const float* __restrict__ gamma, const float* __restrict__ beta,
                           float* __restrict__ out)
{
    int row = blockIdx.x;
    int t = threadIdx.x;
    long long base2 = (long long)row * (D_MODEL / 2);
    float2 a0 = __half22float2(((const __half2*)in1)[base2 + 2 * t]);
    float2 a1 = __half22float2(((const __half2*)in1)[base2 + 2 * t + 1]);
    float2 c0 = __half22float2(((const __half2*)in2)[base2 + 2 * t]);
    float2 c1 = __half22float2(((const __half2*)in2)[base2 + 2 * t + 1]);
    float4 v4;
    v4.x = a0.x + c0.x; v4.y = a0.y + c0.y;
    v4.z = a1.x + c1.x; v4.w = a1.y + c1.y;
    float s = v4.x + v4.y + v4.z + v4.w;
    __shared__ float red[256];
    red[t] = s; __syncthreads();
    for (int o = 128; o > 0; o >>= 1) { if (t < o) red[t] += red[t + o]; __syncthreads(); }
    float mu = red[0] * (1.f / D_MODEL);
    __syncthreads();
    float dx = v4.x - mu, dy = v4.y - mu, dz = v4.z - mu, dw = v4.w - mu;
    red[t] = dx * dx + dy * dy + dz * dz + dw * dw;
    __syncthreads();
    for (int o = 128; o > 0; o >>= 1) { if (t < o) red[t] += red[t + o]; __syncthreads(); }
    float inv = rsqrtf(red[0] * (1.f / D_MODEL) + LN_EPS_F);
    float4 g4 = ((const float4*)gamma)[t];
    float4 b4 = ((const float4*)beta)[t];
    float4 o4;
    o4.x = dx * inv * g4.x + b4.x;
    o4.y = dy * inv * g4.y + b4.y;
    o4.z = dz * inv * g4.z + b4.z;
    o4.w = dw * inv * g4.w + b4.w;
    ((float4*)out)[(long long)row * (D_MODEL / 4) + t] = o4;
}

// ===================== launch ===============================================
extern "C" void kernel_launch(void* const* d_in, const int* in_sizes, int n_in,
                              void* d_out, int out_size)
{
    const float* x    = (const float*)d_in[0];
    const float* Wqkv = (const float*)d_in[1];
    const float* bqkv = (const float*)d_in[2];
    const float* Wg   = (const float*)d_in[3];
    const float* bg   = (const float*)d_in[4];
    const float* Wu   = (const float*)d_in[5];
    const float* bu   = (const float*)d_in[6];
    const float* Wd   = (const float*)d_in[7];
    const float* bd   = (const float*)d_in[8];
    const float* g1   = (const float*)d_in[9];
    const float* b1   = (const float*)d_in[10];
    const float* g2   = (const float*)d_in[11];
    const float* b2   = (const float*)d_in[12];
    float* out = (float*)d_out;

    float *yb, *bgu;
    fp16 *qkvh,*xh,*WqkvT,*WguT,*WdT,*kpT,*vT,*kvh,*x1h,*hh,*ffnh;
    cudaGetSymbolAddress((void**)&qkvh, g_qkvh);
    cudaGetSymbolAddress((void**)&yb,   g_y);
    cudaGetSymbolAddress((void**)&bgu,  g_bgu);
    cudaGetSymbolAddress((void**)&xh,   g_xh);
    cudaGetSymbolAddress((void**)&WqkvT,g_WqkvT);
    cudaGetSymbolAddress((void**)&WguT, g_WguT);
    cudaGetSymbolAddress((void**)&WdT,  g_WdT);
    cudaGetSymbolAddress((void**)&kpT,  g_kpT);
    cudaGetSymbolAddress((void**)&vT,   g_vT);
    cudaGetSymbolAddress((void**)&kvh,  g_kvh);
    cudaGetSymbolAddress((void**)&x1h,  g_x1h);
    cudaGetSymbolAddress((void**)&hh,   g_hh);
    cudaGetSymbolAddress((void**)&ffnh, g_ffnh);

    cudaFuncSetAttribute(mma_gemm_kernel,
                         cudaFuncAttributeMaxDynamicSharedMemorySize, SMEM_SZ);

    // lazily created side stream + events (created once; reused every call)
    static cudaStream_t s2 = nullptr;
    static cudaEvent_t evFork = nullptr, evJoin = nullptr;
    if (!s2) {
        cudaStreamCreateWithFlags(&s2, cudaStreamNonBlocking);
        cudaEventCreateWithFlags(&evFork, cudaEventDisableTiming);
        cudaEventCreateWithFlags(&evJoin, cudaEventDisableTiming);
    }

    dim3 blk(256);
    const long long SD3  = (long long)SEQ * D3;
    const long long DS   = (long long)D_MODEL * SEQ;
    const long long VS   = (long long)DP * SEQ;
    const long long KVS  = (long long)DP * D_MODEL;
    const long long YS   = (long long)SEQ * YLD;

    // ---- fork: prep2 (FFN weights) runs concurrent with attention path ----
    cudaEventRecord(evFork, 0);
    cudaStreamWaitEvent(s2, evFork, 0);
    prep2_kernel<<<NB_PREP2, blk, 0, s2>>>(Wg, Wu, Wd, bg, bu);
    cudaEventRecord(evJoin, s2);

    // ---- 0) prep1: x convert + WqkvT + ones-row ----
    prep1_kernel<<<NB_PREP1, blk>>>(x, Wqkv);

    // ---- 1) qkv GEMM: q->qkvh (elu+1), k->kpT (elu+1, transposed), v->vT ----
    mma_gemm_kernel<<<dim3(D3/BN, MTOT/BM, 1), blk, SMEM_SZ>>>(
        xh, WqkvT, bqkv, nullptr, qkvh, kpT, vT,
        MTOT, D3, D_MODEL, D_MODEL, D_MODEL, D3, D3,
        0, 0, 0, 0, 1, D_MODEL);

    // ---- 2) kvh[e][d] = fp16(sum_s vT'[e,s] kp[s,d]), row 1024 = ksum ----
    mma_gemm_kernel<<<dim3(D_MODEL/BN, (1025 + BM - 1)/BM, BATCH), blk, SMEM_SZ>>>(
        vT, kpT, nullptr, nullptr, kvh, nullptr, nullptr,
        1025, D_MODEL, SEQ, SEQ, SEQ, D_MODEL, D_MODEL,
        VS, DS, KVS, KVS, 0, D_MODEL);

    // ---- 3) y[:, 0:1024] = qp @ kv ; y[:, 1024] = den ----
    mma_gemm_kernel<<<dim3((1025 + BN - 1)/BN, SEQ/BM, BATCH), blk, SMEM_SZ>>>(
        qkvh, kvh, nullptr, yb, nullptr, nullptr, nullptr,
        SEQ, 1025, D_MODEL, D3, D_MODEL, YLD, YLD,
        SD3, KVS, YS, YS, 0, 0);

    // ---- 4) x1h = fp16(LN(x + num/den)) ----
    ln1_kernel<<<MTOT, blk>>>(yb, x, g1, b1, x1h);

    // ---- join: FFN weights must be ready ----
    cudaStreamWaitEvent(0, evJoin, 0);

    // ---- 5+6) hh = fp16(silu(x1@Wg+bg) * (x1@Wu+bu)) ----
    mma_gemm_kernel<<<dim3((NGU+BN-1)/BN, MTOT/BM, 1), blk, SMEM_SZ>>>(
        x1h, WguT, bgu, nullptr, hh, nullptr, nullptr,
        MTOT, NGU, D_MODEL, D_MODEL, D_MODEL, NGU, HFFP,
        0, 0, 0, 0, 5, HFF);

    // ---- 7) ffnh = fp16(h @ Wd + bd) ----
    mma_gemm_kernel<<<dim3(D_MODEL/BN, MTOT/BM, 1), blk, SMEM_SZ>>>(
        hh, WdT, bd, nullptr, ffnh, nullptr, nullptr,
        MTOT, D_MODEL, HFF, HFFP, HFFP, D_MODEL, D_MODEL,
        0, 0, 0, 0, 0, D_MODEL);

    // ---- 8) out = LN(x1h + ffnh) ----
    ln2_kernel<<<MTOT, blk>>>(x1h, ffnh, g2, b2, out);
}

// round 16
// speedup vs baseline: 10.1315x; 1.0111x over previous
#include <cuda_runtime.h>
#include <cuda_fp16.h>
#include <cstdint>
#include <math.h>

#define D_MODEL 1024
#define D3      3072
#define HFF     2730
#define HFFP    2736                 // HFF padded to 8-element (16B) multiple
#define NGU     5472                 // interleaved gate/up N (2*2736)
#define BATCH   4
#define SEQ     4096
#define MTOT    (BATCH*SEQ)          // 16384
#define DP      1152                 // padded e-dim (1025 rounded up)
#define YLD     1032                 // y row stride (1024 num + den + pad)
#define QP_INV  0.015625f            // qp scale 1/64 (fp16-exact)
#define DEN_RESCALE 262144.f         // 64 * 4096
#define NUM_RESCALE 64.f

#define LN_EPS_F   1e-5f
#define ATTN_EPS_F 1e-6f

typedef __half fp16;

// ===================== scratch ==============================================
__device__ fp16  g_qph [(size_t)MTOT * D_MODEL];    // qp' = (elu(q)+1)/64, ld=1024
__device__ fp16  g_xh  [(size_t)MTOT * D_MODEL];
__device__ fp16  g_WqkvT[(size_t)D3 * D_MODEL];
__device__ fp16  g_WguT[(size_t)NGU * D_MODEL];     // interleaved gate/up rows
__device__ float g_bgu [5632];                      // interleaved biases
__device__ fp16  g_WdT [(size_t)D_MODEL * HFFP];    // padded ld
__device__ fp16  g_kpT [(size_t)BATCH * D_MODEL * SEQ];
__device__ fp16  g_vT  [(size_t)BATCH * DP * SEQ];  // row 1024 = 1/4096; 1025+ zero
__device__ fp16  g_kvh [(size_t)BATCH * DP * D_MODEL]; // row 1024 = ksum/4096
__device__ fp16  g_yh [(size_t)MTOT * YLD];         // num' cols 0..1023, den' col 1024
__device__ fp16  g_x1h[(size_t)MTOT * D_MODEL];     // LN1 out (fp16 only)
__device__ fp16  g_hh[(size_t)MTOT * HFFP];         // fused silu(gate)*up
__device__ fp16  g_ffnh[(size_t)MTOT * D_MODEL];    // down-proj out (fp16)

// ===================== helpers ==============================================
__device__ __forceinline__ uint32_t smem_u32(const void* p) {
    uint32_t a;
    asm("{ .reg .u64 t; cvta.to.shared.u64 t, %1; cvt.u32.u64 %0, t; }" : "=r"(a) : "l"(p));
    return a;
}
__device__ __forceinline__ void cp16(uint32_t dst, const void* src, int bytes) {
    asm volatile("cp.async.cg.shared.global [%0], [%1], 16, %2;\n"
        :: "r"(dst), "l"(src), "r"(bytes));
}
#define CP_COMMIT() asm volatile("cp.async.commit_group;\n" ::: "memory")
#define CP_WAIT(n)  asm volatile("cp.async.wait_group %0;\n" :: "n"(n) : "memory")

__device__ __forceinline__ void ldmx4(uint32_t& r0, uint32_t& r1, uint32_t& r2,
                                      uint32_t& r3, uint32_t addr) {
    asm volatile("ldmatrix.sync.aligned.m8n8.x4.shared.b16 {%0,%1,%2,%3}, [%4];"
        : "=r"(r0), "=r"(r1), "=r"(r2), "=r"(r3) : "r"(addr));
}
__device__ __forceinline__ void mma16816(float* c, const uint32_t* a, uint32_t b0, uint32_t b1) {
    asm volatile(
        "mma.sync.aligned.m16n8k16.row.col.f32.f16.f16.f32 "
        "{%0,%1,%2,%3}, {%4,%5,%6,%7}, {%8,%9}, {%0,%1,%2,%3};"
        : "+f"(c[0]), "+f"(c[1]), "+f"(c[2]), "+f"(c[3])
        : "r"(a[0]), "r"(a[1]), "r"(a[2]), "r"(a[3]), "r"(b0), "r"(b1));
}
__device__ __forceinline__ float silu_f(float g) { return g / (1.f + expf(-g)); }

// ===================== mma.sync fp16 GEMM (fp32 accum) ======================
#define BM 128
#define BN 128
#define BK 64
#define SROW 72                       // halves per smem row (64 + 8 pad)
#define A_HALVES (128 * SROW)         // 9216
#define B_HALVES (128 * SROW)         // 9216
#define STAGE_B ((A_HALVES + B_HALVES) * 2)   // 36864 bytes
#define NSTAGE 3
#define SMEM_SZ (NSTAGE * STAGE_B)    // 110592; epilogue staging 68096 fits
#define SSTG 133                      // staging stride

__global__ void __launch_bounds__(256, 2) mma_gemm_kernel(
    const fp16* __restrict__ Ah, const fp16* __restrict__ Bh,
    const float* __restrict__ bias, float* __restrict__ C,
    fp16* __restrict__ Ch, fp16* __restrict__ KT, fp16* __restrict__ VT,
    int M, int N, int K, int lda, int ldb, int ldc, int ldch,
    long long sA, long long sB, long long sC, long long sCh,
    int epi, int colLim)
{
    extern __shared__ __align__(16) char smem[];
    const uint32_t sbase = smem_u32(smem);
    const int tid = threadIdx.x;
    const int wid = tid >> 5;
    const int lane = tid & 31;
    const int warp_m = wid & 1;        // 2 m-warps of 64 rows
    const int warp_n = wid >> 1;       // 4 n-warps of 32 cols
    const int bz = blockIdx.z;
    Ah += sA * bz;  Bh += sB * bz;
    if (C)  C  += sC * bz;
    if (Ch) Ch += sCh * bz;
    const int bm = blockIdx.y * BM;
    const int bn = blockIdx.x * BN;

    float acc[4][4][4];
#pragma unroll
    for (int i = 0; i < 4; i++)
#pragma unroll
        for (int j = 0; j < 4; j++)
#pragma unroll
            for (int v = 0; v < 4; v++) acc[i][j][v] = 0.f;

    const uint32_t a_base =
        ((uint32_t)(warp_m * 64 + (lane & 15)) * SROW + ((lane >> 4) * 8)) * 2;
    const uint32_t b_base = (uint32_t)A_HALVES * 2 +
        (((uint32_t)(warp_n * 32 + ((lane >> 4) & 1) * 8 + (lane & 7))) * SROW +
         (((lane >> 3) & 1) * 8)) * 2;

    const int ntiles = (K + BK - 1) / BK;

    // issue one quarter (chunk) of a stage's loads
    auto load_chunk = [&](uint32_t sb, int t, int chunk) {
        int k0 = t * BK;
        {
            int idx = tid + chunk * 256;
            int r = idx >> 3, ch = idx & 7;
            int kc = k0 + ch * 8;
            int ab = 2 * (K - kc); ab = ab < 0 ? 0 : (ab > 16 ? 16 : ab);
            cp16(sb + (r * SROW + ch * 8) * 2, Ah + (long long)(bm + r) * lda + kc, ab);
        }
        {
            int idx = tid + chunk * 256;
            int r = idx >> 3, ch = idx & 7;
            int kc = k0 + ch * 8;
            int ab = 2 * (K - kc); ab = ab < 0 ? 0 : (ab > 16 ? 16 : ab);
            int gn = bn + r;
            int bb = (gn < N) ? ab : 0;
            cp16(sb + A_HALVES * 2 + (r * SROW + ch * 8) * 2,
                 Bh + (long long)(gn < N ? gn : 0) * ldb + kc, bb);
        }
    };
    auto load_stage = [&](int s, int t) {
        uint32_t sb = sbase + s * STAGE_B;
#pragma unroll
        for (int c = 0; c < 4; c++) load_chunk(sb, t, c);
    };

    load_stage(0, 0); CP_COMMIT();
    if (ntiles > 1) load_stage(1, 1);
    CP_COMMIT();

    for (int t = 0; t < ntiles; t++) {
        CP_WAIT(1);
        __syncthreads();
        int ls = t + NSTAGE - 1;
        bool doload = ls < ntiles;
        uint32_t lsb = sbase + (ls % NSTAGE) * STAGE_B;
        uint32_t sb = sbase + (t % NSTAGE) * STAGE_B;
#pragma unroll
        for (int kk = 0; kk < 4; kk++) {
            if (doload) load_chunk(lsb, ls, kk);   // interleaved prefetch issue
            uint32_t a[4][4], b[2][4];
#pragma unroll
            for (int mi = 0; mi < 4; mi++)
                ldmx4(a[mi][0], a[mi][1], a[mi][2], a[mi][3],
                      sb + a_base + (uint32_t)(mi * 16 * SROW * 2) + kk * 32);
#pragma unroll
            for (int p = 0; p < 2; p++)
                ldmx4(b[p][0], b[p][1], b[p][2], b[p][3],
                      sb + b_base + (uint32_t)(p * 16 * SROW * 2) + kk * 32);
#pragma unroll
            for (int mi = 0; mi < 4; mi++)
#pragma unroll
                for (int nj = 0; nj < 4; nj++)
                    mma16816(acc[mi][nj], a[mi], b[nj >> 1][(nj & 1) * 2],
                             b[nj >> 1][(nj & 1) * 2 + 1]);
        }
        CP_COMMIT();
    }
    CP_WAIT(0);
    __syncthreads();

    float* stg = (float*)smem;
    const int gID = lane >> 2, t4 = lane & 3;

    if (epi == 5) {
        // ---- fused silu(gate)*up: nj even = gate, nj odd = up ----
#pragma unroll
        for (int p = 0; p < 2; p++) {
            int bc = bn + warp_n * 32 + p * 16 + 2 * t4;
            float bg0 = bias[bc],     bg1 = bias[bc + 1];
            float bu0 = bias[bc + 8], bu1 = bias[bc + 9];
            int hc = warp_n * 16 + p * 8 + 2 * t4;
#pragma unroll
            for (int mi = 0; mi < 4; mi++) {
                int r0 = warp_m * 64 + mi * 16 + gID;
                float o0 = silu_f(acc[mi][2*p][0] + bg0) * (acc[mi][2*p+1][0] + bu0);
                float o1 = silu_f(acc[mi][2*p][1] + bg1) * (acc[mi][2*p+1][1] + bu1);
                float o2 = silu_f(acc[mi][2*p][2] + bg0) * (acc[mi][2*p+1][2] + bu0);
                float o3 = silu_f(acc[mi][2*p][3] + bg1) * (acc[mi][2*p+1][3] + bu1);
                stg[r0 * SSTG + hc]           = o0;
                stg[r0 * SSTG + hc + 1]       = o1;
                stg[(r0 + 8) * SSTG + hc]     = o2;
                stg[(r0 + 8) * SSTG + hc + 1] = o3;
            }
        }
        __syncthreads();
        int hbase = bn >> 1;
#pragma unroll 4
        for (int it = 0; it < 32; it++) {
            int idx = tid + it * 256;
            int r = idx >> 6, c = idx & 63;
            int hcol = hbase + c;
            if (hcol < HFF)
                Ch[(long long)(bm + r) * ldch + hcol] = __float2half(stg[r * SSTG + c]);
        }
        return;
    }

    // ---- generic: single 128-col pass via SMEM staging ----
#pragma unroll
    for (int mi = 0; mi < 4; mi++)
#pragma unroll
        for (int nj = 0; nj < 4; nj++) {
            int r0 = warp_m * 64 + mi * 16 + gID;
            int c0 = warp_n * 32 + nj * 8 + 2 * t4;
            stg[r0 * SSTG + c0]           = acc[mi][nj][0];
            stg[r0 * SSTG + c0 + 1]       = acc[mi][nj][1];
            stg[(r0 + 8) * SSTG + c0]     = acc[mi][nj][2];
            stg[(r0 + 8) * SSTG + c0 + 1] = acc[mi][nj][3];
        }
    __syncthreads();

    if (epi == 1 && bn >= D_MODEL) {
        // k or v region: transposed coalesced store to KT/VT
        int reg = bn >> 10;                        // 1=k, 2=v
        fp16* T = (reg == 1) ? KT : VT;
        long long tstride = (reg == 1) ? (long long)D_MODEL * SEQ : (long long)DP * SEQ;
        int dbase = bn - reg * 1024;
        int b = bm >> 12, s0v = bm & 4095;
        fp16* Tb = T + (size_t)b * tstride + s0v;
#pragma unroll 4
        for (int it = 0; it < 64; it++) {
            int idx = tid + it * 256;
            int c = idx >> 7, r = idx & 127;
            int gn = bn + c;
            float tv = stg[r * SSTG + c] + (bias ? bias[gn] : 0.f);
            if (reg == 1) tv = (tv > 0.f) ? tv + 1.f : expf(tv);
            Tb[(size_t)(dbase + c) * SEQ + r] = __float2half(tv);
        }
    } else {
#pragma unroll 4
        for (int it = 0; it < 64; it++) {
            int idx = tid + it * 256;
            int r = idx >> 7, c = idx & 127;
            int gm = bm + r, gn = bn + c;
            if (gn < N) {
                float tv = stg[r * SSTG + c] + (bias ? bias[gn] : 0.f);
                float outv;
                if (epi == 1) {                // q cols: (elu+1)/64 (fp16 range)
                    outv = ((tv > 0.f) ? tv + 1.f : expf(tv)) * QP_INV;
                } else {
                    outv = tv;
                }
                if (C) C[(long long)gm * ldc + gn] = outv;
                if (Ch && gn < colLim)
                    Ch[(long long)gm * ldch + gn] = __float2half(outv);
            }
        }
    }
}

// ===================== prep kernels (split for stream overlap) ==============
#define NB_CONV (MTOT * D_MODEL / 2048)   // 8192 (8 elems/thread, 16B stores)
#define GX_QKV  (D3 / 32)                 // 96
#define NB_QKV  (GX_QKV * (D_MODEL / 32)) // 3072
#define NB_ONES (BATCH * SEQ / 1024)      // 64
#define NB_PREP1 (NB_CONV + NB_QKV + NB_ONES)
#define GX_GU   ((HFF + 31) / 32)         // 86
#define NB_GU   (GX_GU * (D_MODEL / 32))  // 2752
#define GX_WD   (D_MODEL / 32)            // 32
#define NB_WD   (GX_WD * ((HFF + 31) / 32)) // 2752
#define NB_BIAS ((HFF + 255) / 256)       // 11
#define NB_PREP2 (2 * NB_GU + NB_WD + NB_BIAS)

__device__ __forceinline__ void transpose_body(
    const float* in, fp16* oh, int R, int Ccols, int ldi, int ldo,
    int map, int bx, int by, int t, float (*tile)[33])
{
    int r0 = by * 32, c0 = bx * 32;
    int tx = t & 31, ty = t >> 5;
#pragma unroll
    for (int i = 0; i < 32; i += 8) {
        int r = r0 + ty + i, c = c0 + tx;
        tile[ty + i][tx] = (r < R && c < Ccols) ? in[(long long)r * ldi + c] : 0.f;
    }
    __syncthreads();
#pragma unroll
    for (int i = 0; i < 32; i += 8) {
        int r = c0 + ty + i, c = r0 + tx;
        if (r < Ccols && c < R) {
            int rr = r;
            if (map) rr = ((r >> 3) << 4) + (r & 7) + (map == 2 ? 8 : 0);
            oh[(long long)rr * ldo + c] = __float2half(tile[tx][ty + i]);
        }
    }
}

__global__ void __launch_bounds__(256) prep1_kernel(
    const float* __restrict__ x, const float* __restrict__ Wqkv)
{
    __shared__ float tile[32][33];
    int b = blockIdx.x;
    int t = threadIdx.x;
    if (b < NB_CONV) {                    // x -> fp16 (8 elems/thread)
        int i = b * 2048 + t * 8;
        float4 v0 = *(const float4*)(x + i);
        float4 v1 = *(const float4*)(x + i + 4);
        uint4 o;
        *(__half2*)&o.x = __floats2half2_rn(v0.x, v0.y);
        *(__half2*)&o.y = __floats2half2_rn(v0.z, v0.w);
        *(__half2*)&o.z = __floats2half2_rn(v1.x, v1.y);
        *(__half2*)&o.w = __floats2half2_rn(v1.z, v1.w);
        *(uint4*)(g_xh + i) = o;
        return;
    }
    b -= NB_CONV;
    if (b < NB_QKV) {
        transpose_body(Wqkv, g_WqkvT, D_MODEL, D3, D3, D_MODEL, 0,
                       b % GX_QKV, b / GX_QKV, t, tile);
        return;
    }
    b -= NB_QKV;
    {                                     // vT scale row (e = 1024): 1/4096
        int i = b * 1024 + t * 4;
        int bb = i >> 12, s = i & 4095;
        fp16* p = g_vT + (size_t)bb * DP * SEQ + (size_t)1024 * SEQ + s;
        __half2 sc2 = __floats2half2_rn(1.f / 4096.f, 1.f / 4096.f);
        *(__half2*)p       = sc2;
        *(__half2*)(p + 2) = sc2;
    }
}

__global__ void __launch_bounds__(256) prep2_kernel(
    const float* __restrict__ Wg, const float* __restrict__ Wu,
    const float* __restrict__ Wd, const float* __restrict__ bg,
    const float* __restrict__ bu)
{
    __shared__ float tile[32][33];
    int b = blockIdx.x;
    int t = threadIdx.x;
    if (b < NB_GU) {
        transpose_body(Wg, g_WguT, D_MODEL, HFF, HFF, D_MODEL, 1,
                       b % GX_GU, b / GX_GU, t, tile);
        return;
    }
    b -= NB_GU;
    if (b < NB_GU) {
        transpose_body(Wu, g_WguT, D_MODEL, HFF, HFF, D_MODEL, 2,
                       b % GX_GU, b / GX_GU, t, tile);
        return;
    }
    b -= NB_GU;
    if (b < NB_WD) {
        transpose_body(Wd, g_WdT, HFF, D_MODEL, D_MODEL, HFFP, 0,
                       b % GX_WD, b / GX_WD, t, tile);
        return;
    }
    b -= NB_WD;
    {
        int n = b * 256 + t;
        if (n < HFF) {
            int o = ((n >> 3) << 4) + (n & 7);
            g_bgu[o] = bg[n];
            g_bgu[o + 8] = bu[n];
        }
    }
}

// ===================== layernorms ===========================================
// LN1: attn = num'*64 / (den'*262144 + eps); LN(x + attn) -> fp16 x1h.
__global__ void ln1_kernel(const fp16* __restrict__ yh, const float* __restrict__ x,
                           const float* __restrict__ gamma, const float* __restrict__ beta,
                           fp16* __restrict__ oh)
{
    int row = blockIdx.x;
    int t = threadIdx.x;
    const fp16* yr = yh + (long long)row * YLD;
    float den = __half2float(yr[1024]) * DEN_RESCALE + ATTN_EPS_F;
    float rden = NUM_RESCALE / den;
    long long base4 = (long long)row * (D_MODEL / 4);
    uint2 nraw = *(const uint2*)(yr + 4 * t);
    float2 n0 = __half22float2(*(__half2*)&nraw.x);
    float2 n1 = __half22float2(*(__half2*)&nraw.y);
    float4 xv = ((const float4*)x)[base4 + t];
    float4 v4;
    v4.x = xv.x + n0.x * rden;
    v4.y = xv.y + n0.y * rden;
    v4.z = xv.z + n1.x * rden;
    v4.w = xv.w + n1.y * rden;
    float s = v4.x + v4.y + v4.z + v4.w;
    __shared__ float red[256];
    red[t] = s; __syncthreads();
    for (int o = 128; o > 0; o >>= 1) { if (t < o) red[t] += red[t + o]; __syncthreads(); }
    float mu = red[0] * (1.f / D_MODEL);
    __syncthreads();
    float dx = v4.x - mu, dy = v4.y - mu, dz = v4.z - mu, dw = v4.w - mu;
    red[t] = dx * dx + dy * dy + dz * dz + dw * dw;
    __syncthreads();
    for (int o = 128; o > 0; o >>= 1) { if (t < o) red[t] += red[t + o]; __syncthreads(); }
    float inv = rsqrtf(red[0] * (1.f / D_MODEL) + LN_EPS_F);
    float4 g4 = ((const float4*)gamma)[t];
    float4 b4 = ((const float4*)beta)[t];
    ((__half2*)oh)[base4 * 2 + 2 * t] =
        __floats2half2_rn(dx * inv * g4.x + b4.x, dy * inv * g4.y + b4.y);
    ((__half2*)oh)[base4 * 2 + 2 * t + 1] =
        __floats2half2_rn(dz * inv * g4.z + b4.z, dw * inv * g4.w + b4.w);
}
__global__ void ln2_kernel(const fp16* __restrict__ in1, const fp16* __restrict__ in2,
                           const float* __restrict__ gamma, const float* __restrict__ beta,
                           float* __restrict__ out)
{
    int row = blockIdx.x;
    int t = threadIdx.x;
    long long base2 = (long long)row * (D_MODEL / 2);
    float2 a0 = __half22float2(((const __half2*)in1)[base2 + 2 * t]);
    float2 a1 = __half22float2(((const __half2*)in1)[base2 + 2 * t + 1]);
    float2 c0 = __half22float2(((const __half2*)in2)[base2 + 2 * t]);
    float2 c1 = __half22float2(((const __half2*)in2)[base2 + 2 * t + 1]);
    float4 v4;
    v4.x = a0.x + c0.x; v4.y = a0.y + c0.y;
    v4.z = a1.x + c1.x; v4.w = a1.y + c1.y;
    float s = v4.x + v4.y + v4.z + v4.w;
    __shared__ float red[256];
    red[t] = s; __syncthreads();
    for (int o = 128; o > 0; o >>= 1) { if (t < o) red[t] += red[t + o]; __syncthreads(); }
    float mu = red[0] * (1.f / D_MODEL);
    __syncthreads();
    float dx = v4.x - mu, dy = v4.y - mu, dz = v4.z - mu, dw = v4.w - mu;
    red[t] = dx * dx + dy * dy + dz * dz + dw * dw;
    __syncthreads();
    for (int o = 128; o > 0; o >>= 1) { if (t < o) red[t] += red[t + o]; __syncthreads(); }
    float inv = rsqrtf(red[0] * (1.f / D_MODEL) + LN_EPS_F);
    float4 g4 = ((const float4*)gamma)[t];
    float4 b4 = ((const float4*)beta)[t];
    float4 o4;
    o4.x = dx * inv * g4.x + b4.x;
    o4.y = dy * inv * g4.y + b4.y;
    o4.z = dz * inv * g4.z + b4.z;
    o4.w = dw * inv * g4.w + b4.w;
    ((float4*)out)[(long long)row * (D_MODEL / 4) + t] = o4;
}

// ===================== launch ===============================================
extern "C" void kernel_launch(void* const* d_in, const int* in_sizes, int n_in,
                              void* d_out, int out_size)
{
    const float* x    = (const float*)d_in[0];
    const float* Wqkv = (const float*)d_in[1];
    const float* bqkv = (const float*)d_in[2];
    const float* Wg   = (const float*)d_in[3];
    const float* bg   = (const float*)d_in[4];
    const float* Wu   = (const float*)d_in[5];
    const float* bu   = (const float*)d_in[6];
    const float* Wd   = (const float*)d_in[7];
    const float* bd   = (const float*)d_in[8];
    const float* g1   = (const float*)d_in[9];
    const float* b1   = (const float*)d_in[10];
    const float* g2   = (const float*)d_in[11];
    const float* b2   = (const float*)d_in[12];
    float* out = (float*)d_out;

    float *bgu;
    fp16 *qph,*xh,*WqkvT,*WguT,*WdT,*kpT,*vT,*kvh,*yh,*x1h,*hh,*ffnh;
    cudaGetSymbolAddress((void**)&qph,  g_qph);
    cudaGetSymbolAddress((void**)&yh,   g_yh);
    cudaGetSymbolAddress((void**)&bgu,  g_bgu);
    cudaGetSymbolAddress((void**)&xh,   g_xh);
    cudaGetSymbolAddress((void**)&WqkvT,g_WqkvT);
    cudaGetSymbolAddress((void**)&WguT, g_WguT);
    cudaGetSymbolAddress((void**)&WdT,  g_WdT);
    cudaGetSymbolAddress((void**)&kpT,  g_kpT);
    cudaGetSymbolAddress((void**)&vT,   g_vT);
    cudaGetSymbolAddress((void**)&kvh,  g_kvh);
    cudaGetSymbolAddress((void**)&x1h,  g_x1h);
    cudaGetSymbolAddress((void**)&hh,   g_hh);
    cudaGetSymbolAddress((void**)&ffnh, g_ffnh);

    cudaFuncSetAttribute(mma_gemm_kernel,
                         cudaFuncAttributeMaxDynamicSharedMemorySize, SMEM_SZ);

    // lazily created side stream + events (created once; reused every call)
    static cudaStream_t s2 = nullptr;
    static cudaEvent_t evFork = nullptr, evJoin = nullptr;
    if (!s2) {
        cudaStreamCreateWithFlags(&s2, cudaStreamNonBlocking);
        cudaEventCreateWithFlags(&evFork, cudaEventDisableTiming);
        cudaEventCreateWithFlags(&evJoin, cudaEventDisableTiming);
    }

    dim3 blk(256);
    const long long SDM  = (long long)SEQ * D_MODEL;
    const long long DS   = (long long)D_MODEL * SEQ;
    const long long VS   = (long long)DP * SEQ;
    const long long KVS  = (long long)DP * D_MODEL;
    const long long YS   = (long long)SEQ * YLD;

    // ---- fork: prep2 (FFN weights) runs concurrent with attention path ----
    cudaEventRecord(evFork, 0);
    cudaStreamWaitEvent(s2, evFork, 0);
    prep2_kernel<<<NB_PREP2, blk, 0, s2>>>(Wg, Wu, Wd, bg, bu);
    cudaEventRecord(evJoin, s2);

    // ---- 0) prep1: x convert + WqkvT + scale-row ----
    prep1_kernel<<<NB_PREP1, blk>>>(x, Wqkv);

    // ---- 1) qkv GEMM: q->qph ((elu+1)/64), k->kpT (elu+1, transp), v->vT ----
    mma_gemm_kernel<<<dim3(D3/BN, MTOT/BM, 1), blk, SMEM_SZ>>>(
        xh, WqkvT, bqkv, nullptr, qph, kpT, vT,
        MTOT, D3, D_MODEL, D_MODEL, D_MODEL, D_MODEL, D_MODEL,
        0, 0, 0, 0, 1, D_MODEL);

    // ---- 2) kvh[e][d] = fp16(sum_s vT'[e,s] kp[s,d]); row 1024 = ksum/4096 ----
    mma_gemm_kernel<<<dim3(D_MODEL/BN, (1025 + BM - 1)/BM, BATCH), blk, SMEM_SZ>>>(
        vT, kpT, nullptr, nullptr, kvh, nullptr, nullptr,
        1025, D_MODEL, SEQ, SEQ, SEQ, D_MODEL, D_MODEL,
        VS, DS, KVS, KVS, 0, D_MODEL);

    // ---- 3) yh[:, 0:1024] = fp16(qp' @ kv) ; yh[:, 1024] = den/(64*4096) ----
    mma_gemm_kernel<<<dim3((1025 + BN - 1)/BN, SEQ/BM, BATCH), blk, SMEM_SZ>>>(
        qph, kvh, nullptr, nullptr, yh, nullptr, nullptr,
        SEQ, 1025, D_MODEL, D_MODEL, D_MODEL, YLD, YLD,
        SDM, KVS, YS, YS, 0, 1025);

    // ---- 4) x1h = fp16(LN(x + num'*64/den_full)) ----
    ln1_kernel<<<MTOT, blk>>>(yh, x, g1, b1, x1h);

    // ---- join: FFN weights must be ready ----
    cudaStreamWaitEvent(0, evJoin, 0);

    // ---- 5+6) hh = fp16(silu(x1@Wg+bg) * (x1@Wu+bu)) ----
    mma_gemm_kernel<<<dim3((NGU+BN-1)/BN, MTOT/BM, 1), blk, SMEM_SZ>>>(
        x1h, WguT, bgu, nullptr, hh, nullptr, nullptr,
        MTOT, NGU, D_MODEL, D_MODEL, D_MODEL, NGU, HFFP,
        0, 0, 0, 0, 5, HFF);

    // ---- 7) ffnh = fp16(h @ Wd + bd) ----
    mma_gemm_kernel<<<dim3(D_MODEL/BN, MTOT/BM, 1), blk, SMEM_SZ>>>(
        hh, WdT, bd, nullptr, ffnh, nullptr, nullptr,
        MTOT, D_MODEL, HFF, HFFP, HFFP, D_MODEL, D_MODEL,
        0, 0, 0, 0, 0, D_MODEL);

    // ---- 8) out = LN(x1h + ffnh) ----
    ln2_kernel<<<MTOT, blk>>>(x1h, ffnh, g2, b2, out);
}

// round 17
// speedup vs baseline: 10.1700x; 1.0038x over previous
#include <cuda_runtime.h>
#include <cuda_fp16.h>
#include <cstdint>
#include <math.h>

#define D_MODEL 1024
#define D3      3072
#define HFF     2730
#define HFFP    2736                 // HFF padded to 8-element (16B) multiple
#define NGU     5472                 // interleaved gate/up N (2*2736)
#define BATCH   4
#define SEQ     4096
#define MTOT    (BATCH*SEQ)          // 16384
#define DP      1152                 // padded e-dim (1025 rounded up)
#define YLD     1032                 // y row stride (1024 num + den + pad)
#define QP_INV  0.015625f            // qp scale 1/64 (fp16-exact)
#define DEN_RESCALE 262144.f         // 64 * 4096
#define NUM_RESCALE 64.f

#define LN_EPS_F   1e-5f
#define ATTN_EPS_F 1e-6f

typedef __half fp16;

// ===================== scratch ==============================================
__device__ fp16  g_qph [(size_t)MTOT * D_MODEL];    // qp' = (elu(q)+1)/64, ld=1024
__device__ fp16  g_xh  [(size_t)MTOT * D_MODEL];
__device__ fp16  g_WqkvT[(size_t)D3 * D_MODEL];
__device__ fp16  g_WguT[(size_t)NGU * D_MODEL];     // interleaved gate/up rows
__device__ float g_bgu [5632];                      // interleaved biases
__device__ fp16  g_WdT [(size_t)D_MODEL * HFFP];    // padded ld
__device__ fp16  g_kpT [(size_t)BATCH * D_MODEL * SEQ];
__device__ fp16  g_vT  [(size_t)BATCH * DP * SEQ];  // row 1024 = 1/4096; 1025+ zero
__device__ fp16  g_kvh [(size_t)BATCH * DP * D_MODEL]; // row 1024 = ksum/4096
__device__ fp16  g_yh [(size_t)MTOT * YLD];         // num' cols 0..1023, den' col 1024
__device__ fp16  g_x1h[(size_t)MTOT * D_MODEL];     // LN1 out (fp16 only)
__device__ fp16  g_hh[(size_t)MTOT * HFFP];         // fused silu(gate)*up
__device__ fp16  g_ffnh[(size_t)MTOT * D_MODEL];    // down-proj out (fp16)

// ===================== helpers ==============================================
__device__ __forceinline__ uint32_t smem_u32(const void* p) {
    uint32_t a;
    asm("{ .reg .u64 t; cvta.to.shared.u64 t, %1; cvt.u32.u64 %0, t; }" : "=r"(a) : "l"(p));
    return a;
}
__device__ __forceinline__ void cp16(uint32_t dst, const void* src, int bytes) {
    asm volatile("cp.async.cg.shared.global [%0], [%1], 16, %2;\n"
        :: "r"(dst), "l"(src), "r"(bytes));
}
#define CP_COMMIT() asm volatile("cp.async.commit_group;\n" ::: "memory")
#define CP_WAIT(n)  asm volatile("cp.async.wait_group %0;\n" :: "n"(n) : "memory")

__device__ __forceinline__ void ldmx4(uint32_t& r0, uint32_t& r1, uint32_t& r2,
                                      uint32_t& r3, uint32_t addr) {
    asm volatile("ldmatrix.sync.aligned.m8n8.x4.shared.b16 {%0,%1,%2,%3}, [%4];"
        : "=r"(r0), "=r"(r1), "=r"(r2), "=r"(r3) : "r"(addr));
}
__device__ __forceinline__ void mma16816(float* c, const uint32_t* a, uint32_t b0, uint32_t b1) {
    asm volatile(
        "mma.sync.aligned.m16n8k16.row.col.f32.f16.f16.f32 "
        "{%0,%1,%2,%3}, {%4,%5,%6,%7}, {%8,%9}, {%0,%1,%2,%3};"
        : "+f"(c[0]), "+f"(c[1]), "+f"(c[2]), "+f"(c[3])
        : "r"(a[0]), "r"(a[1]), "r"(a[2]), "r"(a[3]), "r"(b0), "r"(b1));
}
__device__ __forceinline__ float silu_f(float g) { return g / (1.f + expf(-g)); }

// ===================== mma.sync fp16 GEMM (fp32 accum) ======================
#define BM 128
#define BN 128
#define BK 64
#define SROW 72                       // halves per smem row (64 + 8 pad)
#define A_HALVES (128 * SROW)         // 9216
#define B_HALVES (128 * SROW)         // 9216
#define STAGE_B ((A_HALVES + B_HALVES) * 2)   // 36864 bytes
#define NSTAGE 3
#define SMEM_SZ (NSTAGE * STAGE_B)    // 110592; epilogue staging 68096 fits
#define SSTG 133                      // staging stride

__global__ void __launch_bounds__(256, 2) mma_gemm_kernel(
    const fp16* __restrict__ Ah, const fp16* __restrict__ Bh,
    const float* __restrict__ bias, float* __restrict__ C,
    fp16* __restrict__ Ch, fp16* __restrict__ KT, fp16* __restrict__ VT,
    int M, int N, int K, int lda, int ldb, int ldc, int ldch,
    long long sA, long long sB, long long sC, long long sCh,
    int epi, int colLim, int bnOff)
{
    extern __shared__ __align__(16) char smem[];
    const uint32_t sbase = smem_u32(smem);
    const int tid = threadIdx.x;
    const int wid = tid >> 5;
    const int lane = tid & 31;
    const int warp_m = wid & 1;        // 2 m-warps of 64 rows
    const int warp_n = wid >> 1;       // 4 n-warps of 32 cols
    const int bz = blockIdx.z;
    Ah += sA * bz;  Bh += sB * bz;
    if (C)  C  += sC * bz;
    if (Ch) Ch += sCh * bz;
    const int bm = blockIdx.y * BM;
    const int bn = blockIdx.x * BN + bnOff;

    float acc[4][4][4];
#pragma unroll
    for (int i = 0; i < 4; i++)
#pragma unroll
        for (int j = 0; j < 4; j++)
#pragma unroll
            for (int v = 0; v < 4; v++) acc[i][j][v] = 0.f;

    const uint32_t a_base =
        ((uint32_t)(warp_m * 64 + (lane & 15)) * SROW + ((lane >> 4) * 8)) * 2;
    const uint32_t b_base = (uint32_t)A_HALVES * 2 +
        (((uint32_t)(warp_n * 32 + ((lane >> 4) & 1) * 8 + (lane & 7))) * SROW +
         (((lane >> 3) & 1) * 8)) * 2;

    const int ntiles = (K + BK - 1) / BK;

    // issue one quarter (chunk) of a stage's loads
    auto load_chunk = [&](uint32_t sb, int t, int chunk) {
        int k0 = t * BK;
        {
            int idx = tid + chunk * 256;
            int r = idx >> 3, ch = idx & 7;
            int kc = k0 + ch * 8;
            int ab = 2 * (K - kc); ab = ab < 0 ? 0 : (ab > 16 ? 16 : ab);
            cp16(sb + (r * SROW + ch * 8) * 2, Ah + (long long)(bm + r) * lda + kc, ab);
        }
        {
            int idx = tid + chunk * 256;
            int r = idx >> 3, ch = idx & 7;
            int kc = k0 + ch * 8;
            int ab = 2 * (K - kc); ab = ab < 0 ? 0 : (ab > 16 ? 16 : ab);
            int gn = bn + r;
            int bb = (gn < N) ? ab : 0;
            cp16(sb + A_HALVES * 2 + (r * SROW + ch * 8) * 2,
                 Bh + (long long)(gn < N ? gn : 0) * ldb + kc, bb);
        }
    };
    auto load_stage = [&](int s, int t) {
        uint32_t sb = sbase + s * STAGE_B;
#pragma unroll
        for (int c = 0; c < 4; c++) load_chunk(sb, t, c);
    };

    load_stage(0, 0); CP_COMMIT();
    if (ntiles > 1) load_stage(1, 1);
    CP_COMMIT();

    for (int t = 0; t < ntiles; t++) {
        CP_WAIT(1);
        __syncthreads();
        int ls = t + NSTAGE - 1;
        bool doload = ls < ntiles;
        uint32_t lsb = sbase + (ls % NSTAGE) * STAGE_B;
        uint32_t sb = sbase + (t % NSTAGE) * STAGE_B;
#pragma unroll
        for (int kk = 0; kk < 4; kk++) {
            if (doload) load_chunk(lsb, ls, kk);   // interleaved prefetch issue
            uint32_t a[4][4], b[2][4];
#pragma unroll
            for (int mi = 0; mi < 4; mi++)
                ldmx4(a[mi][0], a[mi][1], a[mi][2], a[mi][3],
                      sb + a_base + (uint32_t)(mi * 16 * SROW * 2) + kk * 32);
#pragma unroll
            for (int p = 0; p < 2; p++)
                ldmx4(b[p][0], b[p][1], b[p][2], b[p][3],
                      sb + b_base + (uint32_t)(p * 16 * SROW * 2) + kk * 32);
#pragma unroll
            for (int mi = 0; mi < 4; mi++)
#pragma unroll
                for (int nj = 0; nj < 4; nj++)
                    mma16816(acc[mi][nj], a[mi], b[nj >> 1][(nj & 1) * 2],
                             b[nj >> 1][(nj & 1) * 2 + 1]);
        }
        CP_COMMIT();
    }
    CP_WAIT(0);
    __syncthreads();

    float* stg = (float*)smem;
    const int gID = lane >> 2, t4 = lane & 3;

    if (epi == 5) {
        // ---- fused silu(gate)*up: nj even = gate, nj odd = up ----
#pragma unroll
        for (int p = 0; p < 2; p++) {
            int bc = bn + warp_n * 32 + p * 16 + 2 * t4;
            float bg0 = bias[bc],     bg1 = bias[bc + 1];
            float bu0 = bias[bc + 8], bu1 = bias[bc + 9];
            int hc = warp_n * 16 + p * 8 + 2 * t4;
#pragma unroll
            for (int mi = 0; mi < 4; mi++) {
                int r0 = warp_m * 64 + mi * 16 + gID;
                float o0 = silu_f(acc[mi][2*p][0] + bg0) * (acc[mi][2*p+1][0] + bu0);
                float o1 = silu_f(acc[mi][2*p][1] + bg1) * (acc[mi][2*p+1][1] + bu1);
                float o2 = silu_f(acc[mi][2*p][2] + bg0) * (acc[mi][2*p+1][2] + bu0);
                float o3 = silu_f(acc[mi][2*p][3] + bg1) * (acc[mi][2*p+1][3] + bu1);
                stg[r0 * SSTG + hc]           = o0;
                stg[r0 * SSTG + hc + 1]       = o1;
                stg[(r0 + 8) * SSTG + hc]     = o2;
                stg[(r0 + 8) * SSTG + hc + 1] = o3;
            }
        }
        __syncthreads();
        int hbase = bn >> 1;
#pragma unroll 4
        for (int it = 0; it < 32; it++) {
            int idx = tid + it * 256;
            int r = idx >> 6, c = idx & 63;
            int hcol = hbase + c;
            if (hcol < HFF)
                Ch[(long long)(bm + r) * ldch + hcol] = __float2half(stg[r * SSTG + c]);
        }
        return;
    }

    // ---- generic: single 128-col pass via SMEM staging ----
#pragma unroll
    for (int mi = 0; mi < 4; mi++)
#pragma unroll
        for (int nj = 0; nj < 4; nj++) {
            int r0 = warp_m * 64 + mi * 16 + gID;
            int c0 = warp_n * 32 + nj * 8 + 2 * t4;
            stg[r0 * SSTG + c0]           = acc[mi][nj][0];
            stg[r0 * SSTG + c0 + 1]       = acc[mi][nj][1];
            stg[(r0 + 8) * SSTG + c0]     = acc[mi][nj][2];
            stg[(r0 + 8) * SSTG + c0 + 1] = acc[mi][nj][3];
        }
    __syncthreads();

    if (epi == 1 && bn >= D_MODEL) {
        // k or v region: transposed coalesced store to KT/VT
        int reg = bn >> 10;                        // 1=k, 2=v
        fp16* T = (reg == 1) ? KT : VT;
        long long tstride = (reg == 1) ? (long long)D_MODEL * SEQ : (long long)DP * SEQ;
        int dbase = bn - reg * 1024;
        int b = bm >> 12, s0v = bm & 4095;
        fp16* Tb = T + (size_t)b * tstride + s0v;
#pragma unroll 4
        for (int it = 0; it < 64; it++) {
            int idx = tid + it * 256;
            int c = idx >> 7, r = idx & 127;
            int gn = bn + c;
            float tv = stg[r * SSTG + c] + (bias ? bias[gn] : 0.f);
            if (reg == 1) tv = (tv > 0.f) ? tv + 1.f : expf(tv);
            Tb[(size_t)(dbase + c) * SEQ + r] = __float2half(tv);
        }
    } else {
#pragma unroll 4
        for (int it = 0; it < 64; it++) {
            int idx = tid + it * 256;
            int r = idx >> 7, c = idx & 127;
            int gm = bm + r, gn = bn + c;
            if (gn < N) {
                float tv = stg[r * SSTG + c] + (bias ? bias[gn] : 0.f);
                float outv;
                if (epi == 1) {                // q cols: (elu+1)/64 (fp16 range)
                    outv = ((tv > 0.f) ? tv + 1.f : expf(tv)) * QP_INV;
                } else {
                    outv = tv;
                }
                if (C) C[(long long)gm * ldc + gn] = outv;
                if (Ch && gn < colLim)
                    Ch[(long long)gm * ldch + gn] = __float2half(outv);
            }
        }
    }
}

// ===================== prep kernels (split for stream overlap) ==============
#define NB_CONV (MTOT * D_MODEL / 2048)   // 8192 (8 elems/thread, 16B stores)
#define GX_QKV  (D3 / 32)                 // 96
#define NB_QKV  (GX_QKV * (D_MODEL / 32)) // 3072
#define NB_ONES (BATCH * SEQ / 1024)      // 64
#define NB_PREP1 (NB_CONV + NB_QKV + NB_ONES)
#define GX_GU   ((HFF + 31) / 32)         // 86
#define NB_GU   (GX_GU * (D_MODEL / 32))  // 2752
#define GX_WD   (D_MODEL / 32)            // 32
#define NB_WD   (GX_WD * ((HFF + 31) / 32)) // 2752
#define NB_BIAS ((HFF + 255) / 256)       // 11
#define NB_PREP2 (2 * NB_GU + NB_WD + NB_BIAS)

__device__ __forceinline__ void transpose_body(
    const float* in, fp16* oh, int R, int Ccols, int ldi, int ldo,
    int map, int bx, int by, int t, float (*tile)[33])
{
    int r0 = by * 32, c0 = bx * 32;
    int tx = t & 31, ty = t >> 5;
#pragma unroll
    for (int i = 0; i < 32; i += 8) {
        int r = r0 + ty + i, c = c0 + tx;
        tile[ty + i][tx] = (r < R && c < Ccols) ? in[(long long)r * ldi + c] : 0.f;
    }
    __syncthreads();
#pragma unroll
    for (int i = 0; i < 32; i += 8) {
        int r = c0 + ty + i, c = r0 + tx;
        if (r < Ccols && c < R) {
            int rr = r;
            if (map) rr = ((r >> 3) << 4) + (r & 7) + (map == 2 ? 8 : 0);
            oh[(long long)rr * ldo + c] = __float2half(tile[tx][ty + i]);
        }
    }
}

__global__ void __launch_bounds__(256) prep1_kernel(
    const float* __restrict__ x, const float* __restrict__ Wqkv)
{
    __shared__ float tile[32][33];
    int b = blockIdx.x;
    int t = threadIdx.x;
    if (b < NB_CONV) {                    // x -> fp16 (8 elems/thread)
        int i = b * 2048 + t * 8;
        float4 v0 = *(const float4*)(x + i);
        float4 v1 = *(const float4*)(x + i + 4);
        uint4 o;
        *(__half2*)&o.x = __floats2half2_rn(v0.x, v0.y);
        *(__half2*)&o.y = __floats2half2_rn(v0.z, v0.w);
        *(__half2*)&o.z = __floats2half2_rn(v1.x, v1.y);
        *(__half2*)&o.w = __floats2half2_rn(v1.z, v1.w);
        *(uint4*)(g_xh + i) = o;
        return;
    }
    b -= NB_CONV;
    if (b < NB_QKV) {
        transpose_body(Wqkv, g_WqkvT, D_MODEL, D3, D3, D_MODEL, 0,
                       b % GX_QKV, b / GX_QKV, t, tile);
        return;
    }
    b -= NB_QKV;
    {                                     // vT scale row (e = 1024): 1/4096
        int i = b * 1024 + t * 4;
        int bb = i >> 12, s = i & 4095;
        fp16* p = g_vT + (size_t)bb * DP * SEQ + (size_t)1024 * SEQ + s;
        __half2 sc2 = __floats2half2_rn(1.f / 4096.f, 1.f / 4096.f);
        *(__half2*)p       = sc2;
        *(__half2*)(p + 2) = sc2;
    }
}

__global__ void __launch_bounds__(256) prep2_kernel(
    const float* __restrict__ Wg, const float* __restrict__ Wu,
    const float* __restrict__ Wd, const float* __restrict__ bg,
    const float* __restrict__ bu)
{
    __shared__ float tile[32][33];
    int b = blockIdx.x;
    int t = threadIdx.x;
    if (b < NB_GU) {
        transpose_body(Wg, g_WguT, D_MODEL, HFF, HFF, D_MODEL, 1,
                       b % GX_GU, b / GX_GU, t, tile);
        return;
    }
    b -= NB_GU;
    if (b < NB_GU) {
        transpose_body(Wu, g_WguT, D_MODEL, HFF, HFF, D_MODEL, 2,
                       b % GX_GU, b / GX_GU, t, tile);
        return;
    }
    b -= NB_GU;
    if (b < NB_WD) {
        transpose_body(Wd, g_WdT, HFF, D_MODEL, D_MODEL, HFFP, 0,
                       b % GX_WD, b / GX_WD, t, tile);
        return;
    }
    b -= NB_WD;
    {
        int n = b * 256 + t;
        if (n < HFF) {
            int o = ((n >> 3) << 4) + (n & 7);
            g_bgu[o] = bg[n];
            g_bgu[o + 8] = bu[n];
        }
    }
}

// ===================== layernorms ===========================================
// LN1: attn = num'*64 / (den'*262144 + eps); LN(x + attn) -> fp16 x1h.
__global__ void ln1_kernel(const fp16* __restrict__ yh, const float* __restrict__ x,
                           const float* __restrict__ gamma, const float* __restrict__ beta,
                           fp16* __restrict__ oh)
{
    int row = blockIdx.x;
    int t = threadIdx.x;
    const fp16* yr = yh + (long long)row * YLD;
    float den = __half2float(yr[1024]) * DEN_RESCALE + ATTN_EPS_F;
    float rden = NUM_RESCALE / den;
    long long base4 = (long long)row * (D_MODEL / 4);
    uint2 nraw = *(const uint2*)(yr + 4 * t);
    float2 n0 = __half22float2(*(__half2*)&nraw.x);
    float2 n1 = __half22float2(*(__half2*)&nraw.y);
    float4 xv = ((const float4*)x)[base4 + t];
    float4 v4;
    v4.x = xv.x + n0.x * rden;
    v4.y = xv.y + n0.y * rden;
    v4.z = xv.z + n1.x * rden;
    v4.w = xv.w + n1.y * rden;
    float s = v4.x + v4.y + v4.z + v4.w;
    __shared__ float red[256];
    red[t] = s; __syncthreads();
    for (int o = 128; o > 0; o >>= 1) { if (t < o) red[t] += red[t + o]; __syncthreads(); }
    float mu = red[0] * (1.f / D_MODEL);
    __syncthreads();
    float dx = v4.x - mu, dy = v4.y - mu, dz = v4.z - mu, dw = v4.w - mu;
    red[t] = dx * dx + dy * dy + dz * dz + dw * dw;
    __syncthreads();
    for (int o = 128; o > 0; o >>= 1) { if (t < o) red[t] += red[t + o]; __syncthreads(); }
    float inv = rsqrtf(red[0] * (1.f / D_MODEL) + LN_EPS_F);
    float4 g4 = ((const float4*)gamma)[t];
    float4 b4 = ((const float4*)beta)[t];
    ((__half2*)oh)[base4 * 2 + 2 * t] =
        __floats2half2_rn(dx * inv * g4.x + b4.x, dy * inv * g4.y + b4.y);
    ((__half2*)oh)[base4 * 2 + 2 * t + 1] =
        __floats2half2_rn(dz * inv * g4.z + b4.z, dw * inv * g4.w + b4.w);
}
__global__ void ln2_kernel(const fp16* __restrict__ in1, const fp16* __restrict__ in2,
                           const float* __restrict__ gamma, const float* __restrict__ beta,
                           float* __restrict__ out)
{
    int row = blockIdx.x;
    int t = threadIdx.x;
    long long base2 = (long long)row * (D_MODEL / 2);
    float2 a0 = __half22float2(((const __half2*)in1)[base2 + 2 * t]);
    float2 a1 = __half22float2(((const __half2*)in1)[base2 + 2 * t + 1]);
    float2 c0 = __half22float2(((const __half2*)in2)[base2 + 2 * t]);
    float2 c1 = __half22float2(((const __half2*)in2)[base2 + 2 * t + 1]);
    float4 v4;
    v4.x = a0.x + c0.x; v4.y = a0.y + c0.y;
    v4.z = a1.x + c1.x; v4.w = a1.y + c1.y;
    float s = v4.x + v4.y + v4.z + v4.w;
    __shared__ float red[256];
    red[t] = s; __syncthreads();
    for (int o = 128; o > 0; o >>= 1) { if (t < o) red[t] += red[t + o]; __syncthreads(); }
    float mu = red[0] * (1.f / D_MODEL);
    __syncthreads();
    float dx = v4.x - mu, dy = v4.y - mu, dz = v4.z - mu, dw = v4.w - mu;
    red[t] = dx * dx + dy * dy + dz * dz + dw * dw;
    __syncthreads();
    for (int o = 128; o > 0; o >>= 1) { if (t < o) red[t] += red[t + o]; __syncthreads(); }
    float inv = rsqrtf(red[0] * (1.f / D_MODEL) + LN_EPS_F);
    float4 g4 = ((const float4*)gamma)[t];
    float4 b4 = ((const float4*)beta)[t];
    float4 o4;
    o4.x = dx * inv * g4.x + b4.x;
    o4.y = dy * inv * g4.y + b4.y;
    o4.z = dz * inv * g4.z + b4.z;
    o4.w = dw * inv * g4.w + b4.w;
    ((float4*)out)[(long long)row * (D_MODEL / 4) + t] = o4;
}

// ===================== launch ===============================================
extern "C" void kernel_launch(void* const* d_in, const int* in_sizes, int n_in,
                              void* d_out, int out_size)
{
    const float* x    = (const float*)d_in[0];
    const float* Wqkv = (const float*)d_in[1];
    const float* bqkv = (const float*)d_in[2];
    const float* Wg   = (const float*)d_in[3];
    const float* bg   = (const float*)d_in[4];
    const float* Wu   = (const float*)d_in[5];
    const float* bu   = (const float*)d_in[6];
    const float* Wd   = (const float*)d_in[7];
    const float* bd   = (const float*)d_in[8];
    const float* g1   = (const float*)d_in[9];
    const float* b1   = (const float*)d_in[10];
    const float* g2   = (const float*)d_in[11];
    const float* b2   = (const float*)d_in[12];
    float* out = (float*)d_out;

    float *bgu;
    fp16 *qph,*xh,*WqkvT,*WguT,*WdT,*kpT,*vT,*kvh,*yh,*x1h,*hh,*ffnh;
    cudaGetSymbolAddress((void**)&qph,  g_qph);
    cudaGetSymbolAddress((void**)&yh,   g_yh);
    cudaGetSymbolAddress((void**)&bgu,  g_bgu);
    cudaGetSymbolAddress((void**)&xh,   g_xh);
    cudaGetSymbolAddress((void**)&WqkvT,g_WqkvT);
    cudaGetSymbolAddress((void**)&WguT, g_WguT);
    cudaGetSymbolAddress((void**)&WdT,  g_WdT);
    cudaGetSymbolAddress((void**)&kpT,  g_kpT);
    cudaGetSymbolAddress((void**)&vT,   g_vT);
    cudaGetSymbolAddress((void**)&kvh,  g_kvh);
    cudaGetSymbolAddress((void**)&x1h,  g_x1h);
    cudaGetSymbolAddress((void**)&hh,   g_hh);
    cudaGetSymbolAddress((void**)&ffnh, g_ffnh);

    cudaFuncSetAttribute(mma_gemm_kernel,
                         cudaFuncAttributeMaxDynamicSharedMemorySize, SMEM_SZ);

    // lazily created low-priority side stream + events (created once)
    static cudaStream_t s2 = nullptr;
    static cudaEvent_t evRoot = nullptr, evPrep1 = nullptr, evQ = nullptr;
    if (!s2) {
        int lo = 0, hi = 0;
        cudaDeviceGetStreamPriorityRange(&lo, &hi);   // lo = least priority
        cudaStreamCreateWithPriority(&s2, cudaStreamNonBlocking, lo);
        cudaEventCreateWithFlags(&evRoot, cudaEventDisableTiming);
        cudaEventCreateWithFlags(&evPrep1, cudaEventDisableTiming);
        cudaEventCreateWithFlags(&evQ, cudaEventDisableTiming);
    }

    dim3 blk(256);
    const long long SDM  = (long long)SEQ * D_MODEL;
    const long long DS   = (long long)D_MODEL * SEQ;
    const long long VS   = (long long)DP * SEQ;
    const long long KVS  = (long long)DP * D_MODEL;
    const long long YS   = (long long)SEQ * YLD;

    // ---- fork root; prep2 (FFN weights) on side stream ----
    cudaEventRecord(evRoot, 0);
    cudaStreamWaitEvent(s2, evRoot, 0);
    prep2_kernel<<<NB_PREP2, blk, 0, s2>>>(Wg, Wu, Wd, bg, bu);

    // ---- 0) prep1: x convert + WqkvT + scale-row (main) ----
    prep1_kernel<<<NB_PREP1, blk>>>(x, Wqkv);
    cudaEventRecord(evPrep1, 0);

    // ---- 1a) q GEMM on side stream: q->qph ((elu+1)/64) ----
    cudaStreamWaitEvent(s2, evPrep1, 0);
    mma_gemm_kernel<<<dim3(8, MTOT/BM, 1), blk, SMEM_SZ, s2>>>(
        xh, WqkvT, bqkv, nullptr, qph, nullptr, nullptr,
        MTOT, D3, D_MODEL, D_MODEL, D_MODEL, D_MODEL, D_MODEL,
        0, 0, 0, 0, 1, D_MODEL, 0);
    cudaEventRecord(evQ, s2);

    // ---- 1b) k,v GEMM on main: k->kpT (elu+1, transp), v->vT ----
    mma_gemm_kernel<<<dim3(16, MTOT/BM, 1), blk, SMEM_SZ>>>(
        xh, WqkvT, bqkv, nullptr, nullptr, kpT, vT,
        MTOT, D3, D_MODEL, D_MODEL, D_MODEL, D_MODEL, D_MODEL,
        0, 0, 0, 0, 1, 0, D_MODEL);

    // ---- 2) kvh[e][d] = fp16(sum_s vT'[e,s] kp[s,d]); row 1024 = ksum/4096 ----
    mma_gemm_kernel<<<dim3(D_MODEL/BN, (1025 + BM - 1)/BM, BATCH), blk, SMEM_SZ>>>(
        vT, kpT, nullptr, nullptr, kvh, nullptr, nullptr,
        1025, D_MODEL, SEQ, SEQ, SEQ, D_MODEL, D_MODEL,
        VS, DS, KVS, KVS, 0, D_MODEL, 0);

    // ---- join q path, then 3) yh = fp16(qp' @ kv); col 1024 = den' ----
    cudaStreamWaitEvent(0, evQ, 0);
    mma_gemm_kernel<<<dim3((1025 + BN - 1)/BN, SEQ/BM, BATCH), blk, SMEM_SZ>>>(
        qph, kvh, nullptr, nullptr, yh, nullptr, nullptr,
        SEQ, 1025, D_MODEL, D_MODEL, D_MODEL, YLD, YLD,
        SDM, KVS, YS, YS, 0, 1025, 0);

    // ---- 4) x1h = fp16(LN(x + num'*64/den_full)) ----
    ln1_kernel<<<MTOT, blk>>>(yh, x, g1, b1, x1h);

    // ---- 5+6) hh = fp16(silu(x1@Wg+bg) * (x1@Wu+bu)) ----
    // (prep2 precedes G1q on s2; evQ wait above covers it)
    mma_gemm_kernel<<<dim3((NGU+BN-1)/BN, MTOT/BM, 1), blk, SMEM_SZ>>>(
        x1h, WguT, bgu, nullptr, hh, nullptr, nullptr,
        MTOT, NGU, D_MODEL, D_MODEL, D_MODEL, NGU, HFFP,
        0, 0, 0, 0, 5, HFF, 0);

    // ---- 7) ffnh = fp16(h @ Wd + bd) ----
    mma_gemm_kernel<<<dim3(D_MODEL/BN, MTOT/BM, 1), blk, SMEM_SZ>>>(
        hh, WdT, bd, nullptr, ffnh, nullptr, nullptr,
        MTOT, D_MODEL, HFF, HFFP, HFFP, D_MODEL, D_MODEL,
        0, 0, 0, 0, 0, D_MODEL, 0);

    // ---- 8) out = LN(x1h + ffnh) ----
    ln2_kernel<<<MTOT, blk>>>(x1h, ffnh, g2, b2, out);
}